// round 1
// baseline (speedup 1.0000x reference)
#include <cuda_runtime.h>
#include <math.h>

// ---------------- problem constants ----------------
#define B_    16
#define CTX_  100
#define LSEQ  301            // 3*CTX+1
#define D_    1024
#define H_    16
#define HD_   64
#define NL_   4
#define DFF_  4096
#define GRID_ 9
#define NA_   5
#define NTOK  (B_*LSEQ)      // 4816
#define NPOS  (B_*(CTX_+1))  // 1616 loss rows

// ---------------- scratch (static device allocations) ----------------
__device__ float g_h   [NTOK * D_];
__device__ float g_x   [NTOK * D_];
__device__ float g_qkv [NTOK * 3 * D_];
__device__ float g_attn[NTOK * D_];
__device__ float g_ffn [NTOK * DFF_];
__device__ float g_partial[NPOS * 2];

// ---------------- embedding assembly ----------------
// h[b, p, :] = token_embed + wpe[p]
__global__ void embed_kernel(const int* __restrict__ states,
                             const int* __restrict__ actions,
                             const float* __restrict__ rewards,
                             const int* __restrict__ qstates,
                             const float* __restrict__ wpe,
                             const float* __restrict__ e_state,
                             const float* __restrict__ e_act,
                             const float* __restrict__ erw,
                             const float* __restrict__ erb,
                             float* __restrict__ h)
{
    int tok = blockIdx.x;
    int b = tok / LSEQ, p = tok % LSEQ;
    const float* src = nullptr;
    float r = 0.f;
    int type = 0; // 0: table lookup, 1: reward linear
    if (p == 3 * CTX_) {
        int q = qstates[b * 2] * GRID_ + qstates[b * 2 + 1];
        src = e_state + (size_t)q * D_;
    } else {
        int t = p / 3, m = p % 3;
        if (m == 0) {
            int sid = states[(b * CTX_ + t) * 2] * GRID_ + states[(b * CTX_ + t) * 2 + 1];
            src = e_state + (size_t)sid * D_;
        } else if (m == 1) {
            src = e_act + (size_t)actions[b * CTX_ + t] * D_;
        } else {
            r = rewards[b * CTX_ + t];
            type = 1;
        }
    }
    for (int c = threadIdx.x; c < D_; c += blockDim.x) {
        float v = (type == 0) ? src[c] : fmaf(r, erw[c], erb[c]);
        h[(size_t)tok * D_ + c] = v + wpe[(size_t)p * D_ + c];
    }
}

// ---------------- LayerNorm (two-pass, matches reference exactly) ----------------
__global__ void ln_kernel(const float* __restrict__ in, float* __restrict__ out,
                          const float* __restrict__ g, const float* __restrict__ beta)
{
    __shared__ float red[8];
    int row = blockIdx.x;
    const float* x = in + (size_t)row * D_;
    int tid = threadIdx.x;
    float v[4];
    float s = 0.f;
#pragma unroll
    for (int i = 0; i < 4; i++) { v[i] = x[tid + 256 * i]; s += v[i]; }
#pragma unroll
    for (int o = 16; o; o >>= 1) s += __shfl_xor_sync(0xFFFFFFFFu, s, o);
    if ((tid & 31) == 0) red[tid >> 5] = s;
    __syncthreads();
    float mean = (red[0]+red[1]+red[2]+red[3]+red[4]+red[5]+red[6]+red[7]) * (1.f/1024.f);
    __syncthreads();
    float s2 = 0.f;
#pragma unroll
    for (int i = 0; i < 4; i++) { float d = v[i] - mean; s2 += d * d; }
#pragma unroll
    for (int o = 16; o; o >>= 1) s2 += __shfl_xor_sync(0xFFFFFFFFu, s2, o);
    if ((tid & 31) == 0) red[tid >> 5] = s2;
    __syncthreads();
    float var = (red[0]+red[1]+red[2]+red[3]+red[4]+red[5]+red[6]+red[7]) * (1.f/1024.f);
    float inv = 1.f / sqrtf(var + 1e-5f);
#pragma unroll
    for (int i = 0; i < 4; i++) {
        int c = tid + 256 * i;
        out[(size_t)row * D_ + c] = (v[i] - mean) * inv * g[c] + beta[c];
    }
}

// ---------------- GEMM: C = epilogue(A[M,K] @ W[K,N] + bias) ----------------
// mode 0: store, 1: gelu_new store, 2: C += (residual accumulate)
#define TM 128
#define TN 128
#define TK 16

__device__ __forceinline__ float gelu_new(float xv) {
    float c = 0.7978845608028654f;
    float t = tanhf(c * (xv + 0.044715f * xv * xv * xv));
    return 0.5f * xv * (1.f + t);
}

__global__ void __launch_bounds__(256)
gemm_kernel(const float* __restrict__ A, const float* __restrict__ W,
            const float* __restrict__ bias, float* __restrict__ C,
            int M, int N, int K, int mode)
{
    __shared__ __align__(16) float As[TK][TM]; // As[k][m]
    __shared__ __align__(16) float Bs[TK][TN]; // Bs[k][n]
    int tid = threadIdx.x;
    int tx = tid & 15;       // n-dir
    int ty = tid >> 4;       // m-dir
    int m0 = blockIdx.y * TM;
    int n0 = blockIdx.x * TN;

    // loaders: A tile (transpose into As), B tile
    int a_m  = tid >> 1;          // 0..127
    int a_k0 = (tid & 1) * 8;     // 0 or 8
    int b_k  = tid >> 4;          // 0..15
    int b_n0 = (tid & 15) * 8;
    bool am_ok = (m0 + a_m) < M;

    float acc[8][8];
#pragma unroll
    for (int i = 0; i < 8; i++)
#pragma unroll
        for (int j = 0; j < 8; j++) acc[i][j] = 0.f;

    for (int kt = 0; kt < K; kt += TK) {
        const float* Ap = A + (size_t)(m0 + a_m) * K + kt + a_k0;
#pragma unroll
        for (int i = 0; i < 8; i++)
            As[a_k0 + i][a_m] = am_ok ? Ap[i] : 0.f;
        const float* Wp = W + (size_t)(kt + b_k) * N + n0 + b_n0;
#pragma unroll
        for (int i = 0; i < 8; i += 4)
            *reinterpret_cast<float4*>(&Bs[b_k][b_n0 + i]) =
                *reinterpret_cast<const float4*>(Wp + i);
        __syncthreads();
#pragma unroll
        for (int k = 0; k < TK; k++) {
            float4 a0 = *reinterpret_cast<const float4*>(&As[k][ty * 8]);
            float4 a1 = *reinterpret_cast<const float4*>(&As[k][ty * 8 + 4]);
            float4 b0 = *reinterpret_cast<const float4*>(&Bs[k][tx * 8]);
            float4 b1 = *reinterpret_cast<const float4*>(&Bs[k][tx * 8 + 4]);
            float a[8] = {a0.x,a0.y,a0.z,a0.w,a1.x,a1.y,a1.z,a1.w};
            float b[8] = {b0.x,b0.y,b0.z,b0.w,b1.x,b1.y,b1.z,b1.w};
#pragma unroll
            for (int i = 0; i < 8; i++)
#pragma unroll
                for (int j = 0; j < 8; j++)
                    acc[i][j] = fmaf(a[i], b[j], acc[i][j]);
        }
        __syncthreads();
    }

#pragma unroll
    for (int i = 0; i < 8; i++) {
        int m = m0 + ty * 8 + i;
        if (m >= M) continue;
#pragma unroll
        for (int j = 0; j < 8; j++) {
            int n = n0 + tx * 8 + j;
            float v = acc[i][j] + bias[n];
            size_t idx = (size_t)m * N + n;
            if (mode == 1) v = gelu_new(v);
            if (mode == 2) C[idx] += v;
            else           C[idx] = v;
        }
    }
}

// ---------------- fused causal attention: one CTA per (b, head) ----------------
// smem: KT[64][304] transposed keys, V[301][64], per-warp scores[8][304], per-warp q stage
#define KTP 304
#define ATTN_SMEM_FLOATS (HD_*KTP + LSEQ*HD_ + 8*KTP + 8*HD_)

__global__ void __launch_bounds__(256)
attn_kernel(const float* __restrict__ qkv, float* __restrict__ out)
{
    extern __shared__ float sm[];
    float* KT = sm;                          // [64][KTP]
    float* V  = KT + HD_ * KTP;              // [301][64]
    float* SC = V + LSEQ * HD_;              // [8][KTP]
    float* QV = SC + 8 * KTP;                // [8][64]

    int bh = blockIdx.x;
    int b = bh >> 4, hd = bh & 15;
    const float* base = qkv + (size_t)b * LSEQ * (3 * D_);
    int hoff = hd * HD_;

    for (int idx = threadIdx.x; idx < LSEQ * HD_; idx += 256) {
        int j = idx >> 6, d = idx & 63;
        KT[d * KTP + j] = base[(size_t)j * (3 * D_) + D_     + hoff + d];
        V [j * HD_ + d] = base[(size_t)j * (3 * D_) + 2 * D_ + hoff + d];
    }
    __syncthreads();

    int w = threadIdx.x >> 5, lane = threadIdx.x & 31;
    float* sc = SC + w * KTP;
    float* qv = QV + w * HD_;

    for (int q = w; q < LSEQ; q += 8) {
        qv[lane]      = base[(size_t)q * (3 * D_) + hoff + lane];
        qv[lane + 32] = base[(size_t)q * (3 * D_) + hoff + 32 + lane];
        __syncwarp();
        float qr[HD_];
#pragma unroll
        for (int d = 0; d < HD_; d++) qr[d] = qv[d];

        int nk = q + 1;
        float mx = -1e30f;
        for (int j = lane; j < nk; j += 32) {
            float s = 0.f;
#pragma unroll
            for (int d = 0; d < HD_; d++) s = fmaf(qr[d], KT[d * KTP + j], s);
            s *= 0.125f;   // 1/sqrt(64)
            sc[j] = s;
            mx = fmaxf(mx, s);
        }
#pragma unroll
        for (int o = 16; o; o >>= 1) mx = fmaxf(mx, __shfl_xor_sync(0xFFFFFFFFu, mx, o));
        float sum = 0.f;
        for (int j = lane; j < nk; j += 32) {
            float e = expf(sc[j] - mx);
            sc[j] = e;
            sum += e;
        }
#pragma unroll
        for (int o = 16; o; o >>= 1) sum += __shfl_xor_sync(0xFFFFFFFFu, sum, o);
        float inv = 1.f / sum;
        __syncwarp();

        float o0 = 0.f, o1 = 0.f;
        for (int j = 0; j < nk; j++) {
            float p = sc[j];
            o0 = fmaf(p, V[j * HD_ + lane], o0);
            o1 = fmaf(p, V[j * HD_ + 32 + lane], o1);
        }
        size_t orow = (size_t)(b * LSEQ + q) * D_ + hoff;
        out[orow + lane]      = o0 * inv;
        out[orow + 32 + lane] = o1 * inv;
        __syncwarp();
    }
}

// ---------------- fused final-LN + logits + per-position loss/acc ----------------
__global__ void loss_kernel(const float* __restrict__ h,
                            const float* __restrict__ g,
                            const float* __restrict__ beta,
                            const float* __restrict__ pw,   // [D,5]
                            const float* __restrict__ pb,   // [5]
                            const int* __restrict__ actions,
                            const int* __restrict__ tact,
                            float* __restrict__ partial)
{
    __shared__ float red[4];
    __shared__ float lred[5][4];
    int idx = blockIdx.x;
    int b = idx / (CTX_ + 1), t = idx % (CTX_ + 1);
    const float* x = h + (size_t)(b * LSEQ + 3 * t) * D_;
    int tid = threadIdx.x, lane = tid & 31, w = tid >> 5;

    float v[8];
    float s = 0.f;
#pragma unroll
    for (int i = 0; i < 8; i++) { v[i] = x[tid + 128 * i]; s += v[i]; }
#pragma unroll
    for (int o = 16; o; o >>= 1) s += __shfl_xor_sync(0xFFFFFFFFu, s, o);
    if (lane == 0) red[w] = s;
    __syncthreads();
    float mean = (red[0] + red[1] + red[2] + red[3]) * (1.f / 1024.f);
    __syncthreads();
    float s2 = 0.f;
#pragma unroll
    for (int i = 0; i < 8; i++) { float d = v[i] - mean; s2 += d * d; }
#pragma unroll
    for (int o = 16; o; o >>= 1) s2 += __shfl_xor_sync(0xFFFFFFFFu, s2, o);
    if (lane == 0) red[w] = s2;
    __syncthreads();
    float var = (red[0] + red[1] + red[2] + red[3]) * (1.f / 1024.f);
    float inv = 1.f / sqrtf(var + 1e-5f);

    float acc[NA_] = {0.f, 0.f, 0.f, 0.f, 0.f};
#pragma unroll
    for (int i = 0; i < 8; i++) {
        int c = tid + 128 * i;
        float xn = (v[i] - mean) * inv * g[c] + beta[c];
#pragma unroll
        for (int a = 0; a < NA_; a++)
            acc[a] = fmaf(xn, pw[c * NA_ + a], acc[a]);
    }
#pragma unroll
    for (int a = 0; a < NA_; a++) {
        float tv = acc[a];
#pragma unroll
        for (int o = 16; o; o >>= 1) tv += __shfl_xor_sync(0xFFFFFFFFu, tv, o);
        if (lane == 0) lred[a][w] = tv;
    }
    __syncthreads();
    if (tid == 0) {
        float logit[NA_];
#pragma unroll
        for (int a = 0; a < NA_; a++)
            logit[a] = lred[a][0] + lred[a][1] + lred[a][2] + lred[a][3] + pb[a];
        int target = (t < CTX_) ? actions[b * CTX_ + t] : tact[b];
        float mx = logit[0]; int am = 0;
#pragma unroll
        for (int a = 1; a < NA_; a++) if (logit[a] > mx) { mx = logit[a]; am = a; }
        float se = 0.f;
#pragma unroll
        for (int a = 0; a < NA_; a++) se += expf(logit[a] - mx);
        float lse = mx + logf(se);
        float sl = 0.f;
#pragma unroll
        for (int a = 0; a < NA_; a++) sl += (logit[a] - lse);
        float nll = -(logit[target] - lse);
        float smooth = -sl * (1.f / NA_);
        partial[2 * idx]     = 0.9f * nll + 0.1f * smooth;
        partial[2 * idx + 1] = (am == target) ? 1.f : 0.f;
    }
}

__global__ void reduce_kernel(const float* __restrict__ partial, float* __restrict__ out)
{
    __shared__ float rl[8], ra[8];
    int tid = threadIdx.x, lane = tid & 31, w = tid >> 5;
    float l = 0.f, a = 0.f;
    for (int i = tid; i < NPOS; i += 256) {
        l += partial[2 * i];
        a += partial[2 * i + 1];
    }
#pragma unroll
    for (int o = 16; o; o >>= 1) {
        l += __shfl_xor_sync(0xFFFFFFFFu, l, o);
        a += __shfl_xor_sync(0xFFFFFFFFu, a, o);
    }
    if (lane == 0) { rl[w] = l; ra[w] = a; }
    __syncthreads();
    if (tid == 0) {
        float L = 0.f, A = 0.f;
#pragma unroll
        for (int i = 0; i < 8; i++) { L += rl[i]; A += ra[i]; }
        out[0] = L * (1.f / NPOS);
        out[1] = A * (1.f / NPOS);
    }
}

// ---------------- launch ----------------
static inline void launch_gemm(const float* A, const float* W, const float* bias,
                               float* C, int M, int N, int K, int mode)
{
    dim3 grid((N + TN - 1) / TN, (M + TM - 1) / TM);
    gemm_kernel<<<grid, 256>>>(A, W, bias, C, M, N, K, mode);
}

extern "C" void kernel_launch(void* const* d_in, const int* in_sizes, int n_in,
                              void* d_out, int out_size)
{
    const int*   states  = (const int*)  d_in[0];
    const int*   actions = (const int*)  d_in[1];
    const float* rewards = (const float*)d_in[2];
    const int*   qstates = (const int*)  d_in[3];
    const int*   tact    = (const int*)  d_in[4];
    const float* wpe     = (const float*)d_in[5];
    const float* e_state = (const float*)d_in[6];
    const float* e_act   = (const float*)d_in[7];
    const float* erw     = (const float*)d_in[8];
    const float* erb     = (const float*)d_in[9];
    const float* ln1g    = (const float*)d_in[10];
    const float* ln1b    = (const float*)d_in[11];
    const float* attnw   = (const float*)d_in[12];
    const float* attnb   = (const float*)d_in[13];
    const float* apw     = (const float*)d_in[14];
    const float* apb     = (const float*)d_in[15];
    const float* ln2g    = (const float*)d_in[16];
    const float* ln2b    = (const float*)d_in[17];
    const float* fcw     = (const float*)d_in[18];
    const float* fcb     = (const float*)d_in[19];
    const float* mpw     = (const float*)d_in[20];
    const float* mpb     = (const float*)d_in[21];
    const float* lnfg    = (const float*)d_in[22];
    const float* lnfb    = (const float*)d_in[23];
    const float* predw   = (const float*)d_in[24];
    const float* predb   = (const float*)d_in[25];
    float* out = (float*)d_out;

    float *h, *x, *qkv, *attn, *ffn, *partial;
    cudaGetSymbolAddress((void**)&h,    g_h);
    cudaGetSymbolAddress((void**)&x,    g_x);
    cudaGetSymbolAddress((void**)&qkv,  g_qkv);
    cudaGetSymbolAddress((void**)&attn, g_attn);
    cudaGetSymbolAddress((void**)&ffn,  g_ffn);
    cudaGetSymbolAddress((void**)&partial, g_partial);

    const int attn_smem = ATTN_SMEM_FLOATS * (int)sizeof(float);
    cudaFuncSetAttribute(attn_kernel, cudaFuncAttributeMaxDynamicSharedMemorySize, attn_smem);

    embed_kernel<<<NTOK, 256>>>(states, actions, rewards, qstates, wpe,
                                e_state, e_act, erw, erb, h);

    for (int i = 0; i < NL_; i++) {
        ln_kernel<<<NTOK, 256>>>(h, x, ln1g + i * D_, ln1b + i * D_);
        launch_gemm(x, attnw + (size_t)i * D_ * 3 * D_, attnb + i * 3 * D_,
                    qkv, NTOK, 3 * D_, D_, 0);
        attn_kernel<<<B_ * H_, 256, attn_smem>>>(qkv, attn);
        launch_gemm(attn, apw + (size_t)i * D_ * D_, apb + i * D_,
                    h, NTOK, D_, D_, 2);
        ln_kernel<<<NTOK, 256>>>(h, x, ln2g + i * D_, ln2b + i * D_);
        launch_gemm(x, fcw + (size_t)i * D_ * DFF_, fcb + i * DFF_,
                    ffn, NTOK, DFF_, D_, 1);
        launch_gemm(ffn, mpw + (size_t)i * DFF_ * D_, mpb + i * D_,
                    h, NTOK, D_, DFF_, 2);
    }

    loss_kernel<<<NPOS, 128>>>(h, lnfg, lnfb, predw, predb, actions, tact, partial);
    reduce_kernel<<<1, 256>>>(partial, out);
}

// round 2
// speedup vs baseline: 1.0000x; 1.0000x over previous
#include <cuda_runtime.h>
#include <math.h>

// ---------------- problem constants ----------------
#define B_    16
#define CTX_  100
#define LSEQ  301            // 3*CTX+1
#define D_    1024
#define H_    16
#define HD_   64
#define NL_   4
#define DFF_  4096
#define GRID_ 9
#define NA_   5
#define NTOK  (B_*LSEQ)      // 4816
#define NPOS  (B_*(CTX_+1))  // 1616 loss rows

// ---------------- scratch (static device allocations) ----------------
__device__ float g_h   [NTOK * D_];
__device__ float g_x   [NTOK * D_];
__device__ float g_qkv [NTOK * 3 * D_];
__device__ float g_attn[NTOK * D_];
__device__ float g_ffn [NTOK * DFF_];
__device__ float g_partial[NPOS * 2];

// ---------------- embedding assembly ----------------
// h[b, p, :] = token_embed + wpe[p]
__global__ void embed_kernel(const int* __restrict__ states,
                             const int* __restrict__ actions,
                             const float* __restrict__ rewards,
                             const int* __restrict__ qstates,
                             const float* __restrict__ wpe,
                             const float* __restrict__ e_state,
                             const float* __restrict__ e_act,
                             const float* __restrict__ erw,
                             const float* __restrict__ erb,
                             float* __restrict__ h)
{
    int tok = blockIdx.x;
    int b = tok / LSEQ, p = tok % LSEQ;
    const float* src = nullptr;
    float r = 0.f;
    int type = 0; // 0: table lookup, 1: reward linear
    if (p == 3 * CTX_) {
        int q = qstates[b * 2] * GRID_ + qstates[b * 2 + 1];
        src = e_state + (size_t)q * D_;
    } else {
        int t = p / 3, m = p % 3;
        if (m == 0) {
            int sid = states[(b * CTX_ + t) * 2] * GRID_ + states[(b * CTX_ + t) * 2 + 1];
            src = e_state + (size_t)sid * D_;
        } else if (m == 1) {
            src = e_act + (size_t)actions[b * CTX_ + t] * D_;
        } else {
            r = rewards[b * CTX_ + t];
            type = 1;
        }
    }
    for (int c = threadIdx.x; c < D_; c += blockDim.x) {
        float v = (type == 0) ? src[c] : fmaf(r, erw[c], erb[c]);
        h[(size_t)tok * D_ + c] = v + wpe[(size_t)p * D_ + c];
    }
}

// ---------------- LayerNorm (two-pass, matches reference exactly) ----------------
__global__ void ln_kernel(const float* __restrict__ in, float* __restrict__ out,
                          const float* __restrict__ g, const float* __restrict__ beta)
{
    __shared__ float red[8];
    int row = blockIdx.x;
    const float* x = in + (size_t)row * D_;
    int tid = threadIdx.x;
    float v[4];
    float s = 0.f;
#pragma unroll
    for (int i = 0; i < 4; i++) { v[i] = x[tid + 256 * i]; s += v[i]; }
#pragma unroll
    for (int o = 16; o; o >>= 1) s += __shfl_xor_sync(0xFFFFFFFFu, s, o);
    if ((tid & 31) == 0) red[tid >> 5] = s;
    __syncthreads();
    float mean = (red[0]+red[1]+red[2]+red[3]+red[4]+red[5]+red[6]+red[7]) * (1.f/1024.f);
    __syncthreads();
    float s2 = 0.f;
#pragma unroll
    for (int i = 0; i < 4; i++) { float d = v[i] - mean; s2 += d * d; }
#pragma unroll
    for (int o = 16; o; o >>= 1) s2 += __shfl_xor_sync(0xFFFFFFFFu, s2, o);
    if ((tid & 31) == 0) red[tid >> 5] = s2;
    __syncthreads();
    float var = (red[0]+red[1]+red[2]+red[3]+red[4]+red[5]+red[6]+red[7]) * (1.f/1024.f);
    float inv = 1.f / sqrtf(var + 1e-5f);
#pragma unroll
    for (int i = 0; i < 4; i++) {
        int c = tid + 256 * i;
        out[(size_t)row * D_ + c] = (v[i] - mean) * inv * g[c] + beta[c];
    }
}

// ---------------- GEMM: C = epilogue(A[M,K] @ W[K,N] + bias) ----------------
// mode 0: store, 1: gelu_new store, 2: C += (residual accumulate)
#define TM 128
#define TN 128
#define TK 16

__device__ __forceinline__ float gelu_new(float xv) {
    float c = 0.7978845608028654f;
    float t = tanhf(c * (xv + 0.044715f * xv * xv * xv));
    return 0.5f * xv * (1.f + t);
}

__global__ void __launch_bounds__(256)
gemm_kernel(const float* __restrict__ A, const float* __restrict__ W,
            const float* __restrict__ bias, float* __restrict__ C,
            int M, int N, int K, int mode)
{
    __shared__ __align__(16) float As[TK][TM]; // As[k][m]
    __shared__ __align__(16) float Bs[TK][TN]; // Bs[k][n]
    int tid = threadIdx.x;
    int tx = tid & 15;       // n-dir
    int ty = tid >> 4;       // m-dir
    int m0 = blockIdx.y * TM;
    int n0 = blockIdx.x * TN;

    // loaders: A tile (transpose into As), B tile
    int a_m  = tid >> 1;          // 0..127
    int a_k0 = (tid & 1) * 8;     // 0 or 8
    int b_k  = tid >> 4;          // 0..15
    int b_n0 = (tid & 15) * 8;
    bool am_ok = (m0 + a_m) < M;

    float acc[8][8];
#pragma unroll
    for (int i = 0; i < 8; i++)
#pragma unroll
        for (int j = 0; j < 8; j++) acc[i][j] = 0.f;

    for (int kt = 0; kt < K; kt += TK) {
        const float* Ap = A + (size_t)(m0 + a_m) * K + kt + a_k0;
#pragma unroll
        for (int i = 0; i < 8; i++)
            As[a_k0 + i][a_m] = am_ok ? Ap[i] : 0.f;
        const float* Wp = W + (size_t)(kt + b_k) * N + n0 + b_n0;
#pragma unroll
        for (int i = 0; i < 8; i += 4)
            *reinterpret_cast<float4*>(&Bs[b_k][b_n0 + i]) =
                *reinterpret_cast<const float4*>(Wp + i);
        __syncthreads();
#pragma unroll
        for (int k = 0; k < TK; k++) {
            float4 a0 = *reinterpret_cast<const float4*>(&As[k][ty * 8]);
            float4 a1 = *reinterpret_cast<const float4*>(&As[k][ty * 8 + 4]);
            float4 b0 = *reinterpret_cast<const float4*>(&Bs[k][tx * 8]);
            float4 b1 = *reinterpret_cast<const float4*>(&Bs[k][tx * 8 + 4]);
            float a[8] = {a0.x,a0.y,a0.z,a0.w,a1.x,a1.y,a1.z,a1.w};
            float b[8] = {b0.x,b0.y,b0.z,b0.w,b1.x,b1.y,b1.z,b1.w};
#pragma unroll
            for (int i = 0; i < 8; i++)
#pragma unroll
                for (int j = 0; j < 8; j++)
                    acc[i][j] = fmaf(a[i], b[j], acc[i][j]);
        }
        __syncthreads();
    }

#pragma unroll
    for (int i = 0; i < 8; i++) {
        int m = m0 + ty * 8 + i;
        if (m >= M) continue;
#pragma unroll
        for (int j = 0; j < 8; j++) {
            int n = n0 + tx * 8 + j;
            float v = acc[i][j] + bias[n];
            size_t idx = (size_t)m * N + n;
            if (mode == 1) v = gelu_new(v);
            if (mode == 2) C[idx] += v;
            else           C[idx] = v;
        }
    }
}

// ---------------- fused causal attention: one CTA per (b, head) ----------------
// smem: KT[64][304] transposed keys, V[301][64], per-warp scores[8][304], per-warp q stage
#define KTP 304
#define ATTN_SMEM_FLOATS (HD_*KTP + LSEQ*HD_ + 8*KTP + 8*HD_)

__global__ void __launch_bounds__(256)
attn_kernel(const float* __restrict__ qkv, float* __restrict__ out)
{
    extern __shared__ float sm[];
    float* KT = sm;                          // [64][KTP]
    float* V  = KT + HD_ * KTP;              // [301][64]
    float* SC = V + LSEQ * HD_;              // [8][KTP]
    float* QV = SC + 8 * KTP;                // [8][64]

    int bh = blockIdx.x;
    int b = bh >> 4, hd = bh & 15;
    const float* base = qkv + (size_t)b * LSEQ * (3 * D_);
    int hoff = hd * HD_;

    for (int idx = threadIdx.x; idx < LSEQ * HD_; idx += 256) {
        int j = idx >> 6, d = idx & 63;
        KT[d * KTP + j] = base[(size_t)j * (3 * D_) + D_     + hoff + d];
        V [j * HD_ + d] = base[(size_t)j * (3 * D_) + 2 * D_ + hoff + d];
    }
    __syncthreads();

    int w = threadIdx.x >> 5, lane = threadIdx.x & 31;
    float* sc = SC + w * KTP;
    float* qv = QV + w * HD_;

    for (int q = w; q < LSEQ; q += 8) {
        qv[lane]      = base[(size_t)q * (3 * D_) + hoff + lane];
        qv[lane + 32] = base[(size_t)q * (3 * D_) + hoff + 32 + lane];
        __syncwarp();
        float qr[HD_];
#pragma unroll
        for (int d = 0; d < HD_; d++) qr[d] = qv[d];

        int nk = q + 1;
        float mx = -1e30f;
        for (int j = lane; j < nk; j += 32) {
            float s = 0.f;
#pragma unroll
            for (int d = 0; d < HD_; d++) s = fmaf(qr[d], KT[d * KTP + j], s);
            s *= 0.125f;   // 1/sqrt(64)
            sc[j] = s;
            mx = fmaxf(mx, s);
        }
#pragma unroll
        for (int o = 16; o; o >>= 1) mx = fmaxf(mx, __shfl_xor_sync(0xFFFFFFFFu, mx, o));
        float sum = 0.f;
        for (int j = lane; j < nk; j += 32) {
            float e = expf(sc[j] - mx);
            sc[j] = e;
            sum += e;
        }
#pragma unroll
        for (int o = 16; o; o >>= 1) sum += __shfl_xor_sync(0xFFFFFFFFu, sum, o);
        float inv = 1.f / sum;
        __syncwarp();

        float o0 = 0.f, o1 = 0.f;
        for (int j = 0; j < nk; j++) {
            float p = sc[j];
            o0 = fmaf(p, V[j * HD_ + lane], o0);
            o1 = fmaf(p, V[j * HD_ + 32 + lane], o1);
        }
        size_t orow = (size_t)(b * LSEQ + q) * D_ + hoff;
        out[orow + lane]      = o0 * inv;
        out[orow + 32 + lane] = o1 * inv;
        __syncwarp();
    }
}

// ---------------- fused final-LN + logits + per-position loss/acc ----------------
__global__ void loss_kernel(const float* __restrict__ h,
                            const float* __restrict__ g,
                            const float* __restrict__ beta,
                            const float* __restrict__ pw,   // [D,5]
                            const float* __restrict__ pb,   // [5]
                            const int* __restrict__ actions,
                            const int* __restrict__ tact,
                            float* __restrict__ partial)
{
    __shared__ float red[4];
    __shared__ float lred[5][4];
    int idx = blockIdx.x;
    int b = idx / (CTX_ + 1), t = idx % (CTX_ + 1);
    const float* x = h + (size_t)(b * LSEQ + 3 * t) * D_;
    int tid = threadIdx.x, lane = tid & 31, w = tid >> 5;

    float v[8];
    float s = 0.f;
#pragma unroll
    for (int i = 0; i < 8; i++) { v[i] = x[tid + 128 * i]; s += v[i]; }
#pragma unroll
    for (int o = 16; o; o >>= 1) s += __shfl_xor_sync(0xFFFFFFFFu, s, o);
    if (lane == 0) red[w] = s;
    __syncthreads();
    float mean = (red[0] + red[1] + red[2] + red[3]) * (1.f / 1024.f);
    __syncthreads();
    float s2 = 0.f;
#pragma unroll
    for (int i = 0; i < 8; i++) { float d = v[i] - mean; s2 += d * d; }
#pragma unroll
    for (int o = 16; o; o >>= 1) s2 += __shfl_xor_sync(0xFFFFFFFFu, s2, o);
    if (lane == 0) red[w] = s2;
    __syncthreads();
    float var = (red[0] + red[1] + red[2] + red[3]) * (1.f / 1024.f);
    float inv = 1.f / sqrtf(var + 1e-5f);

    float acc[NA_] = {0.f, 0.f, 0.f, 0.f, 0.f};
#pragma unroll
    for (int i = 0; i < 8; i++) {
        int c = tid + 128 * i;
        float xn = (v[i] - mean) * inv * g[c] + beta[c];
#pragma unroll
        for (int a = 0; a < NA_; a++)
            acc[a] = fmaf(xn, pw[c * NA_ + a], acc[a]);
    }
#pragma unroll
    for (int a = 0; a < NA_; a++) {
        float tv = acc[a];
#pragma unroll
        for (int o = 16; o; o >>= 1) tv += __shfl_xor_sync(0xFFFFFFFFu, tv, o);
        if (lane == 0) lred[a][w] = tv;
    }
    __syncthreads();
    if (tid == 0) {
        float logit[NA_];
#pragma unroll
        for (int a = 0; a < NA_; a++)
            logit[a] = lred[a][0] + lred[a][1] + lred[a][2] + lred[a][3] + pb[a];
        int target = (t < CTX_) ? actions[b * CTX_ + t] : tact[b];
        float mx = logit[0]; int am = 0;
#pragma unroll
        for (int a = 1; a < NA_; a++) if (logit[a] > mx) { mx = logit[a]; am = a; }
        float se = 0.f;
#pragma unroll
        for (int a = 0; a < NA_; a++) se += expf(logit[a] - mx);
        float lse = mx + logf(se);
        float sl = 0.f;
#pragma unroll
        for (int a = 0; a < NA_; a++) sl += (logit[a] - lse);
        float nll = -(logit[target] - lse);
        float smooth = -sl * (1.f / NA_);
        partial[2 * idx]     = 0.9f * nll + 0.1f * smooth;
        partial[2 * idx + 1] = (am == target) ? 1.f : 0.f;
    }
}

__global__ void reduce_kernel(const float* __restrict__ partial, float* __restrict__ out)
{
    __shared__ float rl[8], ra[8];
    int tid = threadIdx.x, lane = tid & 31, w = tid >> 5;
    float l = 0.f, a = 0.f;
    for (int i = tid; i < NPOS; i += 256) {
        l += partial[2 * i];
        a += partial[2 * i + 1];
    }
#pragma unroll
    for (int o = 16; o; o >>= 1) {
        l += __shfl_xor_sync(0xFFFFFFFFu, l, o);
        a += __shfl_xor_sync(0xFFFFFFFFu, a, o);
    }
    if (lane == 0) { rl[w] = l; ra[w] = a; }
    __syncthreads();
    if (tid == 0) {
        float L = 0.f, A = 0.f;
#pragma unroll
        for (int i = 0; i < 8; i++) { L += rl[i]; A += ra[i]; }
        out[0] = L * (1.f / NPOS);
        out[1] = A * (1.f / NPOS);
    }
}

// ---------------- launch ----------------
static inline void launch_gemm(const float* A, const float* W, const float* bias,
                               float* C, int M, int N, int K, int mode)
{
    dim3 grid((N + TN - 1) / TN, (M + TM - 1) / TM);
    gemm_kernel<<<grid, 256>>>(A, W, bias, C, M, N, K, mode);
}

extern "C" void kernel_launch(void* const* d_in, const int* in_sizes, int n_in,
                              void* d_out, int out_size)
{
    const int*   states  = (const int*)  d_in[0];
    const int*   actions = (const int*)  d_in[1];
    const float* rewards = (const float*)d_in[2];
    const int*   qstates = (const int*)  d_in[3];
    const int*   tact    = (const int*)  d_in[4];
    const float* wpe     = (const float*)d_in[5];
    const float* e_state = (const float*)d_in[6];
    const float* e_act   = (const float*)d_in[7];
    const float* erw     = (const float*)d_in[8];
    const float* erb     = (const float*)d_in[9];
    const float* ln1g    = (const float*)d_in[10];
    const float* ln1b    = (const float*)d_in[11];
    const float* attnw   = (const float*)d_in[12];
    const float* attnb   = (const float*)d_in[13];
    const float* apw     = (const float*)d_in[14];
    const float* apb     = (const float*)d_in[15];
    const float* ln2g    = (const float*)d_in[16];
    const float* ln2b    = (const float*)d_in[17];
    const float* fcw     = (const float*)d_in[18];
    const float* fcb     = (const float*)d_in[19];
    const float* mpw     = (const float*)d_in[20];
    const float* mpb     = (const float*)d_in[21];
    const float* lnfg    = (const float*)d_in[22];
    const float* lnfb    = (const float*)d_in[23];
    const float* predw   = (const float*)d_in[24];
    const float* predb   = (const float*)d_in[25];
    float* out = (float*)d_out;

    float *h, *x, *qkv, *attn, *ffn, *partial;
    cudaGetSymbolAddress((void**)&h,    g_h);
    cudaGetSymbolAddress((void**)&x,    g_x);
    cudaGetSymbolAddress((void**)&qkv,  g_qkv);
    cudaGetSymbolAddress((void**)&attn, g_attn);
    cudaGetSymbolAddress((void**)&ffn,  g_ffn);
    cudaGetSymbolAddress((void**)&partial, g_partial);

    const int attn_smem = ATTN_SMEM_FLOATS * (int)sizeof(float);
    cudaFuncSetAttribute(attn_kernel, cudaFuncAttributeMaxDynamicSharedMemorySize, attn_smem);

    embed_kernel<<<NTOK, 256>>>(states, actions, rewards, qstates, wpe,
                                e_state, e_act, erw, erb, h);

    for (int i = 0; i < NL_; i++) {
        ln_kernel<<<NTOK, 256>>>(h, x, ln1g + i * D_, ln1b + i * D_);
        launch_gemm(x, attnw + (size_t)i * D_ * 3 * D_, attnb + i * 3 * D_,
                    qkv, NTOK, 3 * D_, D_, 0);
        attn_kernel<<<B_ * H_, 256, attn_smem>>>(qkv, attn);
        launch_gemm(attn, apw + (size_t)i * D_ * D_, apb + i * D_,
                    h, NTOK, D_, D_, 2);
        ln_kernel<<<NTOK, 256>>>(h, x, ln2g + i * D_, ln2b + i * D_);
        launch_gemm(x, fcw + (size_t)i * D_ * DFF_, fcb + i * DFF_,
                    ffn, NTOK, DFF_, D_, 1);
        launch_gemm(ffn, mpw + (size_t)i * DFF_ * D_, mpb + i * D_,
                    h, NTOK, D_, DFF_, 2);
    }

    loss_kernel<<<NPOS, 128>>>(h, lnfg, lnfb, predw, predb, actions, tact, partial);
    reduce_kernel<<<1, 256>>>(partial, out);
}

// round 4
// speedup vs baseline: 1.8293x; 1.8293x over previous
#include <cuda_runtime.h>
#include <cuda_bf16.h>
#include <mma.h>
#include <math.h>
#include <stdint.h>

using namespace nvcuda;

#define B_    16
#define CTX_  100
#define LSEQ  301
#define D_    1024
#define H_    16
#define HD_   64
#define NL_   4
#define DFF_  4096
#define GRID_ 9
#define NA_   5
#define NTOK  (B_*LSEQ)
#define NPOS  (B_*(CTX_+1))
#define WPOOL 50331648

__device__ float g_h   [NTOK * D_];
__device__ float g_qkv [NTOK * 3 * D_];
__device__ __nv_bfloat16 g_xhi[NTOK * D_];
__device__ __nv_bfloat16 g_xlo[NTOK * D_];
__device__ __nv_bfloat16 g_ahi[NTOK * D_];
__device__ __nv_bfloat16 g_alo[NTOK * D_];
__device__ __nv_bfloat16 g_fhi[NTOK * DFF_];
__device__ __nv_bfloat16 g_flo[NTOK * DFF_];
__device__ __nv_bfloat16 g_whi[WPOOL];
__device__ __nv_bfloat16 g_wlo[WPOOL];
__device__ float g_partial[NPOS * 2];

#define CP16(d, s, z)  asm volatile("cp.async.cg.shared.global [%0], [%1], 16, %2;" :: "r"(d), "l"(s), "r"(z) : "memory")
#define CP_COMMIT()    asm volatile("cp.async.commit_group;" ::: "memory")
#define CP_WAIT(n)     asm volatile("cp.async.wait_group %0;" :: "n"(n) : "memory")

__device__ __forceinline__ uint32_t smem_u32(const void* p) {
    uint32_t a;
    asm("{ .reg .u64 t; cvta.to.shared.u64 t, %1; cvt.u32.u64 %0, t; }" : "=r"(a) : "l"(p));
    return a;
}

__device__ __forceinline__ float gelu_new(float xv) {
    float t = tanhf(0.7978845608028654f * (xv + 0.044715f * xv * xv * xv));
    return 0.5f * xv * (1.f + t);
}

// ---------------- embedding ----------------
__global__ void embed_kernel(const int* __restrict__ states,
                             const int* __restrict__ actions,
                             const float* __restrict__ rewards,
                             const int* __restrict__ qstates,
                             const float* __restrict__ wpe,
                             const float* __restrict__ e_state,
                             const float* __restrict__ e_act,
                             const float* __restrict__ erw,
                             const float* __restrict__ erb,
                             float* __restrict__ h)
{
    int tok = blockIdx.x;
    int b = tok / LSEQ, p = tok % LSEQ;
    const float* src = nullptr;
    float r = 0.f;
    int type = 0;
    if (p == 3 * CTX_) {
        int q = qstates[b * 2] * GRID_ + qstates[b * 2 + 1];
        src = e_state + (size_t)q * D_;
    } else {
        int t = p / 3, m = p % 3;
        if (m == 0) {
            int sid = states[(b * CTX_ + t) * 2] * GRID_ + states[(b * CTX_ + t) * 2 + 1];
            src = e_state + (size_t)sid * D_;
        } else if (m == 1) {
            src = e_act + (size_t)actions[b * CTX_ + t] * D_;
        } else {
            r = rewards[b * CTX_ + t];
            type = 1;
        }
    }
    for (int c = threadIdx.x; c < D_; c += blockDim.x) {
        float v = (type == 0) ? src[c] : fmaf(r, erw[c], erb[c]);
        h[(size_t)tok * D_ + c] = v + wpe[(size_t)p * D_ + c];
    }
}

// ---------------- weight transpose + split: W[K,N] -> T[N,K] hi/lo ----------------
__global__ void wprep_kernel(const float* __restrict__ W,
                             __nv_bfloat16* __restrict__ Thi,
                             __nv_bfloat16* __restrict__ Tlo,
                             int K, int N)
{
    __shared__ float t[32][33];
    int n = blockIdx.x * 32 + threadIdx.x;
    int k0 = blockIdx.y * 32;
#pragma unroll
    for (int r = 0; r < 32; r += 8)
        t[threadIdx.y + r][threadIdx.x] = W[(size_t)(k0 + threadIdx.y + r) * N + n];
    __syncthreads();
    int k = k0 + threadIdx.x;
#pragma unroll
    for (int r = 0; r < 32; r += 8) {
        int nn = blockIdx.x * 32 + threadIdx.y + r;
        float v = t[threadIdx.x][threadIdx.y + r];
        __nv_bfloat16 hi = __float2bfloat16(v);
        Thi[(size_t)nn * K + k] = hi;
        Tlo[(size_t)nn * K + k] = __float2bfloat16(v - __bfloat162float(hi));
    }
}

// ---------------- LayerNorm -> hi/lo ----------------
__global__ void ln_kernel(const float* __restrict__ in,
                          __nv_bfloat16* __restrict__ ohi,
                          __nv_bfloat16* __restrict__ olo,
                          const float* __restrict__ g, const float* __restrict__ beta)
{
    __shared__ float red[8];
    int row = blockIdx.x;
    const float* x = in + (size_t)row * D_;
    int tid = threadIdx.x;
    float v[4];
    float s = 0.f;
#pragma unroll
    for (int i = 0; i < 4; i++) { v[i] = x[tid + 256 * i]; s += v[i]; }
#pragma unroll
    for (int o = 16; o; o >>= 1) s += __shfl_xor_sync(0xFFFFFFFFu, s, o);
    if ((tid & 31) == 0) red[tid >> 5] = s;
    __syncthreads();
    float mean = (red[0]+red[1]+red[2]+red[3]+red[4]+red[5]+red[6]+red[7]) * (1.f/1024.f);
    __syncthreads();
    float s2 = 0.f;
#pragma unroll
    for (int i = 0; i < 4; i++) { float d = v[i] - mean; s2 += d * d; }
#pragma unroll
    for (int o = 16; o; o >>= 1) s2 += __shfl_xor_sync(0xFFFFFFFFu, s2, o);
    if ((tid & 31) == 0) red[tid >> 5] = s2;
    __syncthreads();
    float var = (red[0]+red[1]+red[2]+red[3]+red[4]+red[5]+red[6]+red[7]) * (1.f/1024.f);
    float inv = 1.f / sqrtf(var + 1e-5f);
#pragma unroll
    for (int i = 0; i < 4; i++) {
        int c = tid + 256 * i;
        float y = (v[i] - mean) * inv * g[c] + beta[c];
        __nv_bfloat16 hi = __float2bfloat16(y);
        ohi[(size_t)row * D_ + c] = hi;
        olo[(size_t)row * D_ + c] = __float2bfloat16(y - __bfloat162float(hi));
    }
}

// ---------------- WMMA split-bf16 GEMM ----------------
// C[M,N] = epilogue( (Ahi+Alo)[M,K] @ (Bhi+Blo)[N,K]^T + bias )
// mode 0: C=v (fp32);  1: gelu(v) -> Chi/Clo;  2: C+=v
#define BM 128
#define BN 128
#define BK 32
#define LDT 40
#define TILE_B  (128 * LDT * 2)         // 10240 bytes
#define STAGE_B (4 * TILE_B)            // 40960
#define STAGES  3
#define GEMM_SMEM (STAGES * STAGE_B)    // 122880
#define LDS_ 132

__global__ void __launch_bounds__(256, 1)
gemm_wmma(const __nv_bfloat16* __restrict__ Ahi, const __nv_bfloat16* __restrict__ Alo,
          const __nv_bfloat16* __restrict__ Bhi, const __nv_bfloat16* __restrict__ Blo,
          const float* __restrict__ bias, float* __restrict__ C,
          __nv_bfloat16* __restrict__ Chi, __nv_bfloat16* __restrict__ Clo,
          int M, int N, int K, int mode)
{
    extern __shared__ __align__(16) char smem[];
    uint32_t sbase = smem_u32(smem);
    int tid = threadIdx.x, wid = tid >> 5;
    int m0 = blockIdx.y * BM, n0 = blockIdx.x * BN;
    int wm = wid >> 2;      // 0..1 (64 rows)
    int wn = wid & 3;       // 0..3 (32 cols)

    // load geometry: 2 chunks per matrix per thread (512 chunks / 256 thr)
    uint32_t so[2];
    unsigned ao[2], bo[2], szA[2];
#pragma unroll
    for (int i = 0; i < 2; i++) {
        int c = tid + 256 * i;
        int r = c >> 2, gb = c & 3;
        so[i] = (uint32_t)(r * (LDT * 2) + gb * 16);
        bool ok = (m0 + r) < M;
        ao[i] = ok ? ((unsigned)(m0 + r) * (unsigned)K + gb * 8) : 0u;
        bo[i] = (unsigned)(n0 + r) * (unsigned)K + gb * 8;
        szA[i] = ok ? 16u : 0u;
    }
    const int nk = K / BK;

    auto load_tile = [&](int kt) {
        uint32_t st = sbase + (uint32_t)(kt % STAGES) * STAGE_B;
        unsigned ko = (unsigned)kt * BK;
#pragma unroll
        for (int i = 0; i < 2; i++) {
            CP16(st + so[i],            Ahi + ao[i] + ko, szA[i]);
            CP16(st + TILE_B + so[i],   Alo + ao[i] + ko, szA[i]);
            CP16(st + 2*TILE_B + so[i], Bhi + bo[i] + ko, 16u);
            CP16(st + 3*TILE_B + so[i], Blo + bo[i] + ko, 16u);
        }
    };

    wmma::fragment<wmma::accumulator, 16, 16, 16, float> acc[4][2];
#pragma unroll
    for (int i = 0; i < 4; i++)
#pragma unroll
        for (int j = 0; j < 2; j++) wmma::fill_fragment(acc[i][j], 0.f);

#pragma unroll
    for (int s = 0; s < STAGES; s++) {
        if (s < nk) load_tile(s);
        CP_COMMIT();
    }

    for (int kt = 0; kt < nk; kt++) {
        CP_WAIT(2);
        __syncthreads();
        const char* st = smem + (size_t)(kt % STAGES) * STAGE_B;
        const __nv_bfloat16* sah = (const __nv_bfloat16*)(st);
        const __nv_bfloat16* sal = (const __nv_bfloat16*)(st + TILE_B);
        const __nv_bfloat16* sbh = (const __nv_bfloat16*)(st + 2*TILE_B);
        const __nv_bfloat16* sbl = (const __nv_bfloat16*)(st + 3*TILE_B);
#pragma unroll
        for (int ks = 0; ks < 2; ks++) {
            wmma::fragment<wmma::matrix_a, 16, 16, 16, __nv_bfloat16, wmma::row_major> ah[4], al[4];
            wmma::fragment<wmma::matrix_b, 16, 16, 16, __nv_bfloat16, wmma::col_major> bh[2], bl[2];
#pragma unroll
            for (int j = 0; j < 2; j++) {
                const __nv_bfloat16* pb = sbh + (wn * 32 + j * 16) * LDT + ks * 16;
                wmma::load_matrix_sync(bh[j], pb, LDT);
                wmma::load_matrix_sync(bl[j], sbl + (wn * 32 + j * 16) * LDT + ks * 16, LDT);
            }
#pragma unroll
            for (int i = 0; i < 4; i++) {
                wmma::load_matrix_sync(ah[i], sah + (wm * 64 + i * 16) * LDT + ks * 16, LDT);
                wmma::load_matrix_sync(al[i], sal + (wm * 64 + i * 16) * LDT + ks * 16, LDT);
            }
#pragma unroll
            for (int i = 0; i < 4; i++)
#pragma unroll
                for (int j = 0; j < 2; j++) {
                    wmma::mma_sync(acc[i][j], ah[i], bh[j], acc[i][j]);
                    wmma::mma_sync(acc[i][j], ah[i], bl[j], acc[i][j]);
                    wmma::mma_sync(acc[i][j], al[i], bh[j], acc[i][j]);
                }
        }
        __syncthreads();
        if (kt + STAGES < nk) load_tile(kt + STAGES);
        CP_COMMIT();
    }
    CP_WAIT(0);
    __syncthreads();

    // epilogue via fp32 staging (reuse pipeline smem)
    float* stg = (float*)smem;
#pragma unroll
    for (int i = 0; i < 4; i++)
#pragma unroll
        for (int j = 0; j < 2; j++)
            wmma::store_matrix_sync(stg + (wm * 64 + i * 16) * LDS_ + (wn * 32 + j * 16),
                                    acc[i][j], LDS_, wmma::mem_row_major);
    __syncthreads();

#pragma unroll
    for (int i = 0; i < 64; i++) {
        int id = tid + 256 * i;
        int r = id >> 7, cc = id & 127;
        int m = m0 + r;
        if (m < M) {
            int n = n0 + cc;
            float v = stg[r * LDS_ + cc] + bias[n];
            size_t idx = (size_t)m * N + n;
            if (mode == 0) {
                C[idx] = v;
            } else if (mode == 1) {
                float gv = gelu_new(v);
                __nv_bfloat16 hi = __float2bfloat16(gv);
                Chi[idx] = hi;
                Clo[idx] = __float2bfloat16(gv - __bfloat162float(hi));
            } else {
                C[idx] += v;
            }
        }
    }
}

// ---------------- attention ----------------
#define KTP 304
#define ATTN_SMEM_FLOATS (HD_*KTP + LSEQ*HD_ + 8*KTP + 8*HD_)

__global__ void __launch_bounds__(256)
attn_kernel(const float* __restrict__ qkv,
            __nv_bfloat16* __restrict__ ohi, __nv_bfloat16* __restrict__ olo)
{
    extern __shared__ float sm[];
    float* KT = sm;
    float* V  = KT + HD_ * KTP;
    float* SC = V + LSEQ * HD_;
    float* QV = SC + 8 * KTP;

    int bh = blockIdx.x;
    int b = bh >> 4, hd = bh & 15;
    const float* base = qkv + (size_t)b * LSEQ * (3 * D_);
    int hoff = hd * HD_;

    for (int idx = threadIdx.x; idx < LSEQ * HD_; idx += 256) {
        int j = idx >> 6, d = idx & 63;
        KT[d * KTP + j] = base[(size_t)j * (3 * D_) + D_     + hoff + d];
        V [j * HD_ + d] = base[(size_t)j * (3 * D_) + 2 * D_ + hoff + d];
    }
    __syncthreads();

    int w = threadIdx.x >> 5, lane = threadIdx.x & 31;
    float* sc = SC + w * KTP;
    float* qv = QV + w * HD_;

    for (int q = w; q < LSEQ; q += 8) {
        qv[lane]      = base[(size_t)q * (3 * D_) + hoff + lane];
        qv[lane + 32] = base[(size_t)q * (3 * D_) + hoff + 32 + lane];
        __syncwarp();
        float qr[HD_];
#pragma unroll
        for (int d = 0; d < HD_; d++) qr[d] = qv[d];

        int nk = q + 1;
        float mx = -1e30f;
        for (int j = lane; j < nk; j += 32) {
            float s = 0.f;
#pragma unroll
            for (int d = 0; d < HD_; d++) s = fmaf(qr[d], KT[d * KTP + j], s);
            s *= 0.125f;
            sc[j] = s;
            mx = fmaxf(mx, s);
        }
#pragma unroll
        for (int o = 16; o; o >>= 1) mx = fmaxf(mx, __shfl_xor_sync(0xFFFFFFFFu, mx, o));
        float sum = 0.f;
        for (int j = lane; j < nk; j += 32) {
            float e = expf(sc[j] - mx);
            sc[j] = e;
            sum += e;
        }
#pragma unroll
        for (int o = 16; o; o >>= 1) sum += __shfl_xor_sync(0xFFFFFFFFu, sum, o);
        float inv = 1.f / sum;
        __syncwarp();

        float a0=0.f,a1=0.f,a2=0.f,a3=0.f, b0=0.f,b1=0.f,b2=0.f,b3=0.f;
        int j = 0;
        for (; j + 4 <= nk; j += 4) {
            float p0 = sc[j], p1 = sc[j+1], p2 = sc[j+2], p3 = sc[j+3];
            a0 = fmaf(p0, V[(j  ) * HD_ + lane], a0);
            b0 = fmaf(p0, V[(j  ) * HD_ + 32 + lane], b0);
            a1 = fmaf(p1, V[(j+1) * HD_ + lane], a1);
            b1 = fmaf(p1, V[(j+1) * HD_ + 32 + lane], b1);
            a2 = fmaf(p2, V[(j+2) * HD_ + lane], a2);
            b2 = fmaf(p2, V[(j+2) * HD_ + 32 + lane], b2);
            a3 = fmaf(p3, V[(j+3) * HD_ + lane], a3);
            b3 = fmaf(p3, V[(j+3) * HD_ + 32 + lane], b3);
        }
        for (; j < nk; j++) {
            float p = sc[j];
            a0 = fmaf(p, V[j * HD_ + lane], a0);
            b0 = fmaf(p, V[j * HD_ + 32 + lane], b0);
        }
        float o0 = ((a0 + a1) + (a2 + a3)) * inv;
        float o1 = ((b0 + b1) + (b2 + b3)) * inv;

        size_t orow = (size_t)(b * LSEQ + q) * D_ + hoff;
        __nv_bfloat16 h0 = __float2bfloat16(o0);
        __nv_bfloat16 h1 = __float2bfloat16(o1);
        ohi[orow + lane]      = h0;
        olo[orow + lane]      = __float2bfloat16(o0 - __bfloat162float(h0));
        ohi[orow + 32 + lane] = h1;
        olo[orow + 32 + lane] = __float2bfloat16(o1 - __bfloat162float(h1));
        __syncwarp();
    }
}

// ---------------- loss ----------------
__global__ void loss_kernel(const float* __restrict__ h,
                            const float* __restrict__ g,
                            const float* __restrict__ beta,
                            const float* __restrict__ pw,
                            const float* __restrict__ pb,
                            const int* __restrict__ actions,
                            const int* __restrict__ tact,
                            float* __restrict__ partial)
{
    __shared__ float red[4];
    __shared__ float lred[5][4];
    int idx = blockIdx.x;
    int b = idx / (CTX_ + 1), t = idx % (CTX_ + 1);
    const float* x = h + (size_t)(b * LSEQ + 3 * t) * D_;
    int tid = threadIdx.x, lane = tid & 31, w = tid >> 5;

    float v[8];
    float s = 0.f;
#pragma unroll
    for (int i = 0; i < 8; i++) { v[i] = x[tid + 128 * i]; s += v[i]; }
#pragma unroll
    for (int o = 16; o; o >>= 1) s += __shfl_xor_sync(0xFFFFFFFFu, s, o);
    if (lane == 0) red[w] = s;
    __syncthreads();
    float mean = (red[0] + red[1] + red[2] + red[3]) * (1.f / 1024.f);
    __syncthreads();
    float s2 = 0.f;
#pragma unroll
    for (int i = 0; i < 8; i++) { float d = v[i] - mean; s2 += d * d; }
#pragma unroll
    for (int o = 16; o; o >>= 1) s2 += __shfl_xor_sync(0xFFFFFFFFu, s2, o);
    if (lane == 0) red[w] = s2;
    __syncthreads();
    float var = (red[0] + red[1] + red[2] + red[3]) * (1.f / 1024.f);
    float inv = 1.f / sqrtf(var + 1e-5f);

    float acc[NA_] = {0.f, 0.f, 0.f, 0.f, 0.f};
#pragma unroll
    for (int i = 0; i < 8; i++) {
        int c = tid + 128 * i;
        float xn = (v[i] - mean) * inv * g[c] + beta[c];
#pragma unroll
        for (int a = 0; a < NA_; a++)
            acc[a] = fmaf(xn, pw[c * NA_ + a], acc[a]);
    }
#pragma unroll
    for (int a = 0; a < NA_; a++) {
        float tv = acc[a];
#pragma unroll
        for (int o = 16; o; o >>= 1) tv += __shfl_xor_sync(0xFFFFFFFFu, tv, o);
        if (lane == 0) lred[a][w] = tv;
    }
    __syncthreads();
    if (tid == 0) {
        float logit[NA_];
#pragma unroll
        for (int a = 0; a < NA_; a++)
            logit[a] = lred[a][0] + lred[a][1] + lred[a][2] + lred[a][3] + pb[a];
        int target = (t < CTX_) ? actions[b * CTX_ + t] : tact[b];
        float mx = logit[0]; int am = 0;
#pragma unroll
        for (int a = 1; a < NA_; a++) if (logit[a] > mx) { mx = logit[a]; am = a; }
        float se = 0.f;
#pragma unroll
        for (int a = 0; a < NA_; a++) se += expf(logit[a] - mx);
        float lse = mx + logf(se);
        float sl = 0.f;
#pragma unroll
        for (int a = 0; a < NA_; a++) sl += (logit[a] - lse);
        float nll = -(logit[target] - lse);
        float smooth = -sl * (1.f / NA_);
        partial[2 * idx]     = 0.9f * nll + 0.1f * smooth;
        partial[2 * idx + 1] = (am == target) ? 1.f : 0.f;
    }
}

__global__ void reduce_kernel(const float* __restrict__ partial, float* __restrict__ out)
{
    __shared__ float rl[8], ra[8];
    int tid = threadIdx.x, lane = tid & 31, w = tid >> 5;
    float l = 0.f, a = 0.f;
    for (int i = tid; i < NPOS; i += 256) {
        l += partial[2 * i];
        a += partial[2 * i + 1];
    }
#pragma unroll
    for (int o = 16; o; o >>= 1) {
        l += __shfl_xor_sync(0xFFFFFFFFu, l, o);
        a += __shfl_xor_sync(0xFFFFFFFFu, a, o);
    }
    if (lane == 0) { rl[w] = l; ra[w] = a; }
    __syncthreads();
    if (tid == 0) {
        float L = 0.f, A = 0.f;
#pragma unroll
        for (int i = 0; i < 8; i++) { L += rl[i]; A += ra[i]; }
        out[0] = L * (1.f / NPOS);
        out[1] = A * (1.f / NPOS);
    }
}

// ---------------- host ----------------
static inline void launch_gemm(const __nv_bfloat16* Ahi, const __nv_bfloat16* Alo,
                               const __nv_bfloat16* Bhi, const __nv_bfloat16* Blo,
                               const float* bias, float* C,
                               __nv_bfloat16* Chi, __nv_bfloat16* Clo,
                               int M, int N, int K, int mode)
{
    dim3 grid(N / BN, (M + BM - 1) / BM);
    gemm_wmma<<<grid, 256, GEMM_SMEM>>>(Ahi, Alo, Bhi, Blo, bias, C, Chi, Clo, M, N, K, mode);
}

extern "C" void kernel_launch(void* const* d_in, const int* in_sizes, int n_in,
                              void* d_out, int out_size)
{
    const int*   states  = (const int*)  d_in[0];
    const int*   actions = (const int*)  d_in[1];
    const float* rewards = (const float*)d_in[2];
    const int*   qstates = (const int*)  d_in[3];
    const int*   tact    = (const int*)  d_in[4];
    const float* wpe     = (const float*)d_in[5];
    const float* e_state = (const float*)d_in[6];
    const float* e_act   = (const float*)d_in[7];
    const float* erw     = (const float*)d_in[8];
    const float* erb     = (const float*)d_in[9];
    const float* ln1g    = (const float*)d_in[10];
    const float* ln1b    = (const float*)d_in[11];
    const float* attnw   = (const float*)d_in[12];
    const float* attnb   = (const float*)d_in[13];
    const float* apw     = (const float*)d_in[14];
    const float* apb     = (const float*)d_in[15];
    const float* ln2g    = (const float*)d_in[16];
    const float* ln2b    = (const float*)d_in[17];
    const float* fcw     = (const float*)d_in[18];
    const float* fcb     = (const float*)d_in[19];
    const float* mpw     = (const float*)d_in[20];
    const float* mpb     = (const float*)d_in[21];
    const float* lnfg    = (const float*)d_in[22];
    const float* lnfb    = (const float*)d_in[23];
    const float* predw   = (const float*)d_in[24];
    const float* predb   = (const float*)d_in[25];
    float* out = (float*)d_out;

    float *h, *qkv, *partial;
    __nv_bfloat16 *xhi, *xlo, *ahi, *alo, *fhi, *flo, *whi, *wlo;
    cudaGetSymbolAddress((void**)&h,    g_h);
    cudaGetSymbolAddress((void**)&qkv,  g_qkv);
    cudaGetSymbolAddress((void**)&partial, g_partial);
    cudaGetSymbolAddress((void**)&xhi,  g_xhi);
    cudaGetSymbolAddress((void**)&xlo,  g_xlo);
    cudaGetSymbolAddress((void**)&ahi,  g_ahi);
    cudaGetSymbolAddress((void**)&alo,  g_alo);
    cudaGetSymbolAddress((void**)&fhi,  g_fhi);
    cudaGetSymbolAddress((void**)&flo,  g_flo);
    cudaGetSymbolAddress((void**)&whi,  g_whi);
    cudaGetSymbolAddress((void**)&wlo,  g_wlo);

    const int attn_smem = ATTN_SMEM_FLOATS * (int)sizeof(float);
    cudaFuncSetAttribute(attn_kernel, cudaFuncAttributeMaxDynamicSharedMemorySize, attn_smem);
    cudaFuncSetAttribute(gemm_wmma, cudaFuncAttributeMaxDynamicSharedMemorySize, GEMM_SMEM);

    const size_t WPL = 12582912;
    const size_t OFF_QKV = 0, OFF_PROJ = 3145728, OFF_FC = 4194304, OFF_MP = 8388608;
    for (int i = 0; i < NL_; i++) {
        size_t off = (size_t)i * WPL;
        wprep_kernel<<<dim3(3 * D_ / 32, D_ / 32), dim3(32, 8)>>>(
            attnw + (size_t)i * D_ * 3 * D_, whi + off + OFF_QKV, wlo + off + OFF_QKV, D_, 3 * D_);
        wprep_kernel<<<dim3(D_ / 32, D_ / 32), dim3(32, 8)>>>(
            apw + (size_t)i * D_ * D_, whi + off + OFF_PROJ, wlo + off + OFF_PROJ, D_, D_);
        wprep_kernel<<<dim3(DFF_ / 32, D_ / 32), dim3(32, 8)>>>(
            fcw + (size_t)i * D_ * DFF_, whi + off + OFF_FC, wlo + off + OFF_FC, D_, DFF_);
        wprep_kernel<<<dim3(D_ / 32, DFF_ / 32), dim3(32, 8)>>>(
            mpw + (size_t)i * DFF_ * D_, whi + off + OFF_MP, wlo + off + OFF_MP, DFF_, D_);
    }

    embed_kernel<<<NTOK, 256>>>(states, actions, rewards, qstates, wpe,
                                e_state, e_act, erw, erb, h);

    for (int i = 0; i < NL_; i++) {
        size_t off = (size_t)i * WPL;
        ln_kernel<<<NTOK, 256>>>(h, xhi, xlo, ln1g + i * D_, ln1b + i * D_);
        launch_gemm(xhi, xlo, whi + off + OFF_QKV, wlo + off + OFF_QKV,
                    attnb + i * 3 * D_, qkv, nullptr, nullptr, NTOK, 3 * D_, D_, 0);
        attn_kernel<<<B_ * H_, 256, attn_smem>>>(qkv, ahi, alo);
        launch_gemm(ahi, alo, whi + off + OFF_PROJ, wlo + off + OFF_PROJ,
                    apb + i * D_, h, nullptr, nullptr, NTOK, D_, D_, 2);
        ln_kernel<<<NTOK, 256>>>(h, xhi, xlo, ln2g + i * D_, ln2b + i * D_);
        launch_gemm(xhi, xlo, whi + off + OFF_FC, wlo + off + OFF_FC,
                    fcb + i * DFF_, nullptr, fhi, flo, NTOK, DFF_, D_, 1);
        launch_gemm(fhi, flo, whi + off + OFF_MP, wlo + off + OFF_MP,
                    mpb + i * D_, h, nullptr, nullptr, NTOK, D_, DFF_, 2);
    }

    loss_kernel<<<NPOS, 128>>>(h, lnfg, lnfb, predw, predb, actions, tact, partial);
    reduce_kernel<<<1, 256>>>(partial, out);
}

// round 5
// speedup vs baseline: 1.9919x; 1.0889x over previous
#include <cuda_runtime.h>
#include <cuda_bf16.h>
#include <mma.h>
#include <math.h>
#include <stdint.h>

using namespace nvcuda;

#define B_    16
#define CTX_  100
#define LSEQ  301
#define D_    1024
#define H_    16
#define HD_   64
#define NL_   4
#define DFF_  4096
#define GRID_ 9
#define NA_   5
#define NTOK  (B_*LSEQ)
#define NPOS  (B_*(CTX_+1))
#define WPOOL 50331648

__device__ float g_h   [NTOK * D_];
__device__ float g_qkv [NTOK * 3 * D_];
__device__ __nv_bfloat16 g_xhi[NTOK * D_];
__device__ __nv_bfloat16 g_xlo[NTOK * D_];
__device__ __nv_bfloat16 g_ahi[NTOK * D_];
__device__ __nv_bfloat16 g_alo[NTOK * D_];
__device__ __nv_bfloat16 g_fhi[NTOK * DFF_];
__device__ __nv_bfloat16 g_flo[NTOK * DFF_];
__device__ __nv_bfloat16 g_whi[WPOOL];
__device__ __nv_bfloat16 g_wlo[WPOOL];
__device__ float g_partial[NPOS * 2];

#define CP16(d, s, z)  asm volatile("cp.async.cg.shared.global [%0], [%1], 16, %2;" :: "r"(d), "l"(s), "r"(z) : "memory")
#define CP_COMMIT()    asm volatile("cp.async.commit_group;" ::: "memory")
#define CP_WAIT(n)     asm volatile("cp.async.wait_group %0;" :: "n"(n) : "memory")

__device__ __forceinline__ uint32_t smem_u32(const void* p) {
    uint32_t a;
    asm("{ .reg .u64 t; cvta.to.shared.u64 t, %1; cvt.u32.u64 %0, t; }" : "=r"(a) : "l"(p));
    return a;
}

__device__ __forceinline__ float gelu_new(float xv) {
    float t = tanhf(0.7978845608028654f * (xv + 0.044715f * xv * xv * xv));
    return 0.5f * xv * (1.f + t);
}

// ---------------- embedding ----------------
__global__ void embed_kernel(const int* __restrict__ states,
                             const int* __restrict__ actions,
                             const float* __restrict__ rewards,
                             const int* __restrict__ qstates,
                             const float* __restrict__ wpe,
                             const float* __restrict__ e_state,
                             const float* __restrict__ e_act,
                             const float* __restrict__ erw,
                             const float* __restrict__ erb,
                             float* __restrict__ h)
{
    int tok = blockIdx.x;
    int b = tok / LSEQ, p = tok % LSEQ;
    const float* src = nullptr;
    float r = 0.f;
    int type = 0;
    if (p == 3 * CTX_) {
        int q = qstates[b * 2] * GRID_ + qstates[b * 2 + 1];
        src = e_state + (size_t)q * D_;
    } else {
        int t = p / 3, m = p % 3;
        if (m == 0) {
            int sid = states[(b * CTX_ + t) * 2] * GRID_ + states[(b * CTX_ + t) * 2 + 1];
            src = e_state + (size_t)sid * D_;
        } else if (m == 1) {
            src = e_act + (size_t)actions[b * CTX_ + t] * D_;
        } else {
            r = rewards[b * CTX_ + t];
            type = 1;
        }
    }
    for (int c = threadIdx.x; c < D_; c += blockDim.x) {
        float v = (type == 0) ? src[c] : fmaf(r, erw[c], erb[c]);
        h[(size_t)tok * D_ + c] = v + wpe[(size_t)p * D_ + c];
    }
}

// ---------------- weight transpose + split: W[K,N] -> T[N,K] hi/lo ----------------
__global__ void wprep_kernel(const float* __restrict__ W,
                             __nv_bfloat16* __restrict__ Thi,
                             __nv_bfloat16* __restrict__ Tlo,
                             int K, int N)
{
    __shared__ float t[32][33];
    int n = blockIdx.x * 32 + threadIdx.x;
    int k0 = blockIdx.y * 32;
#pragma unroll
    for (int r = 0; r < 32; r += 8)
        t[threadIdx.y + r][threadIdx.x] = W[(size_t)(k0 + threadIdx.y + r) * N + n];
    __syncthreads();
    int k = k0 + threadIdx.x;
#pragma unroll
    for (int r = 0; r < 32; r += 8) {
        int nn = blockIdx.x * 32 + threadIdx.y + r;
        float v = t[threadIdx.x][threadIdx.y + r];
        __nv_bfloat16 hi = __float2bfloat16(v);
        Thi[(size_t)nn * K + k] = hi;
        Tlo[(size_t)nn * K + k] = __float2bfloat16(v - __bfloat162float(hi));
    }
}

// ---------------- LayerNorm -> hi/lo ----------------
__global__ void ln_kernel(const float* __restrict__ in,
                          __nv_bfloat16* __restrict__ ohi,
                          __nv_bfloat16* __restrict__ olo,
                          const float* __restrict__ g, const float* __restrict__ beta)
{
    __shared__ float red[8];
    int row = blockIdx.x;
    const float* x = in + (size_t)row * D_;
    int tid = threadIdx.x;
    float v[4];
    float s = 0.f;
#pragma unroll
    for (int i = 0; i < 4; i++) { v[i] = x[tid + 256 * i]; s += v[i]; }
#pragma unroll
    for (int o = 16; o; o >>= 1) s += __shfl_xor_sync(0xFFFFFFFFu, s, o);
    if ((tid & 31) == 0) red[tid >> 5] = s;
    __syncthreads();
    float mean = (red[0]+red[1]+red[2]+red[3]+red[4]+red[5]+red[6]+red[7]) * (1.f/1024.f);
    __syncthreads();
    float s2 = 0.f;
#pragma unroll
    for (int i = 0; i < 4; i++) { float d = v[i] - mean; s2 += d * d; }
#pragma unroll
    for (int o = 16; o; o >>= 1) s2 += __shfl_xor_sync(0xFFFFFFFFu, s2, o);
    if ((tid & 31) == 0) red[tid >> 5] = s2;
    __syncthreads();
    float var = (red[0]+red[1]+red[2]+red[3]+red[4]+red[5]+red[6]+red[7]) * (1.f/1024.f);
    float inv = 1.f / sqrtf(var + 1e-5f);
#pragma unroll
    for (int i = 0; i < 4; i++) {
        int c = tid + 256 * i;
        float y = (v[i] - mean) * inv * g[c] + beta[c];
        __nv_bfloat16 hi = __float2bfloat16(y);
        ohi[(size_t)row * D_ + c] = hi;
        olo[(size_t)row * D_ + c] = __float2bfloat16(y - __bfloat162float(hi));
    }
}

// ---------------- WMMA split-bf16 GEMM, BK=64 ----------------
// C[M,N] = epilogue( (Ahi+Alo)[M,K] @ (Bhi+Blo)[N,K]^T + bias )
// mode 0: C=v (fp32);  1: gelu(v) -> Chi/Clo;  2: C+=v
#define BM 128
#define BN 128
#define BK 64
#define LDT 72
#define TILE_B  (128 * LDT * 2)         // 18432 bytes
#define STAGE_B (4 * TILE_B)            // 73728
#define STAGES  3
#define GEMM_SMEM (STAGES * STAGE_B)    // 221184
#define LDS_ 132

__global__ void __launch_bounds__(256, 1)
gemm_wmma(const __nv_bfloat16* __restrict__ Ahi, const __nv_bfloat16* __restrict__ Alo,
          const __nv_bfloat16* __restrict__ Bhi, const __nv_bfloat16* __restrict__ Blo,
          const float* __restrict__ bias, float* __restrict__ C,
          __nv_bfloat16* __restrict__ Chi, __nv_bfloat16* __restrict__ Clo,
          int M, int N, int K, int mode)
{
    extern __shared__ __align__(16) char smem[];
    uint32_t sbase = smem_u32(smem);
    int tid = threadIdx.x, wid = tid >> 5;
    int m0 = blockIdx.y * BM, n0 = blockIdx.x * BN;
    int wm = wid >> 2;      // 0..1 (64 rows)
    int wn = wid & 3;       // 0..3 (32 cols)

    // load geometry: 4 chunks per matrix per thread (1024 chunks / 256 thr)
    uint32_t so[4];
    unsigned ao[4], bo[4], szA[4];
#pragma unroll
    for (int i = 0; i < 4; i++) {
        int c = tid + 256 * i;
        int r = c >> 3, gb = c & 7;
        so[i] = (uint32_t)(r * (LDT * 2) + gb * 16);
        bool ok = (m0 + r) < M;
        ao[i] = ok ? ((unsigned)(m0 + r) * (unsigned)K + gb * 8) : 0u;
        bo[i] = (unsigned)(n0 + r) * (unsigned)K + gb * 8;
        szA[i] = ok ? 16u : 0u;
    }
    const int nk = K / BK;

    auto load_tile = [&](int kt) {
        uint32_t st = sbase + (uint32_t)(kt % STAGES) * STAGE_B;
        unsigned ko = (unsigned)kt * BK;
#pragma unroll
        for (int i = 0; i < 4; i++) {
            CP16(st + so[i],            Ahi + ao[i] + ko, szA[i]);
            CP16(st + TILE_B + so[i],   Alo + ao[i] + ko, szA[i]);
            CP16(st + 2*TILE_B + so[i], Bhi + bo[i] + ko, 16u);
            CP16(st + 3*TILE_B + so[i], Blo + bo[i] + ko, 16u);
        }
    };

    wmma::fragment<wmma::accumulator, 16, 16, 16, float> acc[4][2];
#pragma unroll
    for (int i = 0; i < 4; i++)
#pragma unroll
        for (int j = 0; j < 2; j++) wmma::fill_fragment(acc[i][j], 0.f);

#pragma unroll
    for (int s = 0; s < STAGES; s++) {
        if (s < nk) load_tile(s);
        CP_COMMIT();
    }

    for (int kt = 0; kt < nk; kt++) {
        CP_WAIT(2);
        __syncthreads();
        const char* st = smem + (size_t)(kt % STAGES) * STAGE_B;
        const __nv_bfloat16* sah = (const __nv_bfloat16*)(st);
        const __nv_bfloat16* sal = (const __nv_bfloat16*)(st + TILE_B);
        const __nv_bfloat16* sbh = (const __nv_bfloat16*)(st + 2*TILE_B);
        const __nv_bfloat16* sbl = (const __nv_bfloat16*)(st + 3*TILE_B);
#pragma unroll
        for (int ks = 0; ks < 4; ks++) {
            wmma::fragment<wmma::matrix_a, 16, 16, 16, __nv_bfloat16, wmma::row_major> ah[4], al[4];
            wmma::fragment<wmma::matrix_b, 16, 16, 16, __nv_bfloat16, wmma::col_major> bh[2], bl[2];
#pragma unroll
            for (int j = 0; j < 2; j++) {
                wmma::load_matrix_sync(bh[j], sbh + (wn * 32 + j * 16) * LDT + ks * 16, LDT);
                wmma::load_matrix_sync(bl[j], sbl + (wn * 32 + j * 16) * LDT + ks * 16, LDT);
            }
#pragma unroll
            for (int i = 0; i < 4; i++) {
                wmma::load_matrix_sync(ah[i], sah + (wm * 64 + i * 16) * LDT + ks * 16, LDT);
                wmma::load_matrix_sync(al[i], sal + (wm * 64 + i * 16) * LDT + ks * 16, LDT);
            }
#pragma unroll
            for (int i = 0; i < 4; i++)
#pragma unroll
                for (int j = 0; j < 2; j++) {
                    wmma::mma_sync(acc[i][j], ah[i], bh[j], acc[i][j]);
                    wmma::mma_sync(acc[i][j], ah[i], bl[j], acc[i][j]);
                    wmma::mma_sync(acc[i][j], al[i], bh[j], acc[i][j]);
                }
        }
        __syncthreads();
        if (kt + STAGES < nk) load_tile(kt + STAGES);
        CP_COMMIT();
    }
    CP_WAIT(0);
    __syncthreads();

    // epilogue via fp32 staging (reuse pipeline smem)
    float* stg = (float*)smem;
#pragma unroll
    for (int i = 0; i < 4; i++)
#pragma unroll
        for (int j = 0; j < 2; j++)
            wmma::store_matrix_sync(stg + (wm * 64 + i * 16) * LDS_ + (wn * 32 + j * 16),
                                    acc[i][j], LDS_, wmma::mem_row_major);
    __syncthreads();

#pragma unroll
    for (int i = 0; i < 64; i++) {
        int id = tid + 256 * i;
        int r = id >> 7, cc = id & 127;
        int m = m0 + r;
        if (m < M) {
            int n = n0 + cc;
            float v = stg[r * LDS_ + cc] + bias[n];
            size_t idx = (size_t)m * N + n;
            if (mode == 0) {
                C[idx] = v;
            } else if (mode == 1) {
                float gv = gelu_new(v);
                __nv_bfloat16 hi = __float2bfloat16(gv);
                Chi[idx] = hi;
                Clo[idx] = __float2bfloat16(gv - __bfloat162float(hi));
            } else {
                C[idx] += v;
            }
        }
    }
}

// ---------------- attention ----------------
#define KTP 304
#define ATTN_SMEM_FLOATS (HD_*KTP + LSEQ*HD_ + 8*KTP + 8*HD_)

__global__ void __launch_bounds__(256)
attn_kernel(const float* __restrict__ qkv,
            __nv_bfloat16* __restrict__ ohi, __nv_bfloat16* __restrict__ olo)
{
    extern __shared__ float sm[];
    float* KT = sm;
    float* V  = KT + HD_ * KTP;
    float* SC = V + LSEQ * HD_;
    float* QV = SC + 8 * KTP;

    int bh = blockIdx.x;
    int b = bh >> 4, hd = bh & 15;
    const float* base = qkv + (size_t)b * LSEQ * (3 * D_);
    int hoff = hd * HD_;

    for (int idx = threadIdx.x; idx < LSEQ * HD_; idx += 256) {
        int j = idx >> 6, d = idx & 63;
        KT[d * KTP + j] = base[(size_t)j * (3 * D_) + D_     + hoff + d];
        V [j * HD_ + d] = base[(size_t)j * (3 * D_) + 2 * D_ + hoff + d];
    }
    __syncthreads();

    int w = threadIdx.x >> 5, lane = threadIdx.x & 31;
    float* sc = SC + w * KTP;
    float* qv = QV + w * HD_;

    for (int q = w; q < LSEQ; q += 8) {
        qv[lane]      = base[(size_t)q * (3 * D_) + hoff + lane];
        qv[lane + 32] = base[(size_t)q * (3 * D_) + hoff + 32 + lane];
        __syncwarp();
        float qr[HD_];
#pragma unroll
        for (int d = 0; d < HD_; d++) qr[d] = qv[d];

        int nk = q + 1;
        float mx = -1e30f;
        for (int j = lane; j < nk; j += 32) {
            float s = 0.f;
#pragma unroll
            for (int d = 0; d < HD_; d++) s = fmaf(qr[d], KT[d * KTP + j], s);
            s *= 0.125f;
            sc[j] = s;
            mx = fmaxf(mx, s);
        }
#pragma unroll
        for (int o = 16; o; o >>= 1) mx = fmaxf(mx, __shfl_xor_sync(0xFFFFFFFFu, mx, o));
        float sum = 0.f;
        for (int j = lane; j < nk; j += 32) {
            float e = expf(sc[j] - mx);
            sc[j] = e;
            sum += e;
        }
#pragma unroll
        for (int o = 16; o; o >>= 1) sum += __shfl_xor_sync(0xFFFFFFFFu, sum, o);
        float inv = 1.f / sum;
        __syncwarp();

        float a0=0.f,a1=0.f,a2=0.f,a3=0.f, b0=0.f,b1=0.f,b2=0.f,b3=0.f;
        int j = 0;
        for (; j + 4 <= nk; j += 4) {
            float p0 = sc[j], p1 = sc[j+1], p2 = sc[j+2], p3 = sc[j+3];
            a0 = fmaf(p0, V[(j  ) * HD_ + lane], a0);
            b0 = fmaf(p0, V[(j  ) * HD_ + 32 + lane], b0);
            a1 = fmaf(p1, V[(j+1) * HD_ + lane], a1);
            b1 = fmaf(p1, V[(j+1) * HD_ + 32 + lane], b1);
            a2 = fmaf(p2, V[(j+2) * HD_ + lane], a2);
            b2 = fmaf(p2, V[(j+2) * HD_ + 32 + lane], b2);
            a3 = fmaf(p3, V[(j+3) * HD_ + lane], a3);
            b3 = fmaf(p3, V[(j+3) * HD_ + 32 + lane], b3);
        }
        for (; j < nk; j++) {
            float p = sc[j];
            a0 = fmaf(p, V[j * HD_ + lane], a0);
            b0 = fmaf(p, V[j * HD_ + 32 + lane], b0);
        }
        float o0 = ((a0 + a1) + (a2 + a3)) * inv;
        float o1 = ((b0 + b1) + (b2 + b3)) * inv;

        size_t orow = (size_t)(b * LSEQ + q) * D_ + hoff;
        __nv_bfloat16 h0 = __float2bfloat16(o0);
        __nv_bfloat16 h1 = __float2bfloat16(o1);
        ohi[orow + lane]      = h0;
        olo[orow + lane]      = __float2bfloat16(o0 - __bfloat162float(h0));
        ohi[orow + 32 + lane] = h1;
        olo[orow + 32 + lane] = __float2bfloat16(o1 - __bfloat162float(h1));
        __syncwarp();
    }
}

// ---------------- loss ----------------
__global__ void loss_kernel(const float* __restrict__ h,
                            const float* __restrict__ g,
                            const float* __restrict__ beta,
                            const float* __restrict__ pw,
                            const float* __restrict__ pb,
                            const int* __restrict__ actions,
                            const int* __restrict__ tact,
                            float* __restrict__ partial)
{
    __shared__ float red[4];
    __shared__ float lred[5][4];
    int idx = blockIdx.x;
    int b = idx / (CTX_ + 1), t = idx % (CTX_ + 1);
    const float* x = h + (size_t)(b * LSEQ + 3 * t) * D_;
    int tid = threadIdx.x, lane = tid & 31, w = tid >> 5;

    float v[8];
    float s = 0.f;
#pragma unroll
    for (int i = 0; i < 8; i++) { v[i] = x[tid + 128 * i]; s += v[i]; }
#pragma unroll
    for (int o = 16; o; o >>= 1) s += __shfl_xor_sync(0xFFFFFFFFu, s, o);
    if (lane == 0) red[w] = s;
    __syncthreads();
    float mean = (red[0] + red[1] + red[2] + red[3]) * (1.f / 1024.f);
    __syncthreads();
    float s2 = 0.f;
#pragma unroll
    for (int i = 0; i < 8; i++) { float d = v[i] - mean; s2 += d * d; }
#pragma unroll
    for (int o = 16; o; o >>= 1) s2 += __shfl_xor_sync(0xFFFFFFFFu, s2, o);
    if (lane == 0) red[w] = s2;
    __syncthreads();
    float var = (red[0] + red[1] + red[2] + red[3]) * (1.f / 1024.f);
    float inv = 1.f / sqrtf(var + 1e-5f);

    float acc[NA_] = {0.f, 0.f, 0.f, 0.f, 0.f};
#pragma unroll
    for (int i = 0; i < 8; i++) {
        int c = tid + 128 * i;
        float xn = (v[i] - mean) * inv * g[c] + beta[c];
#pragma unroll
        for (int a = 0; a < NA_; a++)
            acc[a] = fmaf(xn, pw[c * NA_ + a], acc[a]);
    }
#pragma unroll
    for (int a = 0; a < NA_; a++) {
        float tv = acc[a];
#pragma unroll
        for (int o = 16; o; o >>= 1) tv += __shfl_xor_sync(0xFFFFFFFFu, tv, o);
        if (lane == 0) lred[a][w] = tv;
    }
    __syncthreads();
    if (tid == 0) {
        float logit[NA_];
#pragma unroll
        for (int a = 0; a < NA_; a++)
            logit[a] = lred[a][0] + lred[a][1] + lred[a][2] + lred[a][3] + pb[a];
        int target = (t < CTX_) ? actions[b * CTX_ + t] : tact[b];
        float mx = logit[0]; int am = 0;
#pragma unroll
        for (int a = 1; a < NA_; a++) if (logit[a] > mx) { mx = logit[a]; am = a; }
        float se = 0.f;
#pragma unroll
        for (int a = 0; a < NA_; a++) se += expf(logit[a] - mx);
        float lse = mx + logf(se);
        float sl = 0.f;
#pragma unroll
        for (int a = 0; a < NA_; a++) sl += (logit[a] - lse);
        float nll = -(logit[target] - lse);
        float smooth = -sl * (1.f / NA_);
        partial[2 * idx]     = 0.9f * nll + 0.1f * smooth;
        partial[2 * idx + 1] = (am == target) ? 1.f : 0.f;
    }
}

__global__ void reduce_kernel(const float* __restrict__ partial, float* __restrict__ out)
{
    __shared__ float rl[8], ra[8];
    int tid = threadIdx.x, lane = tid & 31, w = tid >> 5;
    float l = 0.f, a = 0.f;
    for (int i = tid; i < NPOS; i += 256) {
        l += partial[2 * i];
        a += partial[2 * i + 1];
    }
#pragma unroll
    for (int o = 16; o; o >>= 1) {
        l += __shfl_xor_sync(0xFFFFFFFFu, l, o);
        a += __shfl_xor_sync(0xFFFFFFFFu, a, o);
    }
    if (lane == 0) { rl[w] = l; ra[w] = a; }
    __syncthreads();
    if (tid == 0) {
        float L = 0.f, A = 0.f;
#pragma unroll
        for (int i = 0; i < 8; i++) { L += rl[i]; A += ra[i]; }
        out[0] = L * (1.f / NPOS);
        out[1] = A * (1.f / NPOS);
    }
}

// ---------------- host ----------------
static inline void launch_gemm(const __nv_bfloat16* Ahi, const __nv_bfloat16* Alo,
                               const __nv_bfloat16* Bhi, const __nv_bfloat16* Blo,
                               const float* bias, float* C,
                               __nv_bfloat16* Chi, __nv_bfloat16* Clo,
                               int M, int N, int K, int mode)
{
    dim3 grid(N / BN, (M + BM - 1) / BM);
    gemm_wmma<<<grid, 256, GEMM_SMEM>>>(Ahi, Alo, Bhi, Blo, bias, C, Chi, Clo, M, N, K, mode);
}

extern "C" void kernel_launch(void* const* d_in, const int* in_sizes, int n_in,
                              void* d_out, int out_size)
{
    const int*   states  = (const int*)  d_in[0];
    const int*   actions = (const int*)  d_in[1];
    const float* rewards = (const float*)d_in[2];
    const int*   qstates = (const int*)  d_in[3];
    const int*   tact    = (const int*)  d_in[4];
    const float* wpe     = (const float*)d_in[5];
    const float* e_state = (const float*)d_in[6];
    const float* e_act   = (const float*)d_in[7];
    const float* erw     = (const float*)d_in[8];
    const float* erb     = (const float*)d_in[9];
    const float* ln1g    = (const float*)d_in[10];
    const float* ln1b    = (const float*)d_in[11];
    const float* attnw   = (const float*)d_in[12];
    const float* attnb   = (const float*)d_in[13];
    const float* apw     = (const float*)d_in[14];
    const float* apb     = (const float*)d_in[15];
    const float* ln2g    = (const float*)d_in[16];
    const float* ln2b    = (const float*)d_in[17];
    const float* fcw     = (const float*)d_in[18];
    const float* fcb     = (const float*)d_in[19];
    const float* mpw     = (const float*)d_in[20];
    const float* mpb     = (const float*)d_in[21];
    const float* lnfg    = (const float*)d_in[22];
    const float* lnfb    = (const float*)d_in[23];
    const float* predw   = (const float*)d_in[24];
    const float* predb   = (const float*)d_in[25];
    float* out = (float*)d_out;

    float *h, *qkv, *partial;
    __nv_bfloat16 *xhi, *xlo, *ahi, *alo, *fhi, *flo, *whi, *wlo;
    cudaGetSymbolAddress((void**)&h,    g_h);
    cudaGetSymbolAddress((void**)&qkv,  g_qkv);
    cudaGetSymbolAddress((void**)&partial, g_partial);
    cudaGetSymbolAddress((void**)&xhi,  g_xhi);
    cudaGetSymbolAddress((void**)&xlo,  g_xlo);
    cudaGetSymbolAddress((void**)&ahi,  g_ahi);
    cudaGetSymbolAddress((void**)&alo,  g_alo);
    cudaGetSymbolAddress((void**)&fhi,  g_fhi);
    cudaGetSymbolAddress((void**)&flo,  g_flo);
    cudaGetSymbolAddress((void**)&whi,  g_whi);
    cudaGetSymbolAddress((void**)&wlo,  g_wlo);

    const int attn_smem = ATTN_SMEM_FLOATS * (int)sizeof(float);
    cudaFuncSetAttribute(attn_kernel, cudaFuncAttributeMaxDynamicSharedMemorySize, attn_smem);
    cudaFuncSetAttribute(gemm_wmma, cudaFuncAttributeMaxDynamicSharedMemorySize, GEMM_SMEM);

    const size_t WPL = 12582912;
    const size_t OFF_QKV = 0, OFF_PROJ = 3145728, OFF_FC = 4194304, OFF_MP = 8388608;
    for (int i = 0; i < NL_; i++) {
        size_t off = (size_t)i * WPL;
        wprep_kernel<<<dim3(3 * D_ / 32, D_ / 32), dim3(32, 8)>>>(
            attnw + (size_t)i * D_ * 3 * D_, whi + off + OFF_QKV, wlo + off + OFF_QKV, D_, 3 * D_);
        wprep_kernel<<<dim3(D_ / 32, D_ / 32), dim3(32, 8)>>>(
            apw + (size_t)i * D_ * D_, whi + off + OFF_PROJ, wlo + off + OFF_PROJ, D_, D_);
        wprep_kernel<<<dim3(DFF_ / 32, D_ / 32), dim3(32, 8)>>>(
            fcw + (size_t)i * D_ * DFF_, whi + off + OFF_FC, wlo + off + OFF_FC, D_, DFF_);
        wprep_kernel<<<dim3(D_ / 32, DFF_ / 32), dim3(32, 8)>>>(
            mpw + (size_t)i * DFF_ * D_, whi + off + OFF_MP, wlo + off + OFF_MP, DFF_, D_);
    }

    embed_kernel<<<NTOK, 256>>>(states, actions, rewards, qstates, wpe,
                                e_state, e_act, erw, erb, h);

    for (int i = 0; i < NL_; i++) {
        size_t off = (size_t)i * WPL;
        ln_kernel<<<NTOK, 256>>>(h, xhi, xlo, ln1g + i * D_, ln1b + i * D_);
        launch_gemm(xhi, xlo, whi + off + OFF_QKV, wlo + off + OFF_QKV,
                    attnb + i * 3 * D_, qkv, nullptr, nullptr, NTOK, 3 * D_, D_, 0);
        attn_kernel<<<B_ * H_, 256, attn_smem>>>(qkv, ahi, alo);
        launch_gemm(ahi, alo, whi + off + OFF_PROJ, wlo + off + OFF_PROJ,
                    apb + i * D_, h, nullptr, nullptr, NTOK, D_, D_, 2);
        ln_kernel<<<NTOK, 256>>>(h, xhi, xlo, ln2g + i * D_, ln2b + i * D_);
        launch_gemm(xhi, xlo, whi + off + OFF_FC, wlo + off + OFF_FC,
                    fcb + i * DFF_, nullptr, fhi, flo, NTOK, DFF_, D_, 1);
        launch_gemm(fhi, flo, whi + off + OFF_MP, wlo + off + OFF_MP,
                    mpb + i * D_, h, nullptr, nullptr, NTOK, D_, DFF_, 2);
    }

    loss_kernel<<<NPOS, 128>>>(h, lnfg, lnfb, predw, predb, actions, tact, partial);
    reduce_kernel<<<1, 256>>>(partial, out);
}

// round 6
// speedup vs baseline: 2.5301x; 1.2702x over previous
#include <cuda_runtime.h>
#include <cuda_bf16.h>
#include <math.h>
#include <stdint.h>

#define B_    16
#define CTX_  100
#define LSEQ  301
#define D_    1024
#define H_    16
#define HD_   64
#define NL_   4
#define DFF_  4096
#define GRID_ 9
#define NA_   5
#define NTOK  (B_*LSEQ)
#define NPOS  (B_*(CTX_+1))
#define WPOOL 50331648

__device__ float g_h   [NTOK * D_];
__device__ float g_qkv [NTOK * 3 * D_];
__device__ __nv_bfloat16 g_xhi[NTOK * D_];
__device__ __nv_bfloat16 g_xlo[NTOK * D_];
__device__ __nv_bfloat16 g_ahi[NTOK * D_];
__device__ __nv_bfloat16 g_alo[NTOK * D_];
__device__ __nv_bfloat16 g_fhi[NTOK * DFF_];
__device__ __nv_bfloat16 g_flo[NTOK * DFF_];
__device__ __nv_bfloat16 g_whi[WPOOL];
__device__ __nv_bfloat16 g_wlo[WPOOL];
__device__ float g_partial[NPOS * 2];

#define CP16(d, s, z)  asm volatile("cp.async.cg.shared.global [%0], [%1], 16, %2;" :: "r"(d), "l"(s), "r"(z) : "memory")
#define CP_COMMIT()    asm volatile("cp.async.commit_group;" ::: "memory")
#define CP_WAIT(n)     asm volatile("cp.async.wait_group %0;" :: "n"(n) : "memory")
#define SWZ128(o) ((o) ^ (((o) >> 3) & 0x70))

__device__ __forceinline__ uint32_t smem_u32(const void* p) {
    uint32_t a;
    asm("{ .reg .u64 t; cvta.to.shared.u64 t, %1; cvt.u32.u64 %0, t; }" : "=r"(a) : "l"(p));
    return a;
}
__device__ __forceinline__ void ldsm4(uint32_t* r, uint32_t addr) {
    asm volatile("ldmatrix.sync.aligned.m8n8.x4.shared.b16 {%0,%1,%2,%3}, [%4];"
                 : "=r"(r[0]), "=r"(r[1]), "=r"(r[2]), "=r"(r[3]) : "r"(addr));
}
__device__ __forceinline__ void mma16816(float* c, const uint32_t* a, const uint32_t* b) {
    asm volatile("mma.sync.aligned.m16n8k16.row.col.f32.bf16.bf16.f32 "
                 "{%0,%1,%2,%3}, {%4,%5,%6,%7}, {%8,%9}, {%0,%1,%2,%3};"
                 : "+f"(c[0]), "+f"(c[1]), "+f"(c[2]), "+f"(c[3])
                 : "r"(a[0]), "r"(a[1]), "r"(a[2]), "r"(a[3]), "r"(b[0]), "r"(b[1]));
}

__device__ __forceinline__ float gelu_new(float xv) {
    float t = tanhf(0.7978845608028654f * (xv + 0.044715f * xv * xv * xv));
    return 0.5f * xv * (1.f + t);
}

// ---------------- embedding ----------------
__global__ void embed_kernel(const int* __restrict__ states,
                             const int* __restrict__ actions,
                             const float* __restrict__ rewards,
                             const int* __restrict__ qstates,
                             const float* __restrict__ wpe,
                             const float* __restrict__ e_state,
                             const float* __restrict__ e_act,
                             const float* __restrict__ erw,
                             const float* __restrict__ erb,
                             float* __restrict__ h)
{
    int tok = blockIdx.x;
    int b = tok / LSEQ, p = tok % LSEQ;
    const float* src = nullptr;
    float r = 0.f;
    int type = 0;
    if (p == 3 * CTX_) {
        int q = qstates[b * 2] * GRID_ + qstates[b * 2 + 1];
        src = e_state + (size_t)q * D_;
    } else {
        int t = p / 3, m = p % 3;
        if (m == 0) {
            int sid = states[(b * CTX_ + t) * 2] * GRID_ + states[(b * CTX_ + t) * 2 + 1];
            src = e_state + (size_t)sid * D_;
        } else if (m == 1) {
            src = e_act + (size_t)actions[b * CTX_ + t] * D_;
        } else {
            r = rewards[b * CTX_ + t];
            type = 1;
        }
    }
    for (int c = threadIdx.x; c < D_; c += blockDim.x) {
        float v = (type == 0) ? src[c] : fmaf(r, erw[c], erb[c]);
        h[(size_t)tok * D_ + c] = v + wpe[(size_t)p * D_ + c];
    }
}

// ---------------- weight transpose + split: W[K,N] -> T[N,K] hi/lo ----------------
__global__ void wprep_kernel(const float* __restrict__ W,
                             __nv_bfloat16* __restrict__ Thi,
                             __nv_bfloat16* __restrict__ Tlo,
                             int K, int N)
{
    __shared__ float t[32][33];
    int n = blockIdx.x * 32 + threadIdx.x;
    int k0 = blockIdx.y * 32;
#pragma unroll
    for (int r = 0; r < 32; r += 8)
        t[threadIdx.y + r][threadIdx.x] = W[(size_t)(k0 + threadIdx.y + r) * N + n];
    __syncthreads();
    int k = k0 + threadIdx.x;
#pragma unroll
    for (int r = 0; r < 32; r += 8) {
        int nn = blockIdx.x * 32 + threadIdx.y + r;
        float v = t[threadIdx.x][threadIdx.y + r];
        __nv_bfloat16 hi = __float2bfloat16(v);
        Thi[(size_t)nn * K + k] = hi;
        Tlo[(size_t)nn * K + k] = __float2bfloat16(v - __bfloat162float(hi));
    }
}

// ---------------- LayerNorm -> hi/lo ----------------
__global__ void ln_kernel(const float* __restrict__ in,
                          __nv_bfloat16* __restrict__ ohi,
                          __nv_bfloat16* __restrict__ olo,
                          const float* __restrict__ g, const float* __restrict__ beta)
{
    __shared__ float red[8];
    int row = blockIdx.x;
    const float* x = in + (size_t)row * D_;
    int tid = threadIdx.x;
    float v[4];
    float s = 0.f;
#pragma unroll
    for (int i = 0; i < 4; i++) { v[i] = x[tid + 256 * i]; s += v[i]; }
#pragma unroll
    for (int o = 16; o; o >>= 1) s += __shfl_xor_sync(0xFFFFFFFFu, s, o);
    if ((tid & 31) == 0) red[tid >> 5] = s;
    __syncthreads();
    float mean = (red[0]+red[1]+red[2]+red[3]+red[4]+red[5]+red[6]+red[7]) * (1.f/1024.f);
    __syncthreads();
    float s2 = 0.f;
#pragma unroll
    for (int i = 0; i < 4; i++) { float d = v[i] - mean; s2 += d * d; }
#pragma unroll
    for (int o = 16; o; o >>= 1) s2 += __shfl_xor_sync(0xFFFFFFFFu, s2, o);
    if ((tid & 31) == 0) red[tid >> 5] = s2;
    __syncthreads();
    float var = (red[0]+red[1]+red[2]+red[3]+red[4]+red[5]+red[6]+red[7]) * (1.f/1024.f);
    float inv = 1.f / sqrtf(var + 1e-5f);
#pragma unroll
    for (int i = 0; i < 4; i++) {
        int c = tid + 256 * i;
        float y = (v[i] - mean) * inv * g[c] + beta[c];
        __nv_bfloat16 hi = __float2bfloat16(y);
        ohi[(size_t)row * D_ + c] = hi;
        olo[(size_t)row * D_ + c] = __float2bfloat16(y - __bfloat162float(hi));
    }
}

// ---------------- mma.sync split-bf16 GEMM, BK=64, swizzled ldmatrix ----------------
// C[M,N] = epilogue( (Ahi+Alo)[M,K] @ (Bhi+Blo)[N,K]^T + bias )
// mode 0: C=v (fp32);  1: gelu(v) -> Chi/Clo;  2: C+=v
#define BM 128
#define BN 128
#define BK 64
#define TILE_B  (128 * 128)             // 16384 bytes (128 rows x 128B)
#define STAGE_B (4 * TILE_B)            // 65536
#define STAGES  3
#define GEMM_SMEM (STAGES * STAGE_B)    // 196608
#define LDS_ 132

__global__ void __launch_bounds__(256, 1)
gemm_mma(const __nv_bfloat16* __restrict__ Ahi, const __nv_bfloat16* __restrict__ Alo,
         const __nv_bfloat16* __restrict__ Bhi, const __nv_bfloat16* __restrict__ Blo,
         const float* __restrict__ bias, float* __restrict__ C,
         __nv_bfloat16* __restrict__ Chi, __nv_bfloat16* __restrict__ Clo,
         int M, int N, int K, int mode)
{
    extern __shared__ __align__(128) char smem[];
    uint32_t sbase = smem_u32(smem);
    int tid = threadIdx.x, wid = tid >> 5, lane = tid & 31;
    int m0 = blockIdx.y * BM, n0 = blockIdx.x * BN;
    int wm = wid >> 2;      // 0..1 -> 64 rows
    int wn = wid & 3;       // 0..3 -> 32 cols

    // ---- cp.async geometry: 4 chunks/matrix/thread ----
    uint32_t so[4];
    unsigned ao[4], bo[4], szA[4];
#pragma unroll
    for (int i = 0; i < 4; i++) {
        int c = tid + 256 * i;
        int r = c >> 3, gb = c & 7;
        so[i] = (uint32_t)SWZ128(r * 128 + gb * 16);
        bool ok = (m0 + r) < M;
        ao[i] = ok ? ((unsigned)(m0 + r) * (unsigned)K + gb * 8) : 0u;
        bo[i] = (unsigned)(n0 + r) * (unsigned)K + gb * 8;
        szA[i] = ok ? 16u : 0u;
    }
    const int nk = K / BK;

    auto load_tile = [&](int kt) {
        uint32_t st = sbase + (uint32_t)(kt % STAGES) * STAGE_B;
        unsigned ko = (unsigned)kt * BK;
#pragma unroll
        for (int i = 0; i < 4; i++) {
            CP16(st + so[i],            Ahi + ao[i] + ko, szA[i]);
            CP16(st + TILE_B + so[i],   Alo + ao[i] + ko, szA[i]);
            CP16(st + 2*TILE_B + so[i], Bhi + bo[i] + ko, 16u);
            CP16(st + 3*TILE_B + so[i], Blo + bo[i] + ko, 16u);
        }
    };

    // ---- ldmatrix lane geometry ----
    // A (per m-tile mt): row = wm*64 + mt*16 + ((lane>>3)&1)*8 + (lane&7); khalf16 = (lane>>4)*16
    // tiles order: r0=rows0-7 k0-7, r1=rows8-15 k0-7, r2=rows0-7 k8-15, r3=rows8-15 k8-15 -> matches a-frag
    int a_row_loc = ((lane >> 3) & 1) * 8 + (lane & 7);
    int a_kh = (lane >> 4) * 16;
    // B (per j in 0..1 covering 16 n): nrow = wn*32 + j*16 + (lane>>4)*8 + (lane&7); khalf16 = ((lane>>3)&1)*16
    int b_row_loc = (lane >> 4) * 8 + (lane & 7);
    int b_kh = ((lane >> 3) & 1) * 16;

    float acc[4][4][4];
#pragma unroll
    for (int i = 0; i < 4; i++)
#pragma unroll
        for (int j = 0; j < 4; j++)
#pragma unroll
            for (int k = 0; k < 4; k++) acc[i][j][k] = 0.f;

#pragma unroll
    for (int s = 0; s < STAGES; s++) {
        if (s < nk) load_tile(s);
        CP_COMMIT();
    }

    // precomputed row bases (row*128), swizzle phase = row&7
    uint32_t a_base[4], b_base[2];
    int a_ph[4], b_ph[2];
#pragma unroll
    for (int mt = 0; mt < 4; mt++) {
        int row = wm * 64 + mt * 16 + a_row_loc;
        a_base[mt] = (uint32_t)(row * 128);
        a_ph[mt] = (row & 7) << 4;
    }
#pragma unroll
    for (int j = 0; j < 2; j++) {
        int row = wn * 32 + j * 16 + b_row_loc;
        b_base[j] = (uint32_t)(row * 128);
        b_ph[j] = (row & 7) << 4;
    }

    for (int kt = 0; kt < nk; kt++) {
        CP_WAIT(2);
        __syncthreads();
        uint32_t st = sbase + (uint32_t)(kt % STAGES) * STAGE_B;
        uint32_t stA = st, stAl = st + TILE_B, stB = st + 2*TILE_B, stBl = st + 3*TILE_B;
#pragma unroll
        for (int ks = 0; ks < 4; ks++) {
            uint32_t ah[4][4], al[4][4], bh[2][4], bl[2][4];
#pragma unroll
            for (int j = 0; j < 2; j++) {
                uint32_t off = b_base[j] + (uint32_t)((ks * 32 + b_kh) ^ b_ph[j]);
                ldsm4(bh[j], stB + off);
                ldsm4(bl[j], stBl + off);
            }
#pragma unroll
            for (int mt = 0; mt < 4; mt++) {
                uint32_t off = a_base[mt] + (uint32_t)((ks * 32 + a_kh) ^ a_ph[mt]);
                ldsm4(ah[mt], stA + off);
                ldsm4(al[mt], stAl + off);
            }
#pragma unroll
            for (int mt = 0; mt < 4; mt++)
#pragma unroll
                for (int nt = 0; nt < 4; nt++) {
                    const uint32_t* bph = &bh[nt >> 1][(nt & 1) * 2];
                    const uint32_t* bpl = &bl[nt >> 1][(nt & 1) * 2];
                    mma16816(acc[mt][nt], ah[mt], bph);
                    mma16816(acc[mt][nt], ah[mt], bpl);
                    mma16816(acc[mt][nt], al[mt], bph);
                }
        }
        __syncthreads();
        if (kt + STAGES < nk) load_tile(kt + STAGES);
        CP_COMMIT();
    }
    CP_WAIT(0);
    __syncthreads();

    // ---- epilogue: stage accumulators to fp32 smem, then coalesced global ----
    float* stg = (float*)smem;
    int cr = lane >> 2, ccol = (lane & 3) * 2;
#pragma unroll
    for (int mt = 0; mt < 4; mt++)
#pragma unroll
        for (int nt = 0; nt < 4; nt++) {
            int r = wm * 64 + mt * 16 + cr;
            int cl = wn * 32 + nt * 8 + ccol;
            *(float2*)&stg[r * LDS_ + cl]       = make_float2(acc[mt][nt][0], acc[mt][nt][1]);
            *(float2*)&stg[(r + 8) * LDS_ + cl] = make_float2(acc[mt][nt][2], acc[mt][nt][3]);
        }
    __syncthreads();

#pragma unroll
    for (int i = 0; i < 64; i++) {
        int id = tid + 256 * i;
        int r = id >> 7, cc = id & 127;
        int m = m0 + r;
        if (m < M) {
            int n = n0 + cc;
            float v = stg[r * LDS_ + cc] + bias[n];
            size_t idx = (size_t)m * N + n;
            if (mode == 0) {
                C[idx] = v;
            } else if (mode == 1) {
                float gv = gelu_new(v);
                __nv_bfloat16 hi = __float2bfloat16(gv);
                Chi[idx] = hi;
                Clo[idx] = __float2bfloat16(gv - __bfloat162float(hi));
            } else {
                C[idx] += v;
            }
        }
    }
}

// ---------------- attention ----------------
#define KTP 304
#define ATTN_SMEM_FLOATS (HD_*KTP + LSEQ*HD_ + 8*KTP + 8*HD_)

__global__ void __launch_bounds__(256)
attn_kernel(const float* __restrict__ qkv,
            __nv_bfloat16* __restrict__ ohi, __nv_bfloat16* __restrict__ olo)
{
    extern __shared__ float sm[];
    float* KT = sm;
    float* V  = KT + HD_ * KTP;
    float* SC = V + LSEQ * HD_;
    float* QV = SC + 8 * KTP;

    int bh = blockIdx.x;
    int b = bh >> 4, hd = bh & 15;
    const float* base = qkv + (size_t)b * LSEQ * (3 * D_);
    int hoff = hd * HD_;

    for (int idx = threadIdx.x; idx < LSEQ * HD_; idx += 256) {
        int j = idx >> 6, d = idx & 63;
        KT[d * KTP + j] = base[(size_t)j * (3 * D_) + D_     + hoff + d];
        V [j * HD_ + d] = base[(size_t)j * (3 * D_) + 2 * D_ + hoff + d];
    }
    __syncthreads();

    int w = threadIdx.x >> 5, lane = threadIdx.x & 31;
    float* sc = SC + w * KTP;
    float* qv = QV + w * HD_;

    for (int q = w; q < LSEQ; q += 8) {
        qv[lane]      = base[(size_t)q * (3 * D_) + hoff + lane];
        qv[lane + 32] = base[(size_t)q * (3 * D_) + hoff + 32 + lane];
        __syncwarp();
        float qr[HD_];
#pragma unroll
        for (int d = 0; d < HD_; d++) qr[d] = qv[d];

        int nk = q + 1;
        float mx = -1e30f;
        for (int j = lane; j < nk; j += 32) {
            float s = 0.f;
#pragma unroll
            for (int d = 0; d < HD_; d++) s = fmaf(qr[d], KT[d * KTP + j], s);
            s *= 0.125f;
            sc[j] = s;
            mx = fmaxf(mx, s);
        }
#pragma unroll
        for (int o = 16; o; o >>= 1) mx = fmaxf(mx, __shfl_xor_sync(0xFFFFFFFFu, mx, o));
        float sum = 0.f;
        for (int j = lane; j < nk; j += 32) {
            float e = expf(sc[j] - mx);
            sc[j] = e;
            sum += e;
        }
#pragma unroll
        for (int o = 16; o; o >>= 1) sum += __shfl_xor_sync(0xFFFFFFFFu, sum, o);
        float inv = 1.f / sum;
        __syncwarp();

        float a0=0.f,a1=0.f,a2=0.f,a3=0.f, b0=0.f,b1=0.f,b2=0.f,b3=0.f;
        int j = 0;
        for (; j + 4 <= nk; j += 4) {
            float p0 = sc[j], p1 = sc[j+1], p2 = sc[j+2], p3 = sc[j+3];
            a0 = fmaf(p0, V[(j  ) * HD_ + lane], a0);
            b0 = fmaf(p0, V[(j  ) * HD_ + 32 + lane], b0);
            a1 = fmaf(p1, V[(j+1) * HD_ + lane], a1);
            b1 = fmaf(p1, V[(j+1) * HD_ + 32 + lane], b1);
            a2 = fmaf(p2, V[(j+2) * HD_ + lane], a2);
            b2 = fmaf(p2, V[(j+2) * HD_ + 32 + lane], b2);
            a3 = fmaf(p3, V[(j+3) * HD_ + lane], a3);
            b3 = fmaf(p3, V[(j+3) * HD_ + 32 + lane], b3);
        }
        for (; j < nk; j++) {
            float p = sc[j];
            a0 = fmaf(p, V[j * HD_ + lane], a0);
            b0 = fmaf(p, V[j * HD_ + 32 + lane], b0);
        }
        float o0 = ((a0 + a1) + (a2 + a3)) * inv;
        float o1 = ((b0 + b1) + (b2 + b3)) * inv;

        size_t orow = (size_t)(b * LSEQ + q) * D_ + hoff;
        __nv_bfloat16 h0 = __float2bfloat16(o0);
        __nv_bfloat16 h1 = __float2bfloat16(o1);
        ohi[orow + lane]      = h0;
        olo[orow + lane]      = __float2bfloat16(o0 - __bfloat162float(h0));
        ohi[orow + 32 + lane] = h1;
        olo[orow + 32 + lane] = __float2bfloat16(o1 - __bfloat162float(h1));
        __syncwarp();
    }
}

// ---------------- loss ----------------
__global__ void loss_kernel(const float* __restrict__ h,
                            const float* __restrict__ g,
                            const float* __restrict__ beta,
                            const float* __restrict__ pw,
                            const float* __restrict__ pb,
                            const int* __restrict__ actions,
                            const int* __restrict__ tact,
                            float* __restrict__ partial)
{
    __shared__ float red[4];
    __shared__ float lred[5][4];
    int idx = blockIdx.x;
    int b = idx / (CTX_ + 1), t = idx % (CTX_ + 1);
    const float* x = h + (size_t)(b * LSEQ + 3 * t) * D_;
    int tid = threadIdx.x, lane = tid & 31, w = tid >> 5;

    float v[8];
    float s = 0.f;
#pragma unroll
    for (int i = 0; i < 8; i++) { v[i] = x[tid + 128 * i]; s += v[i]; }
#pragma unroll
    for (int o = 16; o; o >>= 1) s += __shfl_xor_sync(0xFFFFFFFFu, s, o);
    if (lane == 0) red[w] = s;
    __syncthreads();
    float mean = (red[0] + red[1] + red[2] + red[3]) * (1.f / 1024.f);
    __syncthreads();
    float s2 = 0.f;
#pragma unroll
    for (int i = 0; i < 8; i++) { float d = v[i] - mean; s2 += d * d; }
#pragma unroll
    for (int o = 16; o; o >>= 1) s2 += __shfl_xor_sync(0xFFFFFFFFu, s2, o);
    if (lane == 0) red[w] = s2;
    __syncthreads();
    float var = (red[0] + red[1] + red[2] + red[3]) * (1.f / 1024.f);
    float inv = 1.f / sqrtf(var + 1e-5f);

    float acc[NA_] = {0.f, 0.f, 0.f, 0.f, 0.f};
#pragma unroll
    for (int i = 0; i < 8; i++) {
        int c = tid + 128 * i;
        float xn = (v[i] - mean) * inv * g[c] + beta[c];
#pragma unroll
        for (int a = 0; a < NA_; a++)
            acc[a] = fmaf(xn, pw[c * NA_ + a], acc[a]);
    }
#pragma unroll
    for (int a = 0; a < NA_; a++) {
        float tv = acc[a];
#pragma unroll
        for (int o = 16; o; o >>= 1) tv += __shfl_xor_sync(0xFFFFFFFFu, tv, o);
        if (lane == 0) lred[a][w] = tv;
    }
    __syncthreads();
    if (tid == 0) {
        float logit[NA_];
#pragma unroll
        for (int a = 0; a < NA_; a++)
            logit[a] = lred[a][0] + lred[a][1] + lred[a][2] + lred[a][3] + pb[a];
        int target = (t < CTX_) ? actions[b * CTX_ + t] : tact[b];
        float mx = logit[0]; int am = 0;
#pragma unroll
        for (int a = 1; a < NA_; a++) if (logit[a] > mx) { mx = logit[a]; am = a; }
        float se = 0.f;
#pragma unroll
        for (int a = 0; a < NA_; a++) se += expf(logit[a] - mx);
        float lse = mx + logf(se);
        float sl = 0.f;
#pragma unroll
        for (int a = 0; a < NA_; a++) sl += (logit[a] - lse);
        float nll = -(logit[target] - lse);
        float smooth = -sl * (1.f / NA_);
        partial[2 * idx]     = 0.9f * nll + 0.1f * smooth;
        partial[2 * idx + 1] = (am == target) ? 1.f : 0.f;
    }
}

__global__ void reduce_kernel(const float* __restrict__ partial, float* __restrict__ out)
{
    __shared__ float rl[8], ra[8];
    int tid = threadIdx.x, lane = tid & 31, w = tid >> 5;
    float l = 0.f, a = 0.f;
    for (int i = tid; i < NPOS; i += 256) {
        l += partial[2 * i];
        a += partial[2 * i + 1];
    }
#pragma unroll
    for (int o = 16; o; o >>= 1) {
        l += __shfl_xor_sync(0xFFFFFFFFu, l, o);
        a += __shfl_xor_sync(0xFFFFFFFFu, a, o);
    }
    if (lane == 0) { rl[w] = l; ra[w] = a; }
    __syncthreads();
    if (tid == 0) {
        float L = 0.f, A = 0.f;
#pragma unroll
        for (int i = 0; i < 8; i++) { L += rl[i]; A += ra[i]; }
        out[0] = L * (1.f / NPOS);
        out[1] = A * (1.f / NPOS);
    }
}

// ---------------- host ----------------
static inline void launch_gemm(const __nv_bfloat16* Ahi, const __nv_bfloat16* Alo,
                               const __nv_bfloat16* Bhi, const __nv_bfloat16* Blo,
                               const float* bias, float* C,
                               __nv_bfloat16* Chi, __nv_bfloat16* Clo,
                               int M, int N, int K, int mode)
{
    dim3 grid(N / BN, (M + BM - 1) / BM);
    gemm_mma<<<grid, 256, GEMM_SMEM>>>(Ahi, Alo, Bhi, Blo, bias, C, Chi, Clo, M, N, K, mode);
}

extern "C" void kernel_launch(void* const* d_in, const int* in_sizes, int n_in,
                              void* d_out, int out_size)
{
    const int*   states  = (const int*)  d_in[0];
    const int*   actions = (const int*)  d_in[1];
    const float* rewards = (const float*)d_in[2];
    const int*   qstates = (const int*)  d_in[3];
    const int*   tact    = (const int*)  d_in[4];
    const float* wpe     = (const float*)d_in[5];
    const float* e_state = (const float*)d_in[6];
    const float* e_act   = (const float*)d_in[7];
    const float* erw     = (const float*)d_in[8];
    const float* erb     = (const float*)d_in[9];
    const float* ln1g    = (const float*)d_in[10];
    const float* ln1b    = (const float*)d_in[11];
    const float* attnw   = (const float*)d_in[12];
    const float* attnb   = (const float*)d_in[13];
    const float* apw     = (const float*)d_in[14];
    const float* apb     = (const float*)d_in[15];
    const float* ln2g    = (const float*)d_in[16];
    const float* ln2b    = (const float*)d_in[17];
    const float* fcw     = (const float*)d_in[18];
    const float* fcb     = (const float*)d_in[19];
    const float* mpw     = (const float*)d_in[20];
    const float* mpb     = (const float*)d_in[21];
    const float* lnfg    = (const float*)d_in[22];
    const float* lnfb    = (const float*)d_in[23];
    const float* predw   = (const float*)d_in[24];
    const float* predb   = (const float*)d_in[25];
    float* out = (float*)d_out;

    float *h, *qkv, *partial;
    __nv_bfloat16 *xhi, *xlo, *ahi, *alo, *fhi, *flo, *whi, *wlo;
    cudaGetSymbolAddress((void**)&h,    g_h);
    cudaGetSymbolAddress((void**)&qkv,  g_qkv);
    cudaGetSymbolAddress((void**)&partial, g_partial);
    cudaGetSymbolAddress((void**)&xhi,  g_xhi);
    cudaGetSymbolAddress((void**)&xlo,  g_xlo);
    cudaGetSymbolAddress((void**)&ahi,  g_ahi);
    cudaGetSymbolAddress((void**)&alo,  g_alo);
    cudaGetSymbolAddress((void**)&fhi,  g_fhi);
    cudaGetSymbolAddress((void**)&flo,  g_flo);
    cudaGetSymbolAddress((void**)&whi,  g_whi);
    cudaGetSymbolAddress((void**)&wlo,  g_wlo);

    const int attn_smem = ATTN_SMEM_FLOATS * (int)sizeof(float);
    cudaFuncSetAttribute(attn_kernel, cudaFuncAttributeMaxDynamicSharedMemorySize, attn_smem);
    cudaFuncSetAttribute(gemm_mma, cudaFuncAttributeMaxDynamicSharedMemorySize, GEMM_SMEM);

    const size_t WPL = 12582912;
    const size_t OFF_QKV = 0, OFF_PROJ = 3145728, OFF_FC = 4194304, OFF_MP = 8388608;
    for (int i = 0; i < NL_; i++) {
        size_t off = (size_t)i * WPL;
        wprep_kernel<<<dim3(3 * D_ / 32, D_ / 32), dim3(32, 8)>>>(
            attnw + (size_t)i * D_ * 3 * D_, whi + off + OFF_QKV, wlo + off + OFF_QKV, D_, 3 * D_);
        wprep_kernel<<<dim3(D_ / 32, D_ / 32), dim3(32, 8)>>>(
            apw + (size_t)i * D_ * D_, whi + off + OFF_PROJ, wlo + off + OFF_PROJ, D_, D_);
        wprep_kernel<<<dim3(DFF_ / 32, D_ / 32), dim3(32, 8)>>>(
            fcw + (size_t)i * D_ * DFF_, whi + off + OFF_FC, wlo + off + OFF_FC, D_, DFF_);
        wprep_kernel<<<dim3(D_ / 32, DFF_ / 32), dim3(32, 8)>>>(
            mpw + (size_t)i * DFF_ * D_, whi + off + OFF_MP, wlo + off + OFF_MP, DFF_, D_);
    }

    embed_kernel<<<NTOK, 256>>>(states, actions, rewards, qstates, wpe,
                                e_state, e_act, erw, erb, h);

    for (int i = 0; i < NL_; i++) {
        size_t off = (size_t)i * WPL;
        ln_kernel<<<NTOK, 256>>>(h, xhi, xlo, ln1g + i * D_, ln1b + i * D_);
        launch_gemm(xhi, xlo, whi + off + OFF_QKV, wlo + off + OFF_QKV,
                    attnb + i * 3 * D_, qkv, nullptr, nullptr, NTOK, 3 * D_, D_, 0);
        attn_kernel<<<B_ * H_, 256, attn_smem>>>(qkv, ahi, alo);
        launch_gemm(ahi, alo, whi + off + OFF_PROJ, wlo + off + OFF_PROJ,
                    apb + i * D_, h, nullptr, nullptr, NTOK, D_, D_, 2);
        ln_kernel<<<NTOK, 256>>>(h, xhi, xlo, ln2g + i * D_, ln2b + i * D_);
        launch_gemm(xhi, xlo, whi + off + OFF_FC, wlo + off + OFF_FC,
                    fcb + i * DFF_, nullptr, fhi, flo, NTOK, DFF_, D_, 1);
        launch_gemm(fhi, flo, whi + off + OFF_MP, wlo + off + OFF_MP,
                    mpb + i * D_, h, nullptr, nullptr, NTOK, D_, DFF_, 2);
    }

    loss_kernel<<<NPOS, 128>>>(h, lnfg, lnfb, predw, predb, actions, tact, partial);
    reduce_kernel<<<1, 256>>>(partial, out);
}

// round 7
// speedup vs baseline: 3.2398x; 1.2805x over previous
#include <cuda_runtime.h>
#include <cuda_bf16.h>
#include <math.h>
#include <stdint.h>

#define B_    16
#define CTX_  100
#define LSEQ  301
#define D_    1024
#define H_    16
#define HD_   64
#define NL_   4
#define DFF_  4096
#define GRID_ 9
#define NA_   5
#define NTOK  (B_*LSEQ)
#define NPOS  (B_*(CTX_+1))
#define WPOOL 50331648

__device__ float g_h   [NTOK * D_];
__device__ float g_qkv [NTOK * 3 * D_];
__device__ __nv_bfloat16 g_xhi[NTOK * D_];
__device__ __nv_bfloat16 g_xlo[NTOK * D_];
__device__ __nv_bfloat16 g_ahi[NTOK * D_];
__device__ __nv_bfloat16 g_alo[NTOK * D_];
__device__ __nv_bfloat16 g_fhi[NTOK * DFF_];
__device__ __nv_bfloat16 g_flo[NTOK * DFF_];
__device__ __nv_bfloat16 g_whi[WPOOL];
__device__ __nv_bfloat16 g_wlo[WPOOL];
__device__ float g_partial[NPOS * 2];

#define CP16(d, s, z)  asm volatile("cp.async.cg.shared.global [%0], [%1], 16, %2;" :: "r"(d), "l"(s), "r"(z) : "memory")
#define CP_COMMIT()    asm volatile("cp.async.commit_group;" ::: "memory")
#define CP_WAIT(n)     asm volatile("cp.async.wait_group %0;" :: "n"(n) : "memory")
#define SWZ128(o) ((o) ^ (((o) >> 3) & 0x70))

__device__ __forceinline__ uint32_t smem_u32(const void* p) {
    uint32_t a;
    asm("{ .reg .u64 t; cvta.to.shared.u64 t, %1; cvt.u32.u64 %0, t; }" : "=r"(a) : "l"(p));
    return a;
}
__device__ __forceinline__ void ldsm4(uint32_t* r, uint32_t addr) {
    asm volatile("ldmatrix.sync.aligned.m8n8.x4.shared.b16 {%0,%1,%2,%3}, [%4];"
                 : "=r"(r[0]), "=r"(r[1]), "=r"(r[2]), "=r"(r[3]) : "r"(addr));
}
__device__ __forceinline__ void ldsm4t(uint32_t* r, uint32_t addr) {
    asm volatile("ldmatrix.sync.aligned.m8n8.x4.trans.shared.b16 {%0,%1,%2,%3}, [%4];"
                 : "=r"(r[0]), "=r"(r[1]), "=r"(r[2]), "=r"(r[3]) : "r"(addr));
}
__device__ __forceinline__ void mma16816(float* c, const uint32_t* a, const uint32_t* b) {
    asm volatile("mma.sync.aligned.m16n8k16.row.col.f32.bf16.bf16.f32 "
                 "{%0,%1,%2,%3}, {%4,%5,%6,%7}, {%8,%9}, {%0,%1,%2,%3};"
                 : "+f"(c[0]), "+f"(c[1]), "+f"(c[2]), "+f"(c[3])
                 : "r"(a[0]), "r"(a[1]), "r"(a[2]), "r"(a[3]), "r"(b[0]), "r"(b[1]));
}
__device__ __forceinline__ void pack_hilo(float x, float y, uint32_t& hi, uint32_t& lo) {
    __nv_bfloat16 xh = __float2bfloat16(x), yh = __float2bfloat16(y);
    __nv_bfloat162 hv; hv.x = xh; hv.y = yh;
    __nv_bfloat162 lv;
    lv.x = __float2bfloat16(x - __bfloat162float(xh));
    lv.y = __float2bfloat16(y - __bfloat162float(yh));
    hi = *(uint32_t*)&hv; lo = *(uint32_t*)&lv;
}

__device__ __forceinline__ float gelu_new(float xv) {
    float t = tanhf(0.7978845608028654f * (xv + 0.044715f * xv * xv * xv));
    return 0.5f * xv * (1.f + t);
}

// ---------------- embedding ----------------
__global__ void embed_kernel(const int* __restrict__ states,
                             const int* __restrict__ actions,
                             const float* __restrict__ rewards,
                             const int* __restrict__ qstates,
                             const float* __restrict__ wpe,
                             const float* __restrict__ e_state,
                             const float* __restrict__ e_act,
                             const float* __restrict__ erw,
                             const float* __restrict__ erb,
                             float* __restrict__ h)
{
    int tok = blockIdx.x;
    int b = tok / LSEQ, p = tok % LSEQ;
    const float* src = nullptr;
    float r = 0.f;
    int type = 0;
    if (p == 3 * CTX_) {
        int q = qstates[b * 2] * GRID_ + qstates[b * 2 + 1];
        src = e_state + (size_t)q * D_;
    } else {
        int t = p / 3, m = p % 3;
        if (m == 0) {
            int sid = states[(b * CTX_ + t) * 2] * GRID_ + states[(b * CTX_ + t) * 2 + 1];
            src = e_state + (size_t)sid * D_;
        } else if (m == 1) {
            src = e_act + (size_t)actions[b * CTX_ + t] * D_;
        } else {
            r = rewards[b * CTX_ + t];
            type = 1;
        }
    }
    for (int c = threadIdx.x; c < D_; c += blockDim.x) {
        float v = (type == 0) ? src[c] : fmaf(r, erw[c], erb[c]);
        h[(size_t)tok * D_ + c] = v + wpe[(size_t)p * D_ + c];
    }
}

// ---------------- weight transpose + split ----------------
__global__ void wprep_kernel(const float* __restrict__ W,
                             __nv_bfloat16* __restrict__ Thi,
                             __nv_bfloat16* __restrict__ Tlo,
                             int K, int N)
{
    __shared__ float t[32][33];
    int n = blockIdx.x * 32 + threadIdx.x;
    int k0 = blockIdx.y * 32;
#pragma unroll
    for (int r = 0; r < 32; r += 8)
        t[threadIdx.y + r][threadIdx.x] = W[(size_t)(k0 + threadIdx.y + r) * N + n];
    __syncthreads();
    int k = k0 + threadIdx.x;
#pragma unroll
    for (int r = 0; r < 32; r += 8) {
        int nn = blockIdx.x * 32 + threadIdx.y + r;
        float v = t[threadIdx.x][threadIdx.y + r];
        __nv_bfloat16 hi = __float2bfloat16(v);
        Thi[(size_t)nn * K + k] = hi;
        Tlo[(size_t)nn * K + k] = __float2bfloat16(v - __bfloat162float(hi));
    }
}

// ---------------- LayerNorm -> hi/lo ----------------
__global__ void ln_kernel(const float* __restrict__ in,
                          __nv_bfloat16* __restrict__ ohi,
                          __nv_bfloat16* __restrict__ olo,
                          const float* __restrict__ g, const float* __restrict__ beta)
{
    __shared__ float red[8];
    int row = blockIdx.x;
    const float* x = in + (size_t)row * D_;
    int tid = threadIdx.x;
    float v[4];
    float s = 0.f;
#pragma unroll
    for (int i = 0; i < 4; i++) { v[i] = x[tid + 256 * i]; s += v[i]; }
#pragma unroll
    for (int o = 16; o; o >>= 1) s += __shfl_xor_sync(0xFFFFFFFFu, s, o);
    if ((tid & 31) == 0) red[tid >> 5] = s;
    __syncthreads();
    float mean = (red[0]+red[1]+red[2]+red[3]+red[4]+red[5]+red[6]+red[7]) * (1.f/1024.f);
    __syncthreads();
    float s2 = 0.f;
#pragma unroll
    for (int i = 0; i < 4; i++) { float d = v[i] - mean; s2 += d * d; }
#pragma unroll
    for (int o = 16; o; o >>= 1) s2 += __shfl_xor_sync(0xFFFFFFFFu, s2, o);
    if ((tid & 31) == 0) red[tid >> 5] = s2;
    __syncthreads();
    float var = (red[0]+red[1]+red[2]+red[3]+red[4]+red[5]+red[6]+red[7]) * (1.f/1024.f);
    float inv = 1.f / sqrtf(var + 1e-5f);
#pragma unroll
    for (int i = 0; i < 4; i++) {
        int c = tid + 256 * i;
        float y = (v[i] - mean) * inv * g[c] + beta[c];
        __nv_bfloat16 hi = __float2bfloat16(y);
        ohi[(size_t)row * D_ + c] = hi;
        olo[(size_t)row * D_ + c] = __float2bfloat16(y - __bfloat162float(hi));
    }
}

// ---------------- mma.sync split-bf16 GEMM (unchanged from R6) ----------------
#define BM 128
#define BN 128
#define BK 64
#define TILE_B  (128 * 128)
#define STAGE_B (4 * TILE_B)
#define STAGES  3
#define GEMM_SMEM (STAGES * STAGE_B)
#define LDS_ 132

__global__ void __launch_bounds__(256, 1)
gemm_mma(const __nv_bfloat16* __restrict__ Ahi, const __nv_bfloat16* __restrict__ Alo,
         const __nv_bfloat16* __restrict__ Bhi, const __nv_bfloat16* __restrict__ Blo,
         const float* __restrict__ bias, float* __restrict__ C,
         __nv_bfloat16* __restrict__ Chi, __nv_bfloat16* __restrict__ Clo,
         int M, int N, int K, int mode)
{
    extern __shared__ __align__(128) char smem[];
    uint32_t sbase = smem_u32(smem);
    int tid = threadIdx.x, wid = tid >> 5, lane = tid & 31;
    int m0 = blockIdx.y * BM, n0 = blockIdx.x * BN;
    int wm = wid >> 2, wn = wid & 3;

    uint32_t so[4];
    unsigned ao[4], bo[4], szA[4];
#pragma unroll
    for (int i = 0; i < 4; i++) {
        int c = tid + 256 * i;
        int r = c >> 3, gb = c & 7;
        so[i] = (uint32_t)SWZ128(r * 128 + gb * 16);
        bool ok = (m0 + r) < M;
        ao[i] = ok ? ((unsigned)(m0 + r) * (unsigned)K + gb * 8) : 0u;
        bo[i] = (unsigned)(n0 + r) * (unsigned)K + gb * 8;
        szA[i] = ok ? 16u : 0u;
    }
    const int nk = K / BK;

    auto load_tile = [&](int kt) {
        uint32_t st = sbase + (uint32_t)(kt % STAGES) * STAGE_B;
        unsigned ko = (unsigned)kt * BK;
#pragma unroll
        for (int i = 0; i < 4; i++) {
            CP16(st + so[i],            Ahi + ao[i] + ko, szA[i]);
            CP16(st + TILE_B + so[i],   Alo + ao[i] + ko, szA[i]);
            CP16(st + 2*TILE_B + so[i], Bhi + bo[i] + ko, 16u);
            CP16(st + 3*TILE_B + so[i], Blo + bo[i] + ko, 16u);
        }
    };

    int a_row_loc = ((lane >> 3) & 1) * 8 + (lane & 7);
    int a_kh = (lane >> 4) * 16;
    int b_row_loc = (lane >> 4) * 8 + (lane & 7);
    int b_kh = ((lane >> 3) & 1) * 16;

    float acc[4][4][4];
#pragma unroll
    for (int i = 0; i < 4; i++)
#pragma unroll
        for (int j = 0; j < 4; j++)
#pragma unroll
            for (int k = 0; k < 4; k++) acc[i][j][k] = 0.f;

#pragma unroll
    for (int s = 0; s < STAGES; s++) {
        if (s < nk) load_tile(s);
        CP_COMMIT();
    }

    uint32_t a_base[4], b_base[2];
    int a_ph[4], b_ph[2];
#pragma unroll
    for (int mt = 0; mt < 4; mt++) {
        int row = wm * 64 + mt * 16 + a_row_loc;
        a_base[mt] = (uint32_t)(row * 128);
        a_ph[mt] = (row & 7) << 4;
    }
#pragma unroll
    for (int j = 0; j < 2; j++) {
        int row = wn * 32 + j * 16 + b_row_loc;
        b_base[j] = (uint32_t)(row * 128);
        b_ph[j] = (row & 7) << 4;
    }

    for (int kt = 0; kt < nk; kt++) {
        CP_WAIT(2);
        __syncthreads();
        uint32_t st = sbase + (uint32_t)(kt % STAGES) * STAGE_B;
        uint32_t stA = st, stAl = st + TILE_B, stB = st + 2*TILE_B, stBl = st + 3*TILE_B;
#pragma unroll
        for (int ks = 0; ks < 4; ks++) {
            uint32_t ah[4][4], al[4][4], bh[2][4], bl[2][4];
#pragma unroll
            for (int j = 0; j < 2; j++) {
                uint32_t off = b_base[j] + (uint32_t)((ks * 32 + b_kh) ^ b_ph[j]);
                ldsm4(bh[j], stB + off);
                ldsm4(bl[j], stBl + off);
            }
#pragma unroll
            for (int mt = 0; mt < 4; mt++) {
                uint32_t off = a_base[mt] + (uint32_t)((ks * 32 + a_kh) ^ a_ph[mt]);
                ldsm4(ah[mt], stA + off);
                ldsm4(al[mt], stAl + off);
            }
#pragma unroll
            for (int mt = 0; mt < 4; mt++)
#pragma unroll
                for (int nt = 0; nt < 4; nt++) {
                    const uint32_t* bph = &bh[nt >> 1][(nt & 1) * 2];
                    const uint32_t* bpl = &bl[nt >> 1][(nt & 1) * 2];
                    mma16816(acc[mt][nt], ah[mt], bph);
                    mma16816(acc[mt][nt], ah[mt], bpl);
                    mma16816(acc[mt][nt], al[mt], bph);
                }
        }
        __syncthreads();
        if (kt + STAGES < nk) load_tile(kt + STAGES);
        CP_COMMIT();
    }
    CP_WAIT(0);
    __syncthreads();

    float* stg = (float*)smem;
    int cr = lane >> 2, ccol = (lane & 3) * 2;
#pragma unroll
    for (int mt = 0; mt < 4; mt++)
#pragma unroll
        for (int nt = 0; nt < 4; nt++) {
            int r = wm * 64 + mt * 16 + cr;
            int cl = wn * 32 + nt * 8 + ccol;
            *(float2*)&stg[r * LDS_ + cl]       = make_float2(acc[mt][nt][0], acc[mt][nt][1]);
            *(float2*)&stg[(r + 8) * LDS_ + cl] = make_float2(acc[mt][nt][2], acc[mt][nt][3]);
        }
    __syncthreads();

#pragma unroll
    for (int i = 0; i < 64; i++) {
        int id = tid + 256 * i;
        int r = id >> 7, cc = id & 127;
        int m = m0 + r;
        if (m < M) {
            int n = n0 + cc;
            float v = stg[r * LDS_ + cc] + bias[n];
            size_t idx = (size_t)m * N + n;
            if (mode == 0) {
                C[idx] = v;
            } else if (mode == 1) {
                float gv = gelu_new(v);
                __nv_bfloat16 hi = __float2bfloat16(gv);
                Chi[idx] = hi;
                Clo[idx] = __float2bfloat16(gv - __bfloat162float(hi));
            } else {
                C[idx] += v;
            }
        }
    }
}

// ---------------- flash attention (split-bf16 mma) ----------------
// smem: Khi, Klo, Vhi, Vlo each [304 rows][128B] swizzled = 4*38912 = 155648
#define AKHI 0
#define AKLO 38912
#define AVHI 77824
#define AVLO 116736
#define ATTN_SMEM 155648

__global__ void __launch_bounds__(256)
attn_flash(const float* __restrict__ qkv,
           __nv_bfloat16* __restrict__ ohi, __nv_bfloat16* __restrict__ olo)
{
    extern __shared__ __align__(128) char asmem[];
    uint32_t sb = smem_u32(asmem);
    int tid = threadIdx.x;
    int bh = blockIdx.x, b = bh >> 4, hd = bh & 15;
    const float* base = qkv + (size_t)b * LSEQ * 3072;
    int hoff = hd * 64;

    // fill K/V hi/lo, swizzled (coalesced gmem reads, d-fast)
    for (int idx = tid; idx < 304 * 64; idx += 256) {
        int j = idx >> 6, d = idx & 63;
        float kv = 0.f, vv = 0.f;
        if (j < LSEQ) {
            kv = base[(size_t)j * 3072 + 1024 + hoff + d];
            vv = base[(size_t)j * 3072 + 2048 + hoff + d];
        }
        uint32_t off = (uint32_t)SWZ128(j * 128 + d * 2);
        __nv_bfloat16 kh = __float2bfloat16(kv);
        *(__nv_bfloat16*)(asmem + AKHI + off) = kh;
        *(__nv_bfloat16*)(asmem + AKLO + off) = __float2bfloat16(kv - __bfloat162float(kh));
        __nv_bfloat16 vh = __float2bfloat16(vv);
        *(__nv_bfloat16*)(asmem + AVHI + off) = vh;
        *(__nv_bfloat16*)(asmem + AVLO + off) = __float2bfloat16(vv - __bfloat162float(vh));
    }
    __syncthreads();

    int w = tid >> 5, lane = tid & 31;
    int g = lane >> 2, t4 = lane & 3;
    // K (non-trans) b-lane geometry: rows = n(j)
    int kb_row = (lane >> 4) * 8 + (lane & 7);
    int kb_kb  = ((lane >> 3) & 1) * 16;
    // V (trans) b-lane geometry: rows = k(j), col-offset = n(d)
    int vb_row = ((lane >> 3) & 1) * 8 + (lane & 7);
    int vb_nb  = (lane >> 4) * 16;

    // LPT q-tile map: col0=18-w, col1=3+w, col2=2-w (w<3)
    for (int qi = 0; qi < 3; qi++) {
        int qt = (qi == 0) ? (18 - w) : ((qi == 1) ? (3 + w) : ((w < 3) ? (2 - w) : -1));
        if (qt < 0) continue;
        int q0 = qt * 16;

        // Q fragments (direct from gmem)
        uint32_t qh[4][4], ql[4][4];
        int r1 = q0 + g;       int r1c = r1 < LSEQ ? r1 : LSEQ - 1;
        int r2 = r1 + 8;       int r2c = r2 < LSEQ ? r2 : LSEQ - 1;
        const float* q1p = base + (size_t)r1c * 3072 + hoff;
        const float* q2p = base + (size_t)r2c * 3072 + hoff;
#pragma unroll
        for (int kt = 0; kt < 4; kt++) {
            int c0 = kt * 16 + 2 * t4;
            float2 x0 = *(const float2*)(q1p + c0);
            float2 x1 = *(const float2*)(q2p + c0);
            float2 x2 = *(const float2*)(q1p + c0 + 8);
            float2 x3 = *(const float2*)(q2p + c0 + 8);
            pack_hilo(x0.x, x0.y, qh[kt][0], ql[kt][0]);
            pack_hilo(x1.x, x1.y, qh[kt][1], ql[kt][1]);
            pack_hilo(x2.x, x2.y, qh[kt][2], ql[kt][2]);
            pack_hilo(x3.x, x3.y, qh[kt][3], ql[kt][3]);
        }

        float m0 = -1e30f, m1 = -1e30f, l0 = 0.f, l1 = 0.f;
        float o[8][4];
#pragma unroll
        for (int i = 0; i < 8; i++)
#pragma unroll
            for (int k = 0; k < 4; k++) o[i][k] = 0.f;

        for (int jt = 0; jt <= qt; jt++) {
            // ---- S = Q K^T ----
            float s[2][4] = {{0,0,0,0},{0,0,0,0}};
#pragma unroll
            for (int kt = 0; kt < 4; kt++) {
                int row = jt * 16 + kb_row;
                uint32_t off = (uint32_t)(row * 128 + ((kt * 32 + kb_kb) ^ ((row & 7) << 4)));
                uint32_t kh4[4], kl4[4];
                ldsm4(kh4, sb + AKHI + off);
                ldsm4(kl4, sb + AKLO + off);
#pragma unroll
                for (int nt = 0; nt < 2; nt++) {
                    mma16816(s[nt], qh[kt], &kh4[nt*2]);
                    mma16816(s[nt], qh[kt], &kl4[nt*2]);
                    mma16816(s[nt], ql[kt], &kh4[nt*2]);
                }
            }
            // mask + scale
            int qr1 = q0 + g, qr2 = qr1 + 8;
#pragma unroll
            for (int nt = 0; nt < 2; nt++) {
                int jc = jt * 16 + nt * 8 + 2 * t4;
                s[nt][0] = (jc     <= qr1) ? s[nt][0] * 0.125f : -1e30f;
                s[nt][1] = (jc + 1 <= qr1) ? s[nt][1] * 0.125f : -1e30f;
                s[nt][2] = (jc     <= qr2) ? s[nt][2] * 0.125f : -1e30f;
                s[nt][3] = (jc + 1 <= qr2) ? s[nt][3] * 0.125f : -1e30f;
            }
            // online softmax
            float tm0 = fmaxf(fmaxf(s[0][0], s[0][1]), fmaxf(s[1][0], s[1][1]));
            float tm1 = fmaxf(fmaxf(s[0][2], s[0][3]), fmaxf(s[1][2], s[1][3]));
            tm0 = fmaxf(tm0, __shfl_xor_sync(0xFFFFFFFFu, tm0, 1));
            tm0 = fmaxf(tm0, __shfl_xor_sync(0xFFFFFFFFu, tm0, 2));
            tm1 = fmaxf(tm1, __shfl_xor_sync(0xFFFFFFFFu, tm1, 1));
            tm1 = fmaxf(tm1, __shfl_xor_sync(0xFFFFFFFFu, tm1, 2));
            float mn0 = fmaxf(m0, tm0), mn1 = fmaxf(m1, tm1);
            float sc0 = expf(m0 - mn0), sc1 = expf(m1 - mn1);
            m0 = mn0; m1 = mn1;
            float p[2][4];
#pragma unroll
            for (int nt = 0; nt < 2; nt++) {
                p[nt][0] = expf(s[nt][0] - mn0);
                p[nt][1] = expf(s[nt][1] - mn0);
                p[nt][2] = expf(s[nt][2] - mn1);
                p[nt][3] = expf(s[nt][3] - mn1);
            }
            float ts0 = p[0][0] + p[0][1] + p[1][0] + p[1][1];
            float ts1 = p[0][2] + p[0][3] + p[1][2] + p[1][3];
            ts0 += __shfl_xor_sync(0xFFFFFFFFu, ts0, 1);
            ts0 += __shfl_xor_sync(0xFFFFFFFFu, ts0, 2);
            ts1 += __shfl_xor_sync(0xFFFFFFFFu, ts1, 1);
            ts1 += __shfl_xor_sync(0xFFFFFFFFu, ts1, 2);
            l0 = l0 * sc0 + ts0;
            l1 = l1 * sc1 + ts1;
#pragma unroll
            for (int nt = 0; nt < 8; nt++) {
                o[nt][0] *= sc0; o[nt][1] *= sc0; o[nt][2] *= sc1; o[nt][3] *= sc1;
            }
            // P a-frags: a0=row g cols(2t,2t+1); a1=row g+8 same; a2=row g cols+8; a3=row g+8 cols+8
            uint32_t pah[4], pal[4];
            pack_hilo(p[0][0], p[0][1], pah[0], pal[0]);
            pack_hilo(p[0][2], p[0][3], pah[1], pal[1]);
            pack_hilo(p[1][0], p[1][1], pah[2], pal[2]);
            pack_hilo(p[1][2], p[1][3], pah[3], pal[3]);
            // ---- O += P V ---- (V via ldmatrix.trans from [j][d] rows)
#pragma unroll
            for (int dt = 0; dt < 4; dt++) {
                int row = jt * 16 + vb_row;
                uint32_t off = (uint32_t)(row * 128 + ((dt * 32 + vb_nb) ^ ((row & 7) << 4)));
                uint32_t vh4[4], vl4[4];
                ldsm4t(vh4, sb + AVHI + off);
                ldsm4t(vl4, sb + AVLO + off);
#pragma unroll
                for (int su = 0; su < 2; su++) {
                    int nt = dt * 2 + su;
                    mma16816(o[nt], pah, &vh4[su*2]);
                    mma16816(o[nt], pah, &vl4[su*2]);
                    mma16816(o[nt], pal, &vh4[su*2]);
                }
            }
        }
        // finalize + store hi/lo
        float inv0 = 1.f / l0, inv1 = 1.f / l1;
        int row1 = q0 + g, row2 = row1 + 8;
#pragma unroll
        for (int nt = 0; nt < 8; nt++) {
            int col = nt * 8 + 2 * t4;
            if (row1 < LSEQ) {
                uint32_t hp, lp;
                pack_hilo(o[nt][0] * inv0, o[nt][1] * inv0, hp, lp);
                size_t idx = (size_t)(b * LSEQ + row1) * D_ + hoff + col;
                *(uint32_t*)&ohi[idx] = hp;
                *(uint32_t*)&olo[idx] = lp;
            }
            if (row2 < LSEQ) {
                uint32_t hp, lp;
                pack_hilo(o[nt][2] * inv1, o[nt][3] * inv1, hp, lp);
                size_t idx = (size_t)(b * LSEQ + row2) * D_ + hoff + col;
                *(uint32_t*)&ohi[idx] = hp;
                *(uint32_t*)&olo[idx] = lp;
            }
        }
    }
}

// ---------------- loss ----------------
__global__ void loss_kernel(const float* __restrict__ h,
                            const float* __restrict__ g,
                            const float* __restrict__ beta,
                            const float* __restrict__ pw,
                            const float* __restrict__ pb,
                            const int* __restrict__ actions,
                            const int* __restrict__ tact,
                            float* __restrict__ partial)
{
    __shared__ float red[4];
    __shared__ float lred[5][4];
    int idx = blockIdx.x;
    int b = idx / (CTX_ + 1), t = idx % (CTX_ + 1);
    const float* x = h + (size_t)(b * LSEQ + 3 * t) * D_;
    int tid = threadIdx.x, lane = tid & 31, w = tid >> 5;

    float v[8];
    float s = 0.f;
#pragma unroll
    for (int i = 0; i < 8; i++) { v[i] = x[tid + 128 * i]; s += v[i]; }
#pragma unroll
    for (int o = 16; o; o >>= 1) s += __shfl_xor_sync(0xFFFFFFFFu, s, o);
    if (lane == 0) red[w] = s;
    __syncthreads();
    float mean = (red[0] + red[1] + red[2] + red[3]) * (1.f / 1024.f);
    __syncthreads();
    float s2 = 0.f;
#pragma unroll
    for (int i = 0; i < 8; i++) { float d = v[i] - mean; s2 += d * d; }
#pragma unroll
    for (int o = 16; o; o >>= 1) s2 += __shfl_xor_sync(0xFFFFFFFFu, s2, o);
    if (lane == 0) red[w] = s2;
    __syncthreads();
    float var = (red[0] + red[1] + red[2] + red[3]) * (1.f / 1024.f);
    float inv = 1.f / sqrtf(var + 1e-5f);

    float acc[NA_] = {0.f, 0.f, 0.f, 0.f, 0.f};
#pragma unroll
    for (int i = 0; i < 8; i++) {
        int c = tid + 128 * i;
        float xn = (v[i] - mean) * inv * g[c] + beta[c];
#pragma unroll
        for (int a = 0; a < NA_; a++)
            acc[a] = fmaf(xn, pw[c * NA_ + a], acc[a]);
    }
#pragma unroll
    for (int a = 0; a < NA_; a++) {
        float tv = acc[a];
#pragma unroll
        for (int o = 16; o; o >>= 1) tv += __shfl_xor_sync(0xFFFFFFFFu, tv, o);
        if (lane == 0) lred[a][w] = tv;
    }
    __syncthreads();
    if (tid == 0) {
        float logit[NA_];
#pragma unroll
        for (int a = 0; a < NA_; a++)
            logit[a] = lred[a][0] + lred[a][1] + lred[a][2] + lred[a][3] + pb[a];
        int target = (t < CTX_) ? actions[b * CTX_ + t] : tact[b];
        float mx = logit[0]; int am = 0;
#pragma unroll
        for (int a = 1; a < NA_; a++) if (logit[a] > mx) { mx = logit[a]; am = a; }
        float se = 0.f;
#pragma unroll
        for (int a = 0; a < NA_; a++) se += expf(logit[a] - mx);
        float lse = mx + logf(se);
        float sl = 0.f;
#pragma unroll
        for (int a = 0; a < NA_; a++) sl += (logit[a] - lse);
        float nll = -(logit[target] - lse);
        float smooth = -sl * (1.f / NA_);
        partial[2 * idx]     = 0.9f * nll + 0.1f * smooth;
        partial[2 * idx + 1] = (am == target) ? 1.f : 0.f;
    }
}

__global__ void reduce_kernel(const float* __restrict__ partial, float* __restrict__ out)
{
    __shared__ float rl[8], ra[8];
    int tid = threadIdx.x, lane = tid & 31, w = tid >> 5;
    float l = 0.f, a = 0.f;
    for (int i = tid; i < NPOS; i += 256) {
        l += partial[2 * i];
        a += partial[2 * i + 1];
    }
#pragma unroll
    for (int o = 16; o; o >>= 1) {
        l += __shfl_xor_sync(0xFFFFFFFFu, l, o);
        a += __shfl_xor_sync(0xFFFFFFFFu, a, o);
    }
    if (lane == 0) { rl[w] = l; ra[w] = a; }
    __syncthreads();
    if (tid == 0) {
        float L = 0.f, A = 0.f;
#pragma unroll
        for (int i = 0; i < 8; i++) { L += rl[i]; A += ra[i]; }
        out[0] = L * (1.f / NPOS);
        out[1] = A * (1.f / NPOS);
    }
}

// ---------------- host ----------------
static inline void launch_gemm(const __nv_bfloat16* Ahi, const __nv_bfloat16* Alo,
                               const __nv_bfloat16* Bhi, const __nv_bfloat16* Blo,
                               const float* bias, float* C,
                               __nv_bfloat16* Chi, __nv_bfloat16* Clo,
                               int M, int N, int K, int mode)
{
    dim3 grid(N / BN, (M + BM - 1) / BM);
    gemm_mma<<<grid, 256, GEMM_SMEM>>>(Ahi, Alo, Bhi, Blo, bias, C, Chi, Clo, M, N, K, mode);
}

extern "C" void kernel_launch(void* const* d_in, const int* in_sizes, int n_in,
                              void* d_out, int out_size)
{
    const int*   states  = (const int*)  d_in[0];
    const int*   actions = (const int*)  d_in[1];
    const float* rewards = (const float*)d_in[2];
    const int*   qstates = (const int*)  d_in[3];
    const int*   tact    = (const int*)  d_in[4];
    const float* wpe     = (const float*)d_in[5];
    const float* e_state = (const float*)d_in[6];
    const float* e_act   = (const float*)d_in[7];
    const float* erw     = (const float*)d_in[8];
    const float* erb     = (const float*)d_in[9];
    const float* ln1g    = (const float*)d_in[10];
    const float* ln1b    = (const float*)d_in[11];
    const float* attnw   = (const float*)d_in[12];
    const float* attnb   = (const float*)d_in[13];
    const float* apw     = (const float*)d_in[14];
    const float* apb     = (const float*)d_in[15];
    const float* ln2g    = (const float*)d_in[16];
    const float* ln2b    = (const float*)d_in[17];
    const float* fcw     = (const float*)d_in[18];
    const float* fcb     = (const float*)d_in[19];
    const float* mpw     = (const float*)d_in[20];
    const float* mpb     = (const float*)d_in[21];
    const float* lnfg    = (const float*)d_in[22];
    const float* lnfb    = (const float*)d_in[23];
    const float* predw   = (const float*)d_in[24];
    const float* predb   = (const float*)d_in[25];
    float* out = (float*)d_out;

    float *h, *qkv, *partial;
    __nv_bfloat16 *xhi, *xlo, *ahi, *alo, *fhi, *flo, *whi, *wlo;
    cudaGetSymbolAddress((void**)&h,    g_h);
    cudaGetSymbolAddress((void**)&qkv,  g_qkv);
    cudaGetSymbolAddress((void**)&partial, g_partial);
    cudaGetSymbolAddress((void**)&xhi,  g_xhi);
    cudaGetSymbolAddress((void**)&xlo,  g_xlo);
    cudaGetSymbolAddress((void**)&ahi,  g_ahi);
    cudaGetSymbolAddress((void**)&alo,  g_alo);
    cudaGetSymbolAddress((void**)&fhi,  g_fhi);
    cudaGetSymbolAddress((void**)&flo,  g_flo);
    cudaGetSymbolAddress((void**)&whi,  g_whi);
    cudaGetSymbolAddress((void**)&wlo,  g_wlo);

    cudaFuncSetAttribute(attn_flash, cudaFuncAttributeMaxDynamicSharedMemorySize, ATTN_SMEM);
    cudaFuncSetAttribute(gemm_mma, cudaFuncAttributeMaxDynamicSharedMemorySize, GEMM_SMEM);

    const size_t WPL = 12582912;
    const size_t OFF_QKV = 0, OFF_PROJ = 3145728, OFF_FC = 4194304, OFF_MP = 8388608;
    for (int i = 0; i < NL_; i++) {
        size_t off = (size_t)i * WPL;
        wprep_kernel<<<dim3(3 * D_ / 32, D_ / 32), dim3(32, 8)>>>(
            attnw + (size_t)i * D_ * 3 * D_, whi + off + OFF_QKV, wlo + off + OFF_QKV, D_, 3 * D_);
        wprep_kernel<<<dim3(D_ / 32, D_ / 32), dim3(32, 8)>>>(
            apw + (size_t)i * D_ * D_, whi + off + OFF_PROJ, wlo + off + OFF_PROJ, D_, D_);
        wprep_kernel<<<dim3(DFF_ / 32, D_ / 32), dim3(32, 8)>>>(
            fcw + (size_t)i * D_ * DFF_, whi + off + OFF_FC, wlo + off + OFF_FC, D_, DFF_);
        wprep_kernel<<<dim3(D_ / 32, DFF_ / 32), dim3(32, 8)>>>(
            mpw + (size_t)i * DFF_ * D_, whi + off + OFF_MP, wlo + off + OFF_MP, DFF_, D_);
    }

    embed_kernel<<<NTOK, 256>>>(states, actions, rewards, qstates, wpe,
                                e_state, e_act, erw, erb, h);

    for (int i = 0; i < NL_; i++) {
        size_t off = (size_t)i * WPL;
        ln_kernel<<<NTOK, 256>>>(h, xhi, xlo, ln1g + i * D_, ln1b + i * D_);
        launch_gemm(xhi, xlo, whi + off + OFF_QKV, wlo + off + OFF_QKV,
                    attnb + i * 3 * D_, qkv, nullptr, nullptr, NTOK, 3 * D_, D_, 0);
        attn_flash<<<B_ * H_, 256, ATTN_SMEM>>>(qkv, ahi, alo);
        launch_gemm(ahi, alo, whi + off + OFF_PROJ, wlo + off + OFF_PROJ,
                    apb + i * D_, h, nullptr, nullptr, NTOK, D_, D_, 2);
        ln_kernel<<<NTOK, 256>>>(h, xhi, xlo, ln2g + i * D_, ln2b + i * D_);
        launch_gemm(xhi, xlo, whi + off + OFF_FC, wlo + off + OFF_FC,
                    fcb + i * DFF_, nullptr, fhi, flo, NTOK, DFF_, D_, 1);
        launch_gemm(fhi, flo, whi + off + OFF_MP, wlo + off + OFF_MP,
                    mpb + i * D_, h, nullptr, nullptr, NTOK, D_, DFF_, 2);
    }

    loss_kernel<<<NPOS, 128>>>(h, lnfg, lnfb, predw, predb, actions, tact, partial);
    reduce_kernel<<<1, 256>>>(partial, out);
}

// round 8
// speedup vs baseline: 3.6038x; 1.1124x over previous
#include <cuda_runtime.h>
#include <cuda_bf16.h>
#include <math.h>
#include <stdint.h>

#define B_    16
#define CTX_  100
#define LSEQ  301
#define D_    1024
#define H_    16
#define HD_   64
#define NL_   4
#define DFF_  4096
#define GRID_ 9
#define NA_   5
#define NTOK  (B_*LSEQ)
#define NPOS  (B_*(CTX_+1))
#define WPOOL 50331648

__device__ float g_h   [NTOK * D_];
__device__ float g_qkv [NTOK * 3 * D_];
__device__ __nv_bfloat16 g_xhi[NTOK * D_];
__device__ __nv_bfloat16 g_xlo[NTOK * D_];
__device__ __nv_bfloat16 g_ahi[NTOK * D_];
__device__ __nv_bfloat16 g_alo[NTOK * D_];
__device__ __nv_bfloat16 g_fhi[NTOK * DFF_];
__device__ __nv_bfloat16 g_flo[NTOK * DFF_];
__device__ __nv_bfloat16 g_whi[WPOOL];
__device__ __nv_bfloat16 g_wlo[WPOOL];
__device__ float g_partial[NPOS * 2];

#define CP16(d, s, z)  asm volatile("cp.async.cg.shared.global [%0], [%1], 16, %2;" :: "r"(d), "l"(s), "r"(z) : "memory")
#define CP_COMMIT()    asm volatile("cp.async.commit_group;" ::: "memory")
#define CP_WAIT(n)     asm volatile("cp.async.wait_group %0;" :: "n"(n) : "memory")
#define SWZ128(o) ((o) ^ (((o) >> 3) & 0x70))

__device__ __forceinline__ uint32_t smem_u32(const void* p) {
    uint32_t a;
    asm("{ .reg .u64 t; cvta.to.shared.u64 t, %1; cvt.u32.u64 %0, t; }" : "=r"(a) : "l"(p));
    return a;
}
__device__ __forceinline__ void ldsm4(uint32_t* r, uint32_t addr) {
    asm volatile("ldmatrix.sync.aligned.m8n8.x4.shared.b16 {%0,%1,%2,%3}, [%4];"
                 : "=r"(r[0]), "=r"(r[1]), "=r"(r[2]), "=r"(r[3]) : "r"(addr));
}
__device__ __forceinline__ void ldsm4t(uint32_t* r, uint32_t addr) {
    asm volatile("ldmatrix.sync.aligned.m8n8.x4.trans.shared.b16 {%0,%1,%2,%3}, [%4];"
                 : "=r"(r[0]), "=r"(r[1]), "=r"(r[2]), "=r"(r[3]) : "r"(addr));
}
__device__ __forceinline__ void mma16816(float* c, const uint32_t* a, const uint32_t* b) {
    asm volatile("mma.sync.aligned.m16n8k16.row.col.f32.bf16.bf16.f32 "
                 "{%0,%1,%2,%3}, {%4,%5,%6,%7}, {%8,%9}, {%0,%1,%2,%3};"
                 : "+f"(c[0]), "+f"(c[1]), "+f"(c[2]), "+f"(c[3])
                 : "r"(a[0]), "r"(a[1]), "r"(a[2]), "r"(a[3]), "r"(b[0]), "r"(b[1]));
}
__device__ __forceinline__ void pack_hilo(float x, float y, uint32_t& hi, uint32_t& lo) {
    __nv_bfloat16 xh = __float2bfloat16(x), yh = __float2bfloat16(y);
    __nv_bfloat162 hv; hv.x = xh; hv.y = yh;
    __nv_bfloat162 lv;
    lv.x = __float2bfloat16(x - __bfloat162float(xh));
    lv.y = __float2bfloat16(y - __bfloat162float(yh));
    hi = *(uint32_t*)&hv; lo = *(uint32_t*)&lv;
}

__device__ __forceinline__ float gelu_new(float xv) {
    float t = tanhf(0.7978845608028654f * (xv + 0.044715f * xv * xv * xv));
    return 0.5f * xv * (1.f + t);
}

// ---------------- embedding ----------------
__global__ void embed_kernel(const int* __restrict__ states,
                             const int* __restrict__ actions,
                             const float* __restrict__ rewards,
                             const int* __restrict__ qstates,
                             const float* __restrict__ wpe,
                             const float* __restrict__ e_state,
                             const float* __restrict__ e_act,
                             const float* __restrict__ erw,
                             const float* __restrict__ erb,
                             float* __restrict__ h)
{
    int tok = blockIdx.x;
    int b = tok / LSEQ, p = tok % LSEQ;
    const float* src = nullptr;
    float r = 0.f;
    int type = 0;
    if (p == 3 * CTX_) {
        int q = qstates[b * 2] * GRID_ + qstates[b * 2 + 1];
        src = e_state + (size_t)q * D_;
    } else {
        int t = p / 3, m = p % 3;
        if (m == 0) {
            int sid = states[(b * CTX_ + t) * 2] * GRID_ + states[(b * CTX_ + t) * 2 + 1];
            src = e_state + (size_t)sid * D_;
        } else if (m == 1) {
            src = e_act + (size_t)actions[b * CTX_ + t] * D_;
        } else {
            r = rewards[b * CTX_ + t];
            type = 1;
        }
    }
    for (int c = threadIdx.x; c < D_; c += blockDim.x) {
        float v = (type == 0) ? src[c] : fmaf(r, erw[c], erb[c]);
        h[(size_t)tok * D_ + c] = v + wpe[(size_t)p * D_ + c];
    }
}

// ---------------- weight transpose + split (batched over layers via z) ----------------
__global__ void wprep_kernel(const float* __restrict__ W,
                             __nv_bfloat16* __restrict__ Thi,
                             __nv_bfloat16* __restrict__ Tlo,
                             int K, int N, size_t sstride, size_t dstride)
{
    __shared__ float t[32][33];
    const float* Wz = W + (size_t)blockIdx.z * sstride;
    __nv_bfloat16* Th = Thi + (size_t)blockIdx.z * dstride;
    __nv_bfloat16* Tl = Tlo + (size_t)blockIdx.z * dstride;
    int n = blockIdx.x * 32 + threadIdx.x;
    int k0 = blockIdx.y * 32;
#pragma unroll
    for (int r = 0; r < 32; r += 8)
        t[threadIdx.y + r][threadIdx.x] = Wz[(size_t)(k0 + threadIdx.y + r) * N + n];
    __syncthreads();
    int k = k0 + threadIdx.x;
#pragma unroll
    for (int r = 0; r < 32; r += 8) {
        int nn = blockIdx.x * 32 + threadIdx.y + r;
        float v = t[threadIdx.x][threadIdx.y + r];
        __nv_bfloat16 hi = __float2bfloat16(v);
        Th[(size_t)nn * K + k] = hi;
        Tl[(size_t)nn * K + k] = __float2bfloat16(v - __bfloat162float(hi));
    }
}

// ---------------- LayerNorm -> hi/lo ----------------
__global__ void ln_kernel(const float* __restrict__ in,
                          __nv_bfloat16* __restrict__ ohi,
                          __nv_bfloat16* __restrict__ olo,
                          const float* __restrict__ g, const float* __restrict__ beta)
{
    __shared__ float red[8];
    int row = blockIdx.x;
    const float* x = in + (size_t)row * D_;
    int tid = threadIdx.x;
    float v[4];
    float s = 0.f;
#pragma unroll
    for (int i = 0; i < 4; i++) { v[i] = x[tid + 256 * i]; s += v[i]; }
#pragma unroll
    for (int o = 16; o; o >>= 1) s += __shfl_xor_sync(0xFFFFFFFFu, s, o);
    if ((tid & 31) == 0) red[tid >> 5] = s;
    __syncthreads();
    float mean = (red[0]+red[1]+red[2]+red[3]+red[4]+red[5]+red[6]+red[7]) * (1.f/1024.f);
    __syncthreads();
    float s2 = 0.f;
#pragma unroll
    for (int i = 0; i < 4; i++) { float d = v[i] - mean; s2 += d * d; }
#pragma unroll
    for (int o = 16; o; o >>= 1) s2 += __shfl_xor_sync(0xFFFFFFFFu, s2, o);
    if ((tid & 31) == 0) red[tid >> 5] = s2;
    __syncthreads();
    float var = (red[0]+red[1]+red[2]+red[3]+red[4]+red[5]+red[6]+red[7]) * (1.f/1024.f);
    float inv = 1.f / sqrtf(var + 1e-5f);
#pragma unroll
    for (int i = 0; i < 4; i++) {
        int c = tid + 256 * i;
        float y = (v[i] - mean) * inv * g[c] + beta[c];
        __nv_bfloat16 hi = __float2bfloat16(y);
        ohi[(size_t)row * D_ + c] = hi;
        olo[(size_t)row * D_ + c] = __float2bfloat16(y - __bfloat162float(hi));
    }
}

// ---------------- mma.sync split-bf16 GEMM, single-barrier 3-stage pipeline ----------------
#define BM 128
#define BN 128
#define BK 64
#define TILE_B  (128 * 128)
#define STAGE_B (4 * TILE_B)
#define STAGES  3
#define GEMM_SMEM (STAGES * STAGE_B)
#define LDS_ 132

__global__ void __launch_bounds__(256, 1)
gemm_mma(const __nv_bfloat16* __restrict__ Ahi, const __nv_bfloat16* __restrict__ Alo,
         const __nv_bfloat16* __restrict__ Bhi, const __nv_bfloat16* __restrict__ Blo,
         const float* __restrict__ bias, float* __restrict__ C,
         __nv_bfloat16* __restrict__ Chi, __nv_bfloat16* __restrict__ Clo,
         int M, int N, int K, int mode)
{
    extern __shared__ __align__(128) char smem[];
    uint32_t sbase = smem_u32(smem);
    int tid = threadIdx.x, wid = tid >> 5, lane = tid & 31;
    int m0 = blockIdx.y * BM, n0 = blockIdx.x * BN;
    int wm = wid >> 2, wn = wid & 3;

    uint32_t so[4];
    unsigned ao[4], bo[4], szA[4];
#pragma unroll
    for (int i = 0; i < 4; i++) {
        int c = tid + 256 * i;
        int r = c >> 3, gb = c & 7;
        so[i] = (uint32_t)SWZ128(r * 128 + gb * 16);
        bool ok = (m0 + r) < M;
        ao[i] = ok ? ((unsigned)(m0 + r) * (unsigned)K + gb * 8) : 0u;
        bo[i] = (unsigned)(n0 + r) * (unsigned)K + gb * 8;
        szA[i] = ok ? 16u : 0u;
    }
    const int nk = K / BK;

    auto load_tile = [&](int kt) {
        uint32_t st = sbase + (uint32_t)(kt % STAGES) * STAGE_B;
        unsigned ko = (unsigned)kt * BK;
#pragma unroll
        for (int i = 0; i < 4; i++) {
            CP16(st + so[i],            Ahi + ao[i] + ko, szA[i]);
            CP16(st + TILE_B + so[i],   Alo + ao[i] + ko, szA[i]);
            CP16(st + 2*TILE_B + so[i], Bhi + bo[i] + ko, 16u);
            CP16(st + 3*TILE_B + so[i], Blo + bo[i] + ko, 16u);
        }
    };

    int a_row_loc = ((lane >> 3) & 1) * 8 + (lane & 7);
    int a_kh = (lane >> 4) * 16;
    int b_row_loc = (lane >> 4) * 8 + (lane & 7);
    int b_kh = ((lane >> 3) & 1) * 16;

    float acc[4][4][4];
#pragma unroll
    for (int i = 0; i < 4; i++)
#pragma unroll
        for (int j = 0; j < 4; j++)
#pragma unroll
            for (int k = 0; k < 4; k++) acc[i][j][k] = 0.f;

    load_tile(0);
    CP_COMMIT();
    if (nk > 1) load_tile(1);
    CP_COMMIT();

    uint32_t a_base[4], b_base[2];
    int a_ph[4], b_ph[2];
#pragma unroll
    for (int mt = 0; mt < 4; mt++) {
        int row = wm * 64 + mt * 16 + a_row_loc;
        a_base[mt] = (uint32_t)(row * 128);
        a_ph[mt] = (row & 7) << 4;
    }
#pragma unroll
    for (int j = 0; j < 2; j++) {
        int row = wn * 32 + j * 16 + b_row_loc;
        b_base[j] = (uint32_t)(row * 128);
        b_ph[j] = (row & 7) << 4;
    }

    for (int kt = 0; kt < nk; kt++) {
        CP_WAIT(1);
        __syncthreads();
        if (kt + 2 < nk) load_tile(kt + 2);
        CP_COMMIT();
        uint32_t st = sbase + (uint32_t)(kt % STAGES) * STAGE_B;
        uint32_t stA = st, stAl = st + TILE_B, stB = st + 2*TILE_B, stBl = st + 3*TILE_B;
#pragma unroll
        for (int ks = 0; ks < 4; ks++) {
            uint32_t ah[4][4], al[4][4], bh[2][4], bl[2][4];
#pragma unroll
            for (int j = 0; j < 2; j++) {
                uint32_t off = b_base[j] + (uint32_t)((ks * 32 + b_kh) ^ b_ph[j]);
                ldsm4(bh[j], stB + off);
                ldsm4(bl[j], stBl + off);
            }
#pragma unroll
            for (int mt = 0; mt < 4; mt++) {
                uint32_t off = a_base[mt] + (uint32_t)((ks * 32 + a_kh) ^ a_ph[mt]);
                ldsm4(ah[mt], stA + off);
                ldsm4(al[mt], stAl + off);
            }
#pragma unroll
            for (int mt = 0; mt < 4; mt++)
#pragma unroll
                for (int nt = 0; nt < 4; nt++) {
                    const uint32_t* bph = &bh[nt >> 1][(nt & 1) * 2];
                    const uint32_t* bpl = &bl[nt >> 1][(nt & 1) * 2];
                    mma16816(acc[mt][nt], ah[mt], bph);
                    mma16816(acc[mt][nt], ah[mt], bpl);
                    mma16816(acc[mt][nt], al[mt], bph);
                }
        }
    }
    CP_WAIT(0);
    __syncthreads();

    // ---- epilogue: stage fp32 accumulators, then vectorized global pass ----
    float* stg = (float*)smem;
    int cr = lane >> 2, ccol = (lane & 3) * 2;
#pragma unroll
    for (int mt = 0; mt < 4; mt++)
#pragma unroll
        for (int nt = 0; nt < 4; nt++) {
            int r = wm * 64 + mt * 16 + cr;
            int cl = wn * 32 + nt * 8 + ccol;
            *(float2*)&stg[r * LDS_ + cl]       = make_float2(acc[mt][nt][0], acc[mt][nt][1]);
            *(float2*)&stg[(r + 8) * LDS_ + cl] = make_float2(acc[mt][nt][2], acc[mt][nt][3]);
        }
    __syncthreads();

#pragma unroll
    for (int i = 0; i < 16; i++) {
        int id = tid + 256 * i;
        int r = id >> 5, cc = (id & 31) * 4;
        int m = m0 + r;
        if (m < M) {
            int n = n0 + cc;
            float4 v = *(float4*)&stg[r * LDS_ + cc];
            float4 bs = *(const float4*)&bias[n];
            v.x += bs.x; v.y += bs.y; v.z += bs.z; v.w += bs.w;
            size_t idx = (size_t)m * N + n;
            if (mode == 0) {
                *(float4*)&C[idx] = v;
            } else if (mode == 1) {
                float g0 = gelu_new(v.x), g1 = gelu_new(v.y);
                float g2 = gelu_new(v.z), g3 = gelu_new(v.w);
                uint32_t h01, l01, h23, l23;
                pack_hilo(g0, g1, h01, l01);
                pack_hilo(g2, g3, h23, l23);
                *(uint2*)&Chi[idx] = make_uint2(h01, h23);
                *(uint2*)&Clo[idx] = make_uint2(l01, l23);
            } else {
                float4 c0 = *(float4*)&C[idx];
                c0.x += v.x; c0.y += v.y; c0.z += v.z; c0.w += v.w;
                *(float4*)&C[idx] = c0;
            }
        }
    }
}

// ---------------- flash attention (split-bf16 mma) ----------------
#define AKHI 0
#define AKLO 38912
#define AVHI 77824
#define AVLO 116736
#define ATTN_SMEM 155648

__global__ void __launch_bounds__(256)
attn_flash(const float* __restrict__ qkv,
           __nv_bfloat16* __restrict__ ohi, __nv_bfloat16* __restrict__ olo)
{
    extern __shared__ __align__(128) char asmem[];
    uint32_t sb = smem_u32(asmem);
    int tid = threadIdx.x;
    int bh = blockIdx.x, b = bh >> 4, hd = bh & 15;
    const float* base = qkv + (size_t)b * LSEQ * 3072;
    int hoff = hd * 64;

    for (int idx = tid; idx < 304 * 64; idx += 256) {
        int j = idx >> 6, d = idx & 63;
        float kv = 0.f, vv = 0.f;
        if (j < LSEQ) {
            kv = base[(size_t)j * 3072 + 1024 + hoff + d];
            vv = base[(size_t)j * 3072 + 2048 + hoff + d];
        }
        uint32_t off = (uint32_t)SWZ128(j * 128 + d * 2);
        __nv_bfloat16 kh = __float2bfloat16(kv);
        *(__nv_bfloat16*)(asmem + AKHI + off) = kh;
        *(__nv_bfloat16*)(asmem + AKLO + off) = __float2bfloat16(kv - __bfloat162float(kh));
        __nv_bfloat16 vh = __float2bfloat16(vv);
        *(__nv_bfloat16*)(asmem + AVHI + off) = vh;
        *(__nv_bfloat16*)(asmem + AVLO + off) = __float2bfloat16(vv - __bfloat162float(vh));
    }
    __syncthreads();

    int w = tid >> 5, lane = tid & 31;
    int g = lane >> 2, t4 = lane & 3;
    int kb_row = (lane >> 4) * 8 + (lane & 7);
    int kb_kb  = ((lane >> 3) & 1) * 16;
    int vb_row = ((lane >> 3) & 1) * 8 + (lane & 7);
    int vb_nb  = (lane >> 4) * 16;

    for (int qi = 0; qi < 3; qi++) {
        int qt = (qi == 0) ? (18 - w) : ((qi == 1) ? (3 + w) : ((w < 3) ? (2 - w) : -1));
        if (qt < 0) continue;
        int q0 = qt * 16;

        uint32_t qh[4][4], ql[4][4];
        int r1 = q0 + g;       int r1c = r1 < LSEQ ? r1 : LSEQ - 1;
        int r2 = r1 + 8;       int r2c = r2 < LSEQ ? r2 : LSEQ - 1;
        const float* q1p = base + (size_t)r1c * 3072 + hoff;
        const float* q2p = base + (size_t)r2c * 3072 + hoff;
#pragma unroll
        for (int kt = 0; kt < 4; kt++) {
            int c0 = kt * 16 + 2 * t4;
            float2 x0 = *(const float2*)(q1p + c0);
            float2 x1 = *(const float2*)(q2p + c0);
            float2 x2 = *(const float2*)(q1p + c0 + 8);
            float2 x3 = *(const float2*)(q2p + c0 + 8);
            pack_hilo(x0.x, x0.y, qh[kt][0], ql[kt][0]);
            pack_hilo(x1.x, x1.y, qh[kt][1], ql[kt][1]);
            pack_hilo(x2.x, x2.y, qh[kt][2], ql[kt][2]);
            pack_hilo(x3.x, x3.y, qh[kt][3], ql[kt][3]);
        }

        float m0 = -1e30f, m1 = -1e30f, l0 = 0.f, l1 = 0.f;
        float o[8][4];
#pragma unroll
        for (int i = 0; i < 8; i++)
#pragma unroll
            for (int k = 0; k < 4; k++) o[i][k] = 0.f;

        for (int jt = 0; jt <= qt; jt++) {
            float s[2][4] = {{0,0,0,0},{0,0,0,0}};
#pragma unroll
            for (int kt = 0; kt < 4; kt++) {
                int row = jt * 16 + kb_row;
                uint32_t off = (uint32_t)(row * 128 + ((kt * 32 + kb_kb) ^ ((row & 7) << 4)));
                uint32_t kh4[4], kl4[4];
                ldsm4(kh4, sb + AKHI + off);
                ldsm4(kl4, sb + AKLO + off);
#pragma unroll
                for (int nt = 0; nt < 2; nt++) {
                    mma16816(s[nt], qh[kt], &kh4[nt*2]);
                    mma16816(s[nt], qh[kt], &kl4[nt*2]);
                    mma16816(s[nt], ql[kt], &kh4[nt*2]);
                }
            }
            int qr1 = q0 + g, qr2 = qr1 + 8;
#pragma unroll
            for (int nt = 0; nt < 2; nt++) {
                int jc = jt * 16 + nt * 8 + 2 * t4;
                s[nt][0] = (jc     <= qr1) ? s[nt][0] * 0.125f : -1e30f;
                s[nt][1] = (jc + 1 <= qr1) ? s[nt][1] * 0.125f : -1e30f;
                s[nt][2] = (jc     <= qr2) ? s[nt][2] * 0.125f : -1e30f;
                s[nt][3] = (jc + 1 <= qr2) ? s[nt][3] * 0.125f : -1e30f;
            }
            float tm0 = fmaxf(fmaxf(s[0][0], s[0][1]), fmaxf(s[1][0], s[1][1]));
            float tm1 = fmaxf(fmaxf(s[0][2], s[0][3]), fmaxf(s[1][2], s[1][3]));
            tm0 = fmaxf(tm0, __shfl_xor_sync(0xFFFFFFFFu, tm0, 1));
            tm0 = fmaxf(tm0, __shfl_xor_sync(0xFFFFFFFFu, tm0, 2));
            tm1 = fmaxf(tm1, __shfl_xor_sync(0xFFFFFFFFu, tm1, 1));
            tm1 = fmaxf(tm1, __shfl_xor_sync(0xFFFFFFFFu, tm1, 2));
            float mn0 = fmaxf(m0, tm0), mn1 = fmaxf(m1, tm1);
            float sc0 = expf(m0 - mn0), sc1 = expf(m1 - mn1);
            m0 = mn0; m1 = mn1;
            float p[2][4];
#pragma unroll
            for (int nt = 0; nt < 2; nt++) {
                p[nt][0] = expf(s[nt][0] - mn0);
                p[nt][1] = expf(s[nt][1] - mn0);
                p[nt][2] = expf(s[nt][2] - mn1);
                p[nt][3] = expf(s[nt][3] - mn1);
            }
            float ts0 = p[0][0] + p[0][1] + p[1][0] + p[1][1];
            float ts1 = p[0][2] + p[0][3] + p[1][2] + p[1][3];
            ts0 += __shfl_xor_sync(0xFFFFFFFFu, ts0, 1);
            ts0 += __shfl_xor_sync(0xFFFFFFFFu, ts0, 2);
            ts1 += __shfl_xor_sync(0xFFFFFFFFu, ts1, 1);
            ts1 += __shfl_xor_sync(0xFFFFFFFFu, ts1, 2);
            l0 = l0 * sc0 + ts0;
            l1 = l1 * sc1 + ts1;
#pragma unroll
            for (int nt = 0; nt < 8; nt++) {
                o[nt][0] *= sc0; o[nt][1] *= sc0; o[nt][2] *= sc1; o[nt][3] *= sc1;
            }
            uint32_t pah[4], pal[4];
            pack_hilo(p[0][0], p[0][1], pah[0], pal[0]);
            pack_hilo(p[0][2], p[0][3], pah[1], pal[1]);
            pack_hilo(p[1][0], p[1][1], pah[2], pal[2]);
            pack_hilo(p[1][2], p[1][3], pah[3], pal[3]);
#pragma unroll
            for (int dt = 0; dt < 4; dt++) {
                int row = jt * 16 + vb_row;
                uint32_t off = (uint32_t)(row * 128 + ((dt * 32 + vb_nb) ^ ((row & 7) << 4)));
                uint32_t vh4[4], vl4[4];
                ldsm4t(vh4, sb + AVHI + off);
                ldsm4t(vl4, sb + AVLO + off);
#pragma unroll
                for (int su = 0; su < 2; su++) {
                    int nt = dt * 2 + su;
                    mma16816(o[nt], pah, &vh4[su*2]);
                    mma16816(o[nt], pah, &vl4[su*2]);
                    mma16816(o[nt], pal, &vh4[su*2]);
                }
            }
        }
        float inv0 = 1.f / l0, inv1 = 1.f / l1;
        int row1 = q0 + g, row2 = row1 + 8;
#pragma unroll
        for (int nt = 0; nt < 8; nt++) {
            int col = nt * 8 + 2 * t4;
            if (row1 < LSEQ) {
                uint32_t hp, lp;
                pack_hilo(o[nt][0] * inv0, o[nt][1] * inv0, hp, lp);
                size_t idx = (size_t)(b * LSEQ + row1) * D_ + hoff + col;
                *(uint32_t*)&ohi[idx] = hp;
                *(uint32_t*)&olo[idx] = lp;
            }
            if (row2 < LSEQ) {
                uint32_t hp, lp;
                pack_hilo(o[nt][2] * inv1, o[nt][3] * inv1, hp, lp);
                size_t idx = (size_t)(b * LSEQ + row2) * D_ + hoff + col;
                *(uint32_t*)&ohi[idx] = hp;
                *(uint32_t*)&olo[idx] = lp;
            }
        }
    }
}

// ---------------- loss ----------------
__global__ void loss_kernel(const float* __restrict__ h,
                            const float* __restrict__ g,
                            const float* __restrict__ beta,
                            const float* __restrict__ pw,
                            const float* __restrict__ pb,
                            const int* __restrict__ actions,
                            const int* __restrict__ tact,
                            float* __restrict__ partial)
{
    __shared__ float red[4];
    __shared__ float lred[5][4];
    int idx = blockIdx.x;
    int b = idx / (CTX_ + 1), t = idx % (CTX_ + 1);
    const float* x = h + (size_t)(b * LSEQ + 3 * t) * D_;
    int tid = threadIdx.x, lane = tid & 31, w = tid >> 5;

    float v[8];
    float s = 0.f;
#pragma unroll
    for (int i = 0; i < 8; i++) { v[i] = x[tid + 128 * i]; s += v[i]; }
#pragma unroll
    for (int o = 16; o; o >>= 1) s += __shfl_xor_sync(0xFFFFFFFFu, s, o);
    if (lane == 0) red[w] = s;
    __syncthreads();
    float mean = (red[0] + red[1] + red[2] + red[3]) * (1.f / 1024.f);
    __syncthreads();
    float s2 = 0.f;
#pragma unroll
    for (int i = 0; i < 8; i++) { float d = v[i] - mean; s2 += d * d; }
#pragma unroll
    for (int o = 16; o; o >>= 1) s2 += __shfl_xor_sync(0xFFFFFFFFu, s2, o);
    if (lane == 0) red[w] = s2;
    __syncthreads();
    float var = (red[0] + red[1] + red[2] + red[3]) * (1.f / 1024.f);
    float inv = 1.f / sqrtf(var + 1e-5f);

    float acc[NA_] = {0.f, 0.f, 0.f, 0.f, 0.f};
#pragma unroll
    for (int i = 0; i < 8; i++) {
        int c = tid + 128 * i;
        float xn = (v[i] - mean) * inv * g[c] + beta[c];
#pragma unroll
        for (int a = 0; a < NA_; a++)
            acc[a] = fmaf(xn, pw[c * NA_ + a], acc[a]);
    }
#pragma unroll
    for (int a = 0; a < NA_; a++) {
        float tv = acc[a];
#pragma unroll
        for (int o = 16; o; o >>= 1) tv += __shfl_xor_sync(0xFFFFFFFFu, tv, o);
        if (lane == 0) lred[a][w] = tv;
    }
    __syncthreads();
    if (tid == 0) {
        float logit[NA_];
#pragma unroll
        for (int a = 0; a < NA_; a++)
            logit[a] = lred[a][0] + lred[a][1] + lred[a][2] + lred[a][3] + pb[a];
        int target = (t < CTX_) ? actions[b * CTX_ + t] : tact[b];
        float mx = logit[0]; int am = 0;
#pragma unroll
        for (int a = 1; a < NA_; a++) if (logit[a] > mx) { mx = logit[a]; am = a; }
        float se = 0.f;
#pragma unroll
        for (int a = 0; a < NA_; a++) se += expf(logit[a] - mx);
        float lse = mx + logf(se);
        float sl = 0.f;
#pragma unroll
        for (int a = 0; a < NA_; a++) sl += (logit[a] - lse);
        float nll = -(logit[target] - lse);
        float smooth = -sl * (1.f / NA_);
        partial[2 * idx]     = 0.9f * nll + 0.1f * smooth;
        partial[2 * idx + 1] = (am == target) ? 1.f : 0.f;
    }
}

__global__ void reduce_kernel(const float* __restrict__ partial, float* __restrict__ out)
{
    __shared__ float rl[8], ra[8];
    int tid = threadIdx.x, lane = tid & 31, w = tid >> 5;
    float l = 0.f, a = 0.f;
    for (int i = tid; i < NPOS; i += 256) {
        l += partial[2 * i];
        a += partial[2 * i + 1];
    }
#pragma unroll
    for (int o = 16; o; o >>= 1) {
        l += __shfl_xor_sync(0xFFFFFFFFu, l, o);
        a += __shfl_xor_sync(0xFFFFFFFFu, a, o);
    }
    if (lane == 0) { rl[w] = l; ra[w] = a; }
    __syncthreads();
    if (tid == 0) {
        float L = 0.f, A = 0.f;
#pragma unroll
        for (int i = 0; i < 8; i++) { L += rl[i]; A += ra[i]; }
        out[0] = L * (1.f / NPOS);
        out[1] = A * (1.f / NPOS);
    }
}

// ---------------- host ----------------
static inline void launch_gemm(const __nv_bfloat16* Ahi, const __nv_bfloat16* Alo,
                               const __nv_bfloat16* Bhi, const __nv_bfloat16* Blo,
                               const float* bias, float* C,
                               __nv_bfloat16* Chi, __nv_bfloat16* Clo,
                               int M, int N, int K, int mode)
{
    dim3 grid(N / BN, (M + BM - 1) / BM);
    gemm_mma<<<grid, 256, GEMM_SMEM>>>(Ahi, Alo, Bhi, Blo, bias, C, Chi, Clo, M, N, K, mode);
}

extern "C" void kernel_launch(void* const* d_in, const int* in_sizes, int n_in,
                              void* d_out, int out_size)
{
    const int*   states  = (const int*)  d_in[0];
    const int*   actions = (const int*)  d_in[1];
    const float* rewards = (const float*)d_in[2];
    const int*   qstates = (const int*)  d_in[3];
    const int*   tact    = (const int*)  d_in[4];
    const float* wpe     = (const float*)d_in[5];
    const float* e_state = (const float*)d_in[6];
    const float* e_act   = (const float*)d_in[7];
    const float* erw     = (const float*)d_in[8];
    const float* erb     = (const float*)d_in[9];
    const float* ln1g    = (const float*)d_in[10];
    const float* ln1b    = (const float*)d_in[11];
    const float* attnw   = (const float*)d_in[12];
    const float* attnb   = (const float*)d_in[13];
    const float* apw     = (const float*)d_in[14];
    const float* apb     = (const float*)d_in[15];
    const float* ln2g    = (const float*)d_in[16];
    const float* ln2b    = (const float*)d_in[17];
    const float* fcw     = (const float*)d_in[18];
    const float* fcb     = (const float*)d_in[19];
    const float* mpw     = (const float*)d_in[20];
    const float* mpb     = (const float*)d_in[21];
    const float* lnfg    = (const float*)d_in[22];
    const float* lnfb    = (const float*)d_in[23];
    const float* predw   = (const float*)d_in[24];
    const float* predb   = (const float*)d_in[25];
    float* out = (float*)d_out;

    float *h, *qkv, *partial;
    __nv_bfloat16 *xhi, *xlo, *ahi, *alo, *fhi, *flo, *whi, *wlo;
    cudaGetSymbolAddress((void**)&h,    g_h);
    cudaGetSymbolAddress((void**)&qkv,  g_qkv);
    cudaGetSymbolAddress((void**)&partial, g_partial);
    cudaGetSymbolAddress((void**)&xhi,  g_xhi);
    cudaGetSymbolAddress((void**)&xlo,  g_xlo);
    cudaGetSymbolAddress((void**)&ahi,  g_ahi);
    cudaGetSymbolAddress((void**)&alo,  g_alo);
    cudaGetSymbolAddress((void**)&fhi,  g_fhi);
    cudaGetSymbolAddress((void**)&flo,  g_flo);
    cudaGetSymbolAddress((void**)&whi,  g_whi);
    cudaGetSymbolAddress((void**)&wlo,  g_wlo);

    cudaFuncSetAttribute(attn_flash, cudaFuncAttributeMaxDynamicSharedMemorySize, ATTN_SMEM);
    cudaFuncSetAttribute(gemm_mma, cudaFuncAttributeMaxDynamicSharedMemorySize, GEMM_SMEM);

    const size_t WPL = 12582912;
    const size_t OFF_QKV = 0, OFF_PROJ = 3145728, OFF_FC = 4194304, OFF_MP = 8388608;
    // batched weight prep: z = layer
    wprep_kernel<<<dim3(3 * D_ / 32, D_ / 32, NL_), dim3(32, 8)>>>(
        attnw, whi + OFF_QKV, wlo + OFF_QKV, D_, 3 * D_, (size_t)D_ * 3 * D_, WPL);
    wprep_kernel<<<dim3(D_ / 32, D_ / 32, NL_), dim3(32, 8)>>>(
        apw, whi + OFF_PROJ, wlo + OFF_PROJ, D_, D_, (size_t)D_ * D_, WPL);
    wprep_kernel<<<dim3(DFF_ / 32, D_ / 32, NL_), dim3(32, 8)>>>(
        fcw, whi + OFF_FC, wlo + OFF_FC, D_, DFF_, (size_t)D_ * DFF_, WPL);
    wprep_kernel<<<dim3(D_ / 32, DFF_ / 32, NL_), dim3(32, 8)>>>(
        mpw, whi + OFF_MP, wlo + OFF_MP, DFF_, D_, (size_t)DFF_ * D_, WPL);

    embed_kernel<<<NTOK, 256>>>(states, actions, rewards, qstates, wpe,
                                e_state, e_act, erw, erb, h);

    for (int i = 0; i < NL_; i++) {
        size_t off = (size_t)i * WPL;
        ln_kernel<<<NTOK, 256>>>(h, xhi, xlo, ln1g + i * D_, ln1b + i * D_);
        launch_gemm(xhi, xlo, whi + off + OFF_QKV, wlo + off + OFF_QKV,
                    attnb + i * 3 * D_, qkv, nullptr, nullptr, NTOK, 3 * D_, D_, 0);
        attn_flash<<<B_ * H_, 256, ATTN_SMEM>>>(qkv, ahi, alo);
        launch_gemm(ahi, alo, whi + off + OFF_PROJ, wlo + off + OFF_PROJ,
                    apb + i * D_, h, nullptr, nullptr, NTOK, D_, D_, 2);
        ln_kernel<<<NTOK, 256>>>(h, xhi, xlo, ln2g + i * D_, ln2b + i * D_);
        launch_gemm(xhi, xlo, whi + off + OFF_FC, wlo + off + OFF_FC,
                    fcb + i * DFF_, nullptr, fhi, flo, NTOK, DFF_, D_, 1);
        launch_gemm(fhi, flo, whi + off + OFF_MP, wlo + off + OFF_MP,
                    mpb + i * D_, h, nullptr, nullptr, NTOK, D_, DFF_, 2);
    }

    loss_kernel<<<NPOS, 128>>>(h, lnfg, lnfb, predw, predb, actions, tact, partial);
    reduce_kernel<<<1, 256>>>(partial, out);
}

// round 9
// speedup vs baseline: 3.7255x; 1.0338x over previous
#include <cuda_runtime.h>
#include <cuda_bf16.h>
#include <math.h>
#include <stdint.h>

#define B_    16
#define CTX_  100
#define LSEQ  301
#define D_    1024
#define H_    16
#define HD_   64
#define NL_   4
#define DFF_  4096
#define GRID_ 9
#define NA_   5
#define NTOK  (B_*LSEQ)
#define NPOS  (B_*(CTX_+1))
#define WPOOL 50331648

__device__ float g_h   [NTOK * D_];
__device__ float g_qkv [NTOK * 3 * D_];
__device__ __nv_bfloat16 g_xhi[NTOK * D_];
__device__ __nv_bfloat16 g_xlo[NTOK * D_];
__device__ __nv_bfloat16 g_ahi[NTOK * D_];
__device__ __nv_bfloat16 g_alo[NTOK * D_];
__device__ __nv_bfloat16 g_fhi[NTOK * DFF_];
__device__ __nv_bfloat16 g_flo[NTOK * DFF_];
__device__ __nv_bfloat16 g_whi[WPOOL];
__device__ __nv_bfloat16 g_wlo[WPOOL];
__device__ float g_partial[NPOS * 2];

#define CP16(d, s, z)  asm volatile("cp.async.cg.shared.global [%0], [%1], 16, %2;" :: "r"(d), "l"(s), "r"(z) : "memory")
#define CP_COMMIT()    asm volatile("cp.async.commit_group;" ::: "memory")
#define CP_WAIT(n)     asm volatile("cp.async.wait_group %0;" :: "n"(n) : "memory")
#define SWZ128(o) ((o) ^ (((o) >> 3) & 0x70))

__device__ __forceinline__ uint32_t smem_u32(const void* p) {
    uint32_t a;
    asm("{ .reg .u64 t; cvta.to.shared.u64 t, %1; cvt.u32.u64 %0, t; }" : "=r"(a) : "l"(p));
    return a;
}
__device__ __forceinline__ void ldsm4(uint32_t* r, uint32_t addr) {
    asm volatile("ldmatrix.sync.aligned.m8n8.x4.shared.b16 {%0,%1,%2,%3}, [%4];"
                 : "=r"(r[0]), "=r"(r[1]), "=r"(r[2]), "=r"(r[3]) : "r"(addr));
}
__device__ __forceinline__ void ldsm4t(uint32_t* r, uint32_t addr) {
    asm volatile("ldmatrix.sync.aligned.m8n8.x4.trans.shared.b16 {%0,%1,%2,%3}, [%4];"
                 : "=r"(r[0]), "=r"(r[1]), "=r"(r[2]), "=r"(r[3]) : "r"(addr));
}
__device__ __forceinline__ void mma16816(float* c, const uint32_t* a, const uint32_t* b) {
    asm volatile("mma.sync.aligned.m16n8k16.row.col.f32.bf16.bf16.f32 "
                 "{%0,%1,%2,%3}, {%4,%5,%6,%7}, {%8,%9}, {%0,%1,%2,%3};"
                 : "+f"(c[0]), "+f"(c[1]), "+f"(c[2]), "+f"(c[3])
                 : "r"(a[0]), "r"(a[1]), "r"(a[2]), "r"(a[3]), "r"(b[0]), "r"(b[1]));
}
__device__ __forceinline__ void pack_hilo(float x, float y, uint32_t& hi, uint32_t& lo) {
    __nv_bfloat16 xh = __float2bfloat16(x), yh = __float2bfloat16(y);
    __nv_bfloat162 hv; hv.x = xh; hv.y = yh;
    __nv_bfloat162 lv;
    lv.x = __float2bfloat16(x - __bfloat162float(xh));
    lv.y = __float2bfloat16(y - __bfloat162float(yh));
    hi = *(uint32_t*)&hv; lo = *(uint32_t*)&lv;
}

__device__ __forceinline__ float gelu_new(float xv) {
    float t = tanhf(0.7978845608028654f * (xv + 0.044715f * xv * xv * xv));
    return 0.5f * xv * (1.f + t);
}

// ---------------- embedding ----------------
__global__ void embed_kernel(const int* __restrict__ states,
                             const int* __restrict__ actions,
                             const float* __restrict__ rewards,
                             const int* __restrict__ qstates,
                             const float* __restrict__ wpe,
                             const float* __restrict__ e_state,
                             const float* __restrict__ e_act,
                             const float* __restrict__ erw,
                             const float* __restrict__ erb,
                             float* __restrict__ h)
{
    int tok = blockIdx.x;
    int b = tok / LSEQ, p = tok % LSEQ;
    const float* src = nullptr;
    float r = 0.f;
    int type = 0;
    if (p == 3 * CTX_) {
        int q = qstates[b * 2] * GRID_ + qstates[b * 2 + 1];
        src = e_state + (size_t)q * D_;
    } else {
        int t = p / 3, m = p % 3;
        if (m == 0) {
            int sid = states[(b * CTX_ + t) * 2] * GRID_ + states[(b * CTX_ + t) * 2 + 1];
            src = e_state + (size_t)sid * D_;
        } else if (m == 1) {
            src = e_act + (size_t)actions[b * CTX_ + t] * D_;
        } else {
            r = rewards[b * CTX_ + t];
            type = 1;
        }
    }
    for (int c = threadIdx.x; c < D_; c += blockDim.x) {
        float v = (type == 0) ? src[c] : fmaf(r, erw[c], erb[c]);
        h[(size_t)tok * D_ + c] = v + wpe[(size_t)p * D_ + c];
    }
}

// ---------------- weight transpose + split (batched over layers via z) ----------------
__global__ void wprep_kernel(const float* __restrict__ W,
                             __nv_bfloat16* __restrict__ Thi,
                             __nv_bfloat16* __restrict__ Tlo,
                             int K, int N, size_t sstride, size_t dstride)
{
    __shared__ float t[32][33];
    const float* Wz = W + (size_t)blockIdx.z * sstride;
    __nv_bfloat16* Th = Thi + (size_t)blockIdx.z * dstride;
    __nv_bfloat16* Tl = Tlo + (size_t)blockIdx.z * dstride;
    int n = blockIdx.x * 32 + threadIdx.x;
    int k0 = blockIdx.y * 32;
#pragma unroll
    for (int r = 0; r < 32; r += 8)
        t[threadIdx.y + r][threadIdx.x] = Wz[(size_t)(k0 + threadIdx.y + r) * N + n];
    __syncthreads();
    int k = k0 + threadIdx.x;
#pragma unroll
    for (int r = 0; r < 32; r += 8) {
        int nn = blockIdx.x * 32 + threadIdx.y + r;
        float v = t[threadIdx.x][threadIdx.y + r];
        __nv_bfloat16 hi = __float2bfloat16(v);
        Th[(size_t)nn * K + k] = hi;
        Tl[(size_t)nn * K + k] = __float2bfloat16(v - __bfloat162float(hi));
    }
}

// ---------------- LayerNorm -> hi/lo ----------------
__global__ void ln_kernel(const float* __restrict__ in,
                          __nv_bfloat16* __restrict__ ohi,
                          __nv_bfloat16* __restrict__ olo,
                          const float* __restrict__ g, const float* __restrict__ beta)
{
    __shared__ float red[8];
    int row = blockIdx.x;
    const float* x = in + (size_t)row * D_;
    int tid = threadIdx.x;
    float v[4];
    float s = 0.f;
#pragma unroll
    for (int i = 0; i < 4; i++) { v[i] = x[tid + 256 * i]; s += v[i]; }
#pragma unroll
    for (int o = 16; o; o >>= 1) s += __shfl_xor_sync(0xFFFFFFFFu, s, o);
    if ((tid & 31) == 0) red[tid >> 5] = s;
    __syncthreads();
    float mean = (red[0]+red[1]+red[2]+red[3]+red[4]+red[5]+red[6]+red[7]) * (1.f/1024.f);
    __syncthreads();
    float s2 = 0.f;
#pragma unroll
    for (int i = 0; i < 4; i++) { float d = v[i] - mean; s2 += d * d; }
#pragma unroll
    for (int o = 16; o; o >>= 1) s2 += __shfl_xor_sync(0xFFFFFFFFu, s2, o);
    if ((tid & 31) == 0) red[tid >> 5] = s2;
    __syncthreads();
    float var = (red[0]+red[1]+red[2]+red[3]+red[4]+red[5]+red[6]+red[7]) * (1.f/1024.f);
    float inv = 1.f / sqrtf(var + 1e-5f);
#pragma unroll
    for (int i = 0; i < 4; i++) {
        int c = tid + 256 * i;
        float y = (v[i] - mean) * inv * g[c] + beta[c];
        __nv_bfloat16 hi = __float2bfloat16(y);
        ohi[(size_t)row * D_ + c] = hi;
        olo[(size_t)row * D_ + c] = __float2bfloat16(y - __bfloat162float(hi));
    }
}

// ---------------- GEMM 128x128 (QKV / FC), 3-stage, 1 CTA/SM ----------------
#define BM 128
#define BN 128
#define BK 64
#define TILE_B  (128 * 128)
#define STAGE_B (4 * TILE_B)
#define STAGES  3
#define GEMM_SMEM (STAGES * STAGE_B)
#define LDS_ 132

__global__ void __launch_bounds__(256, 1)
gemm_mma(const __nv_bfloat16* __restrict__ Ahi, const __nv_bfloat16* __restrict__ Alo,
         const __nv_bfloat16* __restrict__ Bhi, const __nv_bfloat16* __restrict__ Blo,
         const float* __restrict__ bias, float* __restrict__ C,
         __nv_bfloat16* __restrict__ Chi, __nv_bfloat16* __restrict__ Clo,
         int M, int N, int K, int mode)
{
    extern __shared__ __align__(128) char smem[];
    uint32_t sbase = smem_u32(smem);
    int tid = threadIdx.x, wid = tid >> 5, lane = tid & 31;
    int m0 = blockIdx.y * BM, n0 = blockIdx.x * BN;
    int wm = wid >> 2, wn = wid & 3;

    uint32_t so[4];
    unsigned ao[4], bo[4], szA[4];
#pragma unroll
    for (int i = 0; i < 4; i++) {
        int c = tid + 256 * i;
        int r = c >> 3, gb = c & 7;
        so[i] = (uint32_t)SWZ128(r * 128 + gb * 16);
        bool ok = (m0 + r) < M;
        ao[i] = ok ? ((unsigned)(m0 + r) * (unsigned)K + gb * 8) : 0u;
        bo[i] = (unsigned)(n0 + r) * (unsigned)K + gb * 8;
        szA[i] = ok ? 16u : 0u;
    }
    const int nk = K / BK;

    auto load_tile = [&](int kt) {
        uint32_t st = sbase + (uint32_t)(kt % STAGES) * STAGE_B;
        unsigned ko = (unsigned)kt * BK;
#pragma unroll
        for (int i = 0; i < 4; i++) {
            CP16(st + so[i],            Ahi + ao[i] + ko, szA[i]);
            CP16(st + TILE_B + so[i],   Alo + ao[i] + ko, szA[i]);
            CP16(st + 2*TILE_B + so[i], Bhi + bo[i] + ko, 16u);
            CP16(st + 3*TILE_B + so[i], Blo + bo[i] + ko, 16u);
        }
    };

    int a_row_loc = ((lane >> 3) & 1) * 8 + (lane & 7);
    int a_kh = (lane >> 4) * 16;
    int b_row_loc = (lane >> 4) * 8 + (lane & 7);
    int b_kh = ((lane >> 3) & 1) * 16;

    float acc[4][4][4];
#pragma unroll
    for (int i = 0; i < 4; i++)
#pragma unroll
        for (int j = 0; j < 4; j++)
#pragma unroll
            for (int k = 0; k < 4; k++) acc[i][j][k] = 0.f;

    load_tile(0);
    CP_COMMIT();
    if (nk > 1) load_tile(1);
    CP_COMMIT();

    uint32_t a_base[4], b_base[2];
    int a_ph[4], b_ph[2];
#pragma unroll
    for (int mt = 0; mt < 4; mt++) {
        int row = wm * 64 + mt * 16 + a_row_loc;
        a_base[mt] = (uint32_t)(row * 128);
        a_ph[mt] = (row & 7) << 4;
    }
#pragma unroll
    for (int j = 0; j < 2; j++) {
        int row = wn * 32 + j * 16 + b_row_loc;
        b_base[j] = (uint32_t)(row * 128);
        b_ph[j] = (row & 7) << 4;
    }

    for (int kt = 0; kt < nk; kt++) {
        CP_WAIT(1);
        __syncthreads();
        if (kt + 2 < nk) load_tile(kt + 2);
        CP_COMMIT();
        uint32_t st = sbase + (uint32_t)(kt % STAGES) * STAGE_B;
        uint32_t stA = st, stAl = st + TILE_B, stB = st + 2*TILE_B, stBl = st + 3*TILE_B;
#pragma unroll
        for (int ks = 0; ks < 4; ks++) {
            uint32_t ah[4][4], al[4][4], bh[2][4], bl[2][4];
#pragma unroll
            for (int j = 0; j < 2; j++) {
                uint32_t off = b_base[j] + (uint32_t)((ks * 32 + b_kh) ^ b_ph[j]);
                ldsm4(bh[j], stB + off);
                ldsm4(bl[j], stBl + off);
            }
#pragma unroll
            for (int mt = 0; mt < 4; mt++) {
                uint32_t off = a_base[mt] + (uint32_t)((ks * 32 + a_kh) ^ a_ph[mt]);
                ldsm4(ah[mt], stA + off);
                ldsm4(al[mt], stAl + off);
            }
#pragma unroll
            for (int mt = 0; mt < 4; mt++)
#pragma unroll
                for (int nt = 0; nt < 4; nt++) {
                    const uint32_t* bph = &bh[nt >> 1][(nt & 1) * 2];
                    const uint32_t* bpl = &bl[nt >> 1][(nt & 1) * 2];
                    mma16816(acc[mt][nt], ah[mt], bph);
                    mma16816(acc[mt][nt], ah[mt], bpl);
                    mma16816(acc[mt][nt], al[mt], bph);
                }
        }
    }
    CP_WAIT(0);
    __syncthreads();

    float* stg = (float*)smem;
    int cr = lane >> 2, ccol = (lane & 3) * 2;
#pragma unroll
    for (int mt = 0; mt < 4; mt++)
#pragma unroll
        for (int nt = 0; nt < 4; nt++) {
            int r = wm * 64 + mt * 16 + cr;
            int cl = wn * 32 + nt * 8 + ccol;
            *(float2*)&stg[r * LDS_ + cl]       = make_float2(acc[mt][nt][0], acc[mt][nt][1]);
            *(float2*)&stg[(r + 8) * LDS_ + cl] = make_float2(acc[mt][nt][2], acc[mt][nt][3]);
        }
    __syncthreads();

#pragma unroll
    for (int i = 0; i < 16; i++) {
        int id = tid + 256 * i;
        int r = id >> 5, cc = (id & 31) * 4;
        int m = m0 + r;
        if (m < M) {
            int n = n0 + cc;
            float4 v = *(float4*)&stg[r * LDS_ + cc];
            float4 bs = *(const float4*)&bias[n];
            v.x += bs.x; v.y += bs.y; v.z += bs.z; v.w += bs.w;
            size_t idx = (size_t)m * N + n;
            if (mode == 0) {
                *(float4*)&C[idx] = v;
            } else {
                float g0 = gelu_new(v.x), g1 = gelu_new(v.y);
                float g2 = gelu_new(v.z), g3 = gelu_new(v.w);
                uint32_t h01, l01, h23, l23;
                pack_hilo(g0, g1, h01, l01);
                pack_hilo(g2, g3, h23, l23);
                *(uint2*)&Chi[idx] = make_uint2(h01, h23);
                *(uint2*)&Clo[idx] = make_uint2(l01, l23);
            }
        }
    }
}

// ---------------- GEMM 128x64 (proj / mlp_proj, residual add), 2-stage, 2 CTA/SM ----------------
#define TILE_A2 (128 * 128)   // 16384 B
#define TILE_B2 (64 * 128)    // 8192 B
#define STAGE_B2 (2 * TILE_A2 + 2 * TILE_B2)   // 49152
#define GEMM2_SMEM (2 * STAGE_B2)              // 98304
#define LDS2_ 68

__global__ void __launch_bounds__(256, 2)
gemm_mma64(const __nv_bfloat16* __restrict__ Ahi, const __nv_bfloat16* __restrict__ Alo,
           const __nv_bfloat16* __restrict__ Bhi, const __nv_bfloat16* __restrict__ Blo,
           const float* __restrict__ bias, float* __restrict__ C,
           int M, int N, int K)
{
    extern __shared__ __align__(128) char smem[];
    uint32_t sbase = smem_u32(smem);
    int tid = threadIdx.x, wid = tid >> 5, lane = tid & 31;
    int m0 = blockIdx.y * BM, n0 = blockIdx.x * 64;
    int wm = wid >> 2, wn = wid & 3;    // 2 x 4 warps; warp tile 64 x 16

    // cp.async geometry: A 4 chunks/matrix, B 2 chunks/matrix
    uint32_t soA[4], soB[2];
    unsigned ao[4], bo[2], szA[4];
#pragma unroll
    for (int i = 0; i < 4; i++) {
        int c = tid + 256 * i;
        int r = c >> 3, gb = c & 7;
        soA[i] = (uint32_t)SWZ128(r * 128 + gb * 16);
        bool ok = (m0 + r) < M;
        ao[i] = ok ? ((unsigned)(m0 + r) * (unsigned)K + gb * 8) : 0u;
        szA[i] = ok ? 16u : 0u;
    }
#pragma unroll
    for (int i = 0; i < 2; i++) {
        int c = tid + 256 * i;
        int r = c >> 3, gb = c & 7;
        soB[i] = (uint32_t)SWZ128(r * 128 + gb * 16);
        bo[i] = (unsigned)(n0 + r) * (unsigned)K + gb * 8;
    }
    const int nk = K / BK;

    auto load_tile = [&](int kt) {
        uint32_t st = sbase + (uint32_t)(kt & 1) * STAGE_B2;
        unsigned ko = (unsigned)kt * BK;
#pragma unroll
        for (int i = 0; i < 4; i++) {
            CP16(st + soA[i],           Ahi + ao[i] + ko, szA[i]);
            CP16(st + TILE_A2 + soA[i], Alo + ao[i] + ko, szA[i]);
        }
#pragma unroll
        for (int i = 0; i < 2; i++) {
            CP16(st + 2*TILE_A2 + soB[i],            Bhi + bo[i] + ko, 16u);
            CP16(st + 2*TILE_A2 + TILE_B2 + soB[i],  Blo + bo[i] + ko, 16u);
        }
    };

    int a_row_loc = ((lane >> 3) & 1) * 8 + (lane & 7);
    int a_kh = (lane >> 4) * 16;
    int b_row_loc = (lane >> 4) * 8 + (lane & 7);
    int b_kh = ((lane >> 3) & 1) * 16;

    float acc[4][2][4];
#pragma unroll
    for (int i = 0; i < 4; i++)
#pragma unroll
        for (int j = 0; j < 2; j++)
#pragma unroll
            for (int k = 0; k < 4; k++) acc[i][j][k] = 0.f;

    load_tile(0);
    CP_COMMIT();
    if (nk > 1) load_tile(1);
    CP_COMMIT();

    uint32_t a_base[4];
    int a_ph[4];
#pragma unroll
    for (int mt = 0; mt < 4; mt++) {
        int row = wm * 64 + mt * 16 + a_row_loc;
        a_base[mt] = (uint32_t)(row * 128);
        a_ph[mt] = (row & 7) << 4;
    }
    int brow = wn * 16 + b_row_loc;
    uint32_t b_base = (uint32_t)(brow * 128);
    int b_ph = (brow & 7) << 4;

    for (int kt = 0; kt < nk; kt++) {
        CP_WAIT(1);
        __syncthreads();
        uint32_t st = sbase + (uint32_t)(kt & 1) * STAGE_B2;
        uint32_t stA = st, stAl = st + TILE_A2;
        uint32_t stB = st + 2*TILE_A2, stBl = st + 2*TILE_A2 + TILE_B2;
#pragma unroll
        for (int ks = 0; ks < 4; ks++) {
            uint32_t ah[4][4], al[4][4], bh[4], bl[4];
            {
                uint32_t off = b_base + (uint32_t)((ks * 32 + b_kh) ^ b_ph);
                ldsm4(bh, stB + off);
                ldsm4(bl, stBl + off);
            }
#pragma unroll
            for (int mt = 0; mt < 4; mt++) {
                uint32_t off = a_base[mt] + (uint32_t)((ks * 32 + a_kh) ^ a_ph[mt]);
                ldsm4(ah[mt], stA + off);
                ldsm4(al[mt], stAl + off);
            }
#pragma unroll
            for (int mt = 0; mt < 4; mt++)
#pragma unroll
                for (int nt = 0; nt < 2; nt++) {
                    const uint32_t* bph = &bh[nt * 2];
                    const uint32_t* bpl = &bl[nt * 2];
                    mma16816(acc[mt][nt], ah[mt], bph);
                    mma16816(acc[mt][nt], ah[mt], bpl);
                    mma16816(acc[mt][nt], al[mt], bph);
                }
        }
        __syncthreads();
        if (kt + 2 < nk) load_tile(kt + 2);
        CP_COMMIT();
    }
    CP_WAIT(0);
    __syncthreads();

    float* stg = (float*)smem;
    int cr = lane >> 2, ccol = (lane & 3) * 2;
#pragma unroll
    for (int mt = 0; mt < 4; mt++)
#pragma unroll
        for (int nt = 0; nt < 2; nt++) {
            int r = wm * 64 + mt * 16 + cr;
            int cl = wn * 16 + nt * 8 + ccol;
            *(float2*)&stg[r * LDS2_ + cl]       = make_float2(acc[mt][nt][0], acc[mt][nt][1]);
            *(float2*)&stg[(r + 8) * LDS2_ + cl] = make_float2(acc[mt][nt][2], acc[mt][nt][3]);
        }
    __syncthreads();

#pragma unroll
    for (int i = 0; i < 8; i++) {
        int id = tid + 256 * i;
        int r = id >> 4, cc = (id & 15) * 4;
        int m = m0 + r;
        if (m < M) {
            int n = n0 + cc;
            float4 v = *(float4*)&stg[r * LDS2_ + cc];
            float4 bs = *(const float4*)&bias[n];
            size_t idx = (size_t)m * N + n;
            float4 c0 = *(float4*)&C[idx];
            c0.x += v.x + bs.x; c0.y += v.y + bs.y;
            c0.z += v.z + bs.z; c0.w += v.w + bs.w;
            *(float4*)&C[idx] = c0;
        }
    }
}

// ---------------- flash attention (split-bf16 mma) ----------------
#define AKHI 0
#define AKLO 38912
#define AVHI 77824
#define AVLO 116736
#define ATTN_SMEM 155648

__global__ void __launch_bounds__(256)
attn_flash(const float* __restrict__ qkv,
           __nv_bfloat16* __restrict__ ohi, __nv_bfloat16* __restrict__ olo)
{
    extern __shared__ __align__(128) char asmem[];
    uint32_t sb = smem_u32(asmem);
    int tid = threadIdx.x;
    int bh = blockIdx.x, b = bh >> 4, hd = bh & 15;
    const float* base = qkv + (size_t)b * LSEQ * 3072;
    int hoff = hd * 64;

    for (int idx = tid; idx < 304 * 64; idx += 256) {
        int j = idx >> 6, d = idx & 63;
        float kv = 0.f, vv = 0.f;
        if (j < LSEQ) {
            kv = base[(size_t)j * 3072 + 1024 + hoff + d];
            vv = base[(size_t)j * 3072 + 2048 + hoff + d];
        }
        uint32_t off = (uint32_t)SWZ128(j * 128 + d * 2);
        __nv_bfloat16 kh = __float2bfloat16(kv);
        *(__nv_bfloat16*)(asmem + AKHI + off) = kh;
        *(__nv_bfloat16*)(asmem + AKLO + off) = __float2bfloat16(kv - __bfloat162float(kh));
        __nv_bfloat16 vh = __float2bfloat16(vv);
        *(__nv_bfloat16*)(asmem + AVHI + off) = vh;
        *(__nv_bfloat16*)(asmem + AVLO + off) = __float2bfloat16(vv - __bfloat162float(vh));
    }
    __syncthreads();

    int w = tid >> 5, lane = tid & 31;
    int g = lane >> 2, t4 = lane & 3;
    int kb_row = (lane >> 4) * 8 + (lane & 7);
    int kb_kb  = ((lane >> 3) & 1) * 16;
    int vb_row = ((lane >> 3) & 1) * 8 + (lane & 7);
    int vb_nb  = (lane >> 4) * 16;

    for (int qi = 0; qi < 3; qi++) {
        int qt = (qi == 0) ? (18 - w) : ((qi == 1) ? (3 + w) : ((w < 3) ? (2 - w) : -1));
        if (qt < 0) continue;
        int q0 = qt * 16;

        uint32_t qh[4][4], ql[4][4];
        int r1 = q0 + g;       int r1c = r1 < LSEQ ? r1 : LSEQ - 1;
        int r2 = r1 + 8;       int r2c = r2 < LSEQ ? r2 : LSEQ - 1;
        const float* q1p = base + (size_t)r1c * 3072 + hoff;
        const float* q2p = base + (size_t)r2c * 3072 + hoff;
#pragma unroll
        for (int kt = 0; kt < 4; kt++) {
            int c0 = kt * 16 + 2 * t4;
            float2 x0 = *(const float2*)(q1p + c0);
            float2 x1 = *(const float2*)(q2p + c0);
            float2 x2 = *(const float2*)(q1p + c0 + 8);
            float2 x3 = *(const float2*)(q2p + c0 + 8);
            pack_hilo(x0.x, x0.y, qh[kt][0], ql[kt][0]);
            pack_hilo(x1.x, x1.y, qh[kt][1], ql[kt][1]);
            pack_hilo(x2.x, x2.y, qh[kt][2], ql[kt][2]);
            pack_hilo(x3.x, x3.y, qh[kt][3], ql[kt][3]);
        }

        float m0 = -1e30f, m1 = -1e30f, l0 = 0.f, l1 = 0.f;
        float o[8][4];
#pragma unroll
        for (int i = 0; i < 8; i++)
#pragma unroll
            for (int k = 0; k < 4; k++) o[i][k] = 0.f;

        for (int jt = 0; jt <= qt; jt++) {
            float s[2][4] = {{0,0,0,0},{0,0,0,0}};
#pragma unroll
            for (int kt = 0; kt < 4; kt++) {
                int row = jt * 16 + kb_row;
                uint32_t off = (uint32_t)(row * 128 + ((kt * 32 + kb_kb) ^ ((row & 7) << 4)));
                uint32_t kh4[4], kl4[4];
                ldsm4(kh4, sb + AKHI + off);
                ldsm4(kl4, sb + AKLO + off);
#pragma unroll
                for (int nt = 0; nt < 2; nt++) {
                    mma16816(s[nt], qh[kt], &kh4[nt*2]);
                    mma16816(s[nt], qh[kt], &kl4[nt*2]);
                    mma16816(s[nt], ql[kt], &kh4[nt*2]);
                }
            }
            int qr1 = q0 + g, qr2 = qr1 + 8;
#pragma unroll
            for (int nt = 0; nt < 2; nt++) {
                int jc = jt * 16 + nt * 8 + 2 * t4;
                s[nt][0] = (jc     <= qr1) ? s[nt][0] * 0.125f : -1e30f;
                s[nt][1] = (jc + 1 <= qr1) ? s[nt][1] * 0.125f : -1e30f;
                s[nt][2] = (jc     <= qr2) ? s[nt][2] * 0.125f : -1e30f;
                s[nt][3] = (jc + 1 <= qr2) ? s[nt][3] * 0.125f : -1e30f;
            }
            float tm0 = fmaxf(fmaxf(s[0][0], s[0][1]), fmaxf(s[1][0], s[1][1]));
            float tm1 = fmaxf(fmaxf(s[0][2], s[0][3]), fmaxf(s[1][2], s[1][3]));
            tm0 = fmaxf(tm0, __shfl_xor_sync(0xFFFFFFFFu, tm0, 1));
            tm0 = fmaxf(tm0, __shfl_xor_sync(0xFFFFFFFFu, tm0, 2));
            tm1 = fmaxf(tm1, __shfl_xor_sync(0xFFFFFFFFu, tm1, 1));
            tm1 = fmaxf(tm1, __shfl_xor_sync(0xFFFFFFFFu, tm1, 2));
            float mn0 = fmaxf(m0, tm0), mn1 = fmaxf(m1, tm1);
            float sc0 = expf(m0 - mn0), sc1 = expf(m1 - mn1);
            m0 = mn0; m1 = mn1;
            float p[2][4];
#pragma unroll
            for (int nt = 0; nt < 2; nt++) {
                p[nt][0] = expf(s[nt][0] - mn0);
                p[nt][1] = expf(s[nt][1] - mn0);
                p[nt][2] = expf(s[nt][2] - mn1);
                p[nt][3] = expf(s[nt][3] - mn1);
            }
            float ts0 = p[0][0] + p[0][1] + p[1][0] + p[1][1];
            float ts1 = p[0][2] + p[0][3] + p[1][2] + p[1][3];
            ts0 += __shfl_xor_sync(0xFFFFFFFFu, ts0, 1);
            ts0 += __shfl_xor_sync(0xFFFFFFFFu, ts0, 2);
            ts1 += __shfl_xor_sync(0xFFFFFFFFu, ts1, 1);
            ts1 += __shfl_xor_sync(0xFFFFFFFFu, ts1, 2);
            l0 = l0 * sc0 + ts0;
            l1 = l1 * sc1 + ts1;
#pragma unroll
            for (int nt = 0; nt < 8; nt++) {
                o[nt][0] *= sc0; o[nt][1] *= sc0; o[nt][2] *= sc1; o[nt][3] *= sc1;
            }
            uint32_t pah[4], pal[4];
            pack_hilo(p[0][0], p[0][1], pah[0], pal[0]);
            pack_hilo(p[0][2], p[0][3], pah[1], pal[1]);
            pack_hilo(p[1][0], p[1][1], pah[2], pal[2]);
            pack_hilo(p[1][2], p[1][3], pah[3], pal[3]);
#pragma unroll
            for (int dt = 0; dt < 4; dt++) {
                int row = jt * 16 + vb_row;
                uint32_t off = (uint32_t)(row * 128 + ((dt * 32 + vb_nb) ^ ((row & 7) << 4)));
                uint32_t vh4[4], vl4[4];
                ldsm4t(vh4, sb + AVHI + off);
                ldsm4t(vl4, sb + AVLO + off);
#pragma unroll
                for (int su = 0; su < 2; su++) {
                    int nt = dt * 2 + su;
                    mma16816(o[nt], pah, &vh4[su*2]);
                    mma16816(o[nt], pah, &vl4[su*2]);
                    mma16816(o[nt], pal, &vh4[su*2]);
                }
            }
        }
        float inv0 = 1.f / l0, inv1 = 1.f / l1;
        int row1 = q0 + g, row2 = row1 + 8;
#pragma unroll
        for (int nt = 0; nt < 8; nt++) {
            int col = nt * 8 + 2 * t4;
            if (row1 < LSEQ) {
                uint32_t hp, lp;
                pack_hilo(o[nt][0] * inv0, o[nt][1] * inv0, hp, lp);
                size_t idx = (size_t)(b * LSEQ + row1) * D_ + hoff + col;
                *(uint32_t*)&ohi[idx] = hp;
                *(uint32_t*)&olo[idx] = lp;
            }
            if (row2 < LSEQ) {
                uint32_t hp, lp;
                pack_hilo(o[nt][2] * inv1, o[nt][3] * inv1, hp, lp);
                size_t idx = (size_t)(b * LSEQ + row2) * D_ + hoff + col;
                *(uint32_t*)&ohi[idx] = hp;
                *(uint32_t*)&olo[idx] = lp;
            }
        }
    }
}

// ---------------- loss ----------------
__global__ void loss_kernel(const float* __restrict__ h,
                            const float* __restrict__ g,
                            const float* __restrict__ beta,
                            const float* __restrict__ pw,
                            const float* __restrict__ pb,
                            const int* __restrict__ actions,
                            const int* __restrict__ tact,
                            float* __restrict__ partial)
{
    __shared__ float red[4];
    __shared__ float lred[5][4];
    int idx = blockIdx.x;
    int b = idx / (CTX_ + 1), t = idx % (CTX_ + 1);
    const float* x = h + (size_t)(b * LSEQ + 3 * t) * D_;
    int tid = threadIdx.x, lane = tid & 31, w = tid >> 5;

    float v[8];
    float s = 0.f;
#pragma unroll
    for (int i = 0; i < 8; i++) { v[i] = x[tid + 128 * i]; s += v[i]; }
#pragma unroll
    for (int o = 16; o; o >>= 1) s += __shfl_xor_sync(0xFFFFFFFFu, s, o);
    if (lane == 0) red[w] = s;
    __syncthreads();
    float mean = (red[0] + red[1] + red[2] + red[3]) * (1.f / 1024.f);
    __syncthreads();
    float s2 = 0.f;
#pragma unroll
    for (int i = 0; i < 8; i++) { float d = v[i] - mean; s2 += d * d; }
#pragma unroll
    for (int o = 16; o; o >>= 1) s2 += __shfl_xor_sync(0xFFFFFFFFu, s2, o);
    if (lane == 0) red[w] = s2;
    __syncthreads();
    float var = (red[0] + red[1] + red[2] + red[3]) * (1.f / 1024.f);
    float inv = 1.f / sqrtf(var + 1e-5f);

    float acc[NA_] = {0.f, 0.f, 0.f, 0.f, 0.f};
#pragma unroll
    for (int i = 0; i < 8; i++) {
        int c = tid + 128 * i;
        float xn = (v[i] - mean) * inv * g[c] + beta[c];
#pragma unroll
        for (int a = 0; a < NA_; a++)
            acc[a] = fmaf(xn, pw[c * NA_ + a], acc[a]);
    }
#pragma unroll
    for (int a = 0; a < NA_; a++) {
        float tv = acc[a];
#pragma unroll
        for (int o = 16; o; o >>= 1) tv += __shfl_xor_sync(0xFFFFFFFFu, tv, o);
        if (lane == 0) lred[a][w] = tv;
    }
    __syncthreads();
    if (tid == 0) {
        float logit[NA_];
#pragma unroll
        for (int a = 0; a < NA_; a++)
            logit[a] = lred[a][0] + lred[a][1] + lred[a][2] + lred[a][3] + pb[a];
        int target = (t < CTX_) ? actions[b * CTX_ + t] : tact[b];
        float mx = logit[0]; int am = 0;
#pragma unroll
        for (int a = 1; a < NA_; a++) if (logit[a] > mx) { mx = logit[a]; am = a; }
        float se = 0.f;
#pragma unroll
        for (int a = 0; a < NA_; a++) se += expf(logit[a] - mx);
        float lse = mx + logf(se);
        float sl = 0.f;
#pragma unroll
        for (int a = 0; a < NA_; a++) sl += (logit[a] - lse);
        float nll = -(logit[target] - lse);
        float smooth = -sl * (1.f / NA_);
        partial[2 * idx]     = 0.9f * nll + 0.1f * smooth;
        partial[2 * idx + 1] = (am == target) ? 1.f : 0.f;
    }
}

__global__ void reduce_kernel(const float* __restrict__ partial, float* __restrict__ out)
{
    __shared__ float rl[8], ra[8];
    int tid = threadIdx.x, lane = tid & 31, w = tid >> 5;
    float l = 0.f, a = 0.f;
    for (int i = tid; i < NPOS; i += 256) {
        l += partial[2 * i];
        a += partial[2 * i + 1];
    }
#pragma unroll
    for (int o = 16; o; o >>= 1) {
        l += __shfl_xor_sync(0xFFFFFFFFu, l, o);
        a += __shfl_xor_sync(0xFFFFFFFFu, a, o);
    }
    if (lane == 0) { rl[w] = l; ra[w] = a; }
    __syncthreads();
    if (tid == 0) {
        float L = 0.f, A = 0.f;
#pragma unroll
        for (int i = 0; i < 8; i++) { L += rl[i]; A += ra[i]; }
        out[0] = L * (1.f / NPOS);
        out[1] = A * (1.f / NPOS);
    }
}

// ---------------- host ----------------
static inline void launch_gemm(const __nv_bfloat16* Ahi, const __nv_bfloat16* Alo,
                               const __nv_bfloat16* Bhi, const __nv_bfloat16* Blo,
                               const float* bias, float* C,
                               __nv_bfloat16* Chi, __nv_bfloat16* Clo,
                               int M, int N, int K, int mode)
{
    dim3 grid(N / BN, (M + BM - 1) / BM);
    gemm_mma<<<grid, 256, GEMM_SMEM>>>(Ahi, Alo, Bhi, Blo, bias, C, Chi, Clo, M, N, K, mode);
}

static inline void launch_gemm64(const __nv_bfloat16* Ahi, const __nv_bfloat16* Alo,
                                 const __nv_bfloat16* Bhi, const __nv_bfloat16* Blo,
                                 const float* bias, float* C, int M, int N, int K)
{
    dim3 grid(N / 64, (M + BM - 1) / BM);
    gemm_mma64<<<grid, 256, GEMM2_SMEM>>>(Ahi, Alo, Bhi, Blo, bias, C, M, N, K);
}

extern "C" void kernel_launch(void* const* d_in, const int* in_sizes, int n_in,
                              void* d_out, int out_size)
{
    const int*   states  = (const int*)  d_in[0];
    const int*   actions = (const int*)  d_in[1];
    const float* rewards = (const float*)d_in[2];
    const int*   qstates = (const int*)  d_in[3];
    const int*   tact    = (const int*)  d_in[4];
    const float* wpe     = (const float*)d_in[5];
    const float* e_state = (const float*)d_in[6];
    const float* e_act   = (const float*)d_in[7];
    const float* erw     = (const float*)d_in[8];
    const float* erb     = (const float*)d_in[9];
    const float* ln1g    = (const float*)d_in[10];
    const float* ln1b    = (const float*)d_in[11];
    const float* attnw   = (const float*)d_in[12];
    const float* attnb   = (const float*)d_in[13];
    const float* apw     = (const float*)d_in[14];
    const float* apb     = (const float*)d_in[15];
    const float* ln2g    = (const float*)d_in[16];
    const float* ln2b    = (const float*)d_in[17];
    const float* fcw     = (const float*)d_in[18];
    const float* fcb     = (const float*)d_in[19];
    const float* mpw     = (const float*)d_in[20];
    const float* mpb     = (const float*)d_in[21];
    const float* lnfg    = (const float*)d_in[22];
    const float* lnfb    = (const float*)d_in[23];
    const float* predw   = (const float*)d_in[24];
    const float* predb   = (const float*)d_in[25];
    float* out = (float*)d_out;

    float *h, *qkv, *partial;
    __nv_bfloat16 *xhi, *xlo, *ahi, *alo, *fhi, *flo, *whi, *wlo;
    cudaGetSymbolAddress((void**)&h,    g_h);
    cudaGetSymbolAddress((void**)&qkv,  g_qkv);
    cudaGetSymbolAddress((void**)&partial, g_partial);
    cudaGetSymbolAddress((void**)&xhi,  g_xhi);
    cudaGetSymbolAddress((void**)&xlo,  g_xlo);
    cudaGetSymbolAddress((void**)&ahi,  g_ahi);
    cudaGetSymbolAddress((void**)&alo,  g_alo);
    cudaGetSymbolAddress((void**)&fhi,  g_fhi);
    cudaGetSymbolAddress((void**)&flo,  g_flo);
    cudaGetSymbolAddress((void**)&whi,  g_whi);
    cudaGetSymbolAddress((void**)&wlo,  g_wlo);

    cudaFuncSetAttribute(attn_flash, cudaFuncAttributeMaxDynamicSharedMemorySize, ATTN_SMEM);
    cudaFuncSetAttribute(gemm_mma, cudaFuncAttributeMaxDynamicSharedMemorySize, GEMM_SMEM);
    cudaFuncSetAttribute(gemm_mma64, cudaFuncAttributeMaxDynamicSharedMemorySize, GEMM2_SMEM);

    const size_t WPL = 12582912;
    const size_t OFF_QKV = 0, OFF_PROJ = 3145728, OFF_FC = 4194304, OFF_MP = 8388608;
    wprep_kernel<<<dim3(3 * D_ / 32, D_ / 32, NL_), dim3(32, 8)>>>(
        attnw, whi + OFF_QKV, wlo + OFF_QKV, D_, 3 * D_, (size_t)D_ * 3 * D_, WPL);
    wprep_kernel<<<dim3(D_ / 32, D_ / 32, NL_), dim3(32, 8)>>>(
        apw, whi + OFF_PROJ, wlo + OFF_PROJ, D_, D_, (size_t)D_ * D_, WPL);
    wprep_kernel<<<dim3(DFF_ / 32, D_ / 32, NL_), dim3(32, 8)>>>(
        fcw, whi + OFF_FC, wlo + OFF_FC, D_, DFF_, (size_t)D_ * DFF_, WPL);
    wprep_kernel<<<dim3(D_ / 32, DFF_ / 32, NL_), dim3(32, 8)>>>(
        mpw, whi + OFF_MP, wlo + OFF_MP, DFF_, D_, (size_t)DFF_ * D_, WPL);

    embed_kernel<<<NTOK, 256>>>(states, actions, rewards, qstates, wpe,
                                e_state, e_act, erw, erb, h);

    for (int i = 0; i < NL_; i++) {
        size_t off = (size_t)i * WPL;
        ln_kernel<<<NTOK, 256>>>(h, xhi, xlo, ln1g + i * D_, ln1b + i * D_);
        launch_gemm(xhi, xlo, whi + off + OFF_QKV, wlo + off + OFF_QKV,
                    attnb + i * 3 * D_, qkv, nullptr, nullptr, NTOK, 3 * D_, D_, 0);
        attn_flash<<<B_ * H_, 256, ATTN_SMEM>>>(qkv, ahi, alo);
        launch_gemm64(ahi, alo, whi + off + OFF_PROJ, wlo + off + OFF_PROJ,
                      apb + i * D_, h, NTOK, D_, D_);
        ln_kernel<<<NTOK, 256>>>(h, xhi, xlo, ln2g + i * D_, ln2b + i * D_);
        launch_gemm(xhi, xlo, whi + off + OFF_FC, wlo + off + OFF_FC,
                    fcb + i * DFF_, nullptr, fhi, flo, NTOK, DFF_, D_, 1);
        launch_gemm64(fhi, flo, whi + off + OFF_MP, wlo + off + OFF_MP,
                      mpb + i * D_, h, NTOK, D_, DFF_);
    }

    loss_kernel<<<NPOS, 128>>>(h, lnfg, lnfb, predw, predb, actions, tact, partial);
    reduce_kernel<<<1, 256>>>(partial, out);
}

// round 10
// speedup vs baseline: 3.8614x; 1.0365x over previous
#include <cuda_runtime.h>
#include <cuda_bf16.h>
#include <math.h>
#include <stdint.h>

#define B_    16
#define CTX_  100
#define LSEQ  301
#define D_    1024
#define H_    16
#define HD_   64
#define NL_   4
#define DFF_  4096
#define GRID_ 9
#define NA_   5
#define NTOK  (B_*LSEQ)
#define NPOS  (B_*(CTX_+1))
#define WPOOL 50331648

__device__ float g_h   [NTOK * D_];
__device__ float g_qkv [NTOK * 3 * D_];
__device__ __nv_bfloat16 g_xhi[NTOK * D_];
__device__ __nv_bfloat16 g_xlo[NTOK * D_];
__device__ __nv_bfloat16 g_ahi[NTOK * D_];
__device__ __nv_bfloat16 g_alo[NTOK * D_];
__device__ __nv_bfloat16 g_fhi[NTOK * DFF_];
__device__ __nv_bfloat16 g_flo[NTOK * DFF_];
__device__ __nv_bfloat16 g_whi[WPOOL];
__device__ __nv_bfloat16 g_wlo[WPOOL];
__device__ float g_partial[NPOS * 2];

#define CP16(d, s, z)  asm volatile("cp.async.cg.shared.global [%0], [%1], 16, %2;" :: "r"(d), "l"(s), "r"(z) : "memory")
#define CP_COMMIT()    asm volatile("cp.async.commit_group;" ::: "memory")
#define CP_WAIT(n)     asm volatile("cp.async.wait_group %0;" :: "n"(n) : "memory")
#define SWZ128(o) ((o) ^ (((o) >> 3) & 0x70))

__device__ __forceinline__ uint32_t smem_u32(const void* p) {
    uint32_t a;
    asm("{ .reg .u64 t; cvta.to.shared.u64 t, %1; cvt.u32.u64 %0, t; }" : "=r"(a) : "l"(p));
    return a;
}
__device__ __forceinline__ void ldsm4(uint32_t* r, uint32_t addr) {
    asm volatile("ldmatrix.sync.aligned.m8n8.x4.shared.b16 {%0,%1,%2,%3}, [%4];"
                 : "=r"(r[0]), "=r"(r[1]), "=r"(r[2]), "=r"(r[3]) : "r"(addr));
}
__device__ __forceinline__ void ldsm4t(uint32_t* r, uint32_t addr) {
    asm volatile("ldmatrix.sync.aligned.m8n8.x4.trans.shared.b16 {%0,%1,%2,%3}, [%4];"
                 : "=r"(r[0]), "=r"(r[1]), "=r"(r[2]), "=r"(r[3]) : "r"(addr));
}
__device__ __forceinline__ void mma16816(float* c, const uint32_t* a, const uint32_t* b) {
    asm volatile("mma.sync.aligned.m16n8k16.row.col.f32.bf16.bf16.f32 "
                 "{%0,%1,%2,%3}, {%4,%5,%6,%7}, {%8,%9}, {%0,%1,%2,%3};"
                 : "+f"(c[0]), "+f"(c[1]), "+f"(c[2]), "+f"(c[3])
                 : "r"(a[0]), "r"(a[1]), "r"(a[2]), "r"(a[3]), "r"(b[0]), "r"(b[1]));
}
__device__ __forceinline__ void pack_hilo(float x, float y, uint32_t& hi, uint32_t& lo) {
    __nv_bfloat16 xh = __float2bfloat16(x), yh = __float2bfloat16(y);
    __nv_bfloat162 hv; hv.x = xh; hv.y = yh;
    __nv_bfloat162 lv;
    lv.x = __float2bfloat16(x - __bfloat162float(xh));
    lv.y = __float2bfloat16(y - __bfloat162float(yh));
    hi = *(uint32_t*)&hv; lo = *(uint32_t*)&lv;
}

__device__ __forceinline__ float gelu_new(float xv) {
    float t = tanhf(0.7978845608028654f * (xv + 0.044715f * xv * xv * xv));
    return 0.5f * xv * (1.f + t);
}

// ---------------- embedding ----------------
__global__ void embed_kernel(const int* __restrict__ states,
                             const int* __restrict__ actions,
                             const float* __restrict__ rewards,
                             const int* __restrict__ qstates,
                             const float* __restrict__ wpe,
                             const float* __restrict__ e_state,
                             const float* __restrict__ e_act,
                             const float* __restrict__ erw,
                             const float* __restrict__ erb,
                             float* __restrict__ h)
{
    int tok = blockIdx.x;
    int b = tok / LSEQ, p = tok % LSEQ;
    const float* src = nullptr;
    float r = 0.f;
    int type = 0;
    if (p == 3 * CTX_) {
        int q = qstates[b * 2] * GRID_ + qstates[b * 2 + 1];
        src = e_state + (size_t)q * D_;
    } else {
        int t = p / 3, m = p % 3;
        if (m == 0) {
            int sid = states[(b * CTX_ + t) * 2] * GRID_ + states[(b * CTX_ + t) * 2 + 1];
            src = e_state + (size_t)sid * D_;
        } else if (m == 1) {
            src = e_act + (size_t)actions[b * CTX_ + t] * D_;
        } else {
            r = rewards[b * CTX_ + t];
            type = 1;
        }
    }
    for (int c = threadIdx.x; c < D_; c += blockDim.x) {
        float v = (type == 0) ? src[c] : fmaf(r, erw[c], erb[c]);
        h[(size_t)tok * D_ + c] = v + wpe[(size_t)p * D_ + c];
    }
}

// ---------------- weight transpose + split (batched over layers via z) ----------------
__global__ void wprep_kernel(const float* __restrict__ W,
                             __nv_bfloat16* __restrict__ Thi,
                             __nv_bfloat16* __restrict__ Tlo,
                             int K, int N, size_t sstride, size_t dstride)
{
    __shared__ float t[32][33];
    const float* Wz = W + (size_t)blockIdx.z * sstride;
    __nv_bfloat16* Th = Thi + (size_t)blockIdx.z * dstride;
    __nv_bfloat16* Tl = Tlo + (size_t)blockIdx.z * dstride;
    int n = blockIdx.x * 32 + threadIdx.x;
    int k0 = blockIdx.y * 32;
#pragma unroll
    for (int r = 0; r < 32; r += 8)
        t[threadIdx.y + r][threadIdx.x] = Wz[(size_t)(k0 + threadIdx.y + r) * N + n];
    __syncthreads();
    int k = k0 + threadIdx.x;
#pragma unroll
    for (int r = 0; r < 32; r += 8) {
        int nn = blockIdx.x * 32 + threadIdx.y + r;
        float v = t[threadIdx.x][threadIdx.y + r];
        __nv_bfloat16 hi = __float2bfloat16(v);
        Th[(size_t)nn * K + k] = hi;
        Tl[(size_t)nn * K + k] = __float2bfloat16(v - __bfloat162float(hi));
    }
}

// ---------------- LayerNorm -> hi/lo ----------------
__global__ void ln_kernel(const float* __restrict__ in,
                          __nv_bfloat16* __restrict__ ohi,
                          __nv_bfloat16* __restrict__ olo,
                          const float* __restrict__ g, const float* __restrict__ beta)
{
    __shared__ float red[8];
    int row = blockIdx.x;
    const float* x = in + (size_t)row * D_;
    int tid = threadIdx.x;
    float v[4];
    float s = 0.f;
#pragma unroll
    for (int i = 0; i < 4; i++) { v[i] = x[tid + 256 * i]; s += v[i]; }
#pragma unroll
    for (int o = 16; o; o >>= 1) s += __shfl_xor_sync(0xFFFFFFFFu, s, o);
    if ((tid & 31) == 0) red[tid >> 5] = s;
    __syncthreads();
    float mean = (red[0]+red[1]+red[2]+red[3]+red[4]+red[5]+red[6]+red[7]) * (1.f/1024.f);
    __syncthreads();
    float s2 = 0.f;
#pragma unroll
    for (int i = 0; i < 4; i++) { float d = v[i] - mean; s2 += d * d; }
#pragma unroll
    for (int o = 16; o; o >>= 1) s2 += __shfl_xor_sync(0xFFFFFFFFu, s2, o);
    if ((tid & 31) == 0) red[tid >> 5] = s2;
    __syncthreads();
    float var = (red[0]+red[1]+red[2]+red[3]+red[4]+red[5]+red[6]+red[7]) * (1.f/1024.f);
    float inv = 1.f / sqrtf(var + 1e-5f);
#pragma unroll
    for (int i = 0; i < 4; i++) {
        int c = tid + 256 * i;
        float y = (v[i] - mean) * inv * g[c] + beta[c];
        __nv_bfloat16 hi = __float2bfloat16(y);
        ohi[(size_t)row * D_ + c] = hi;
        olo[(size_t)row * D_ + c] = __float2bfloat16(y - __bfloat162float(hi));
    }
}

// ---------------- GEMM 128x64, 2-stage, 2 CTA/SM (all GEMMs) ----------------
// mode 0: C = v (fp32)  1: gelu(v) -> Chi/Clo  2: C += v
#define BM 128
#define BK 64
#define TILE_A2 (128 * 128)   // 16384 B
#define TILE_B2 (64 * 128)    // 8192 B
#define STAGE_B2 (2 * TILE_A2 + 2 * TILE_B2)   // 49152
#define GEMM2_SMEM (2 * STAGE_B2)              // 98304
#define LDS2_ 68

__global__ void __launch_bounds__(256, 2)
gemm_mma64(const __nv_bfloat16* __restrict__ Ahi, const __nv_bfloat16* __restrict__ Alo,
           const __nv_bfloat16* __restrict__ Bhi, const __nv_bfloat16* __restrict__ Blo,
           const float* __restrict__ bias, float* __restrict__ C,
           __nv_bfloat16* __restrict__ Chi, __nv_bfloat16* __restrict__ Clo,
           int M, int N, int K, int mode)
{
    extern __shared__ __align__(128) char smem[];
    uint32_t sbase = smem_u32(smem);
    int tid = threadIdx.x, wid = tid >> 5, lane = tid & 31;
    int m0 = blockIdx.y * BM, n0 = blockIdx.x * 64;
    int wm = wid >> 2, wn = wid & 3;    // 2 x 4 warps; warp tile 64 x 16

    uint32_t soA[4], soB[2];
    unsigned ao[4], bo[2], szA[4];
#pragma unroll
    for (int i = 0; i < 4; i++) {
        int c = tid + 256 * i;
        int r = c >> 3, gb = c & 7;
        soA[i] = (uint32_t)SWZ128(r * 128 + gb * 16);
        bool ok = (m0 + r) < M;
        ao[i] = ok ? ((unsigned)(m0 + r) * (unsigned)K + gb * 8) : 0u;
        szA[i] = ok ? 16u : 0u;
    }
#pragma unroll
    for (int i = 0; i < 2; i++) {
        int c = tid + 256 * i;
        int r = c >> 3, gb = c & 7;
        soB[i] = (uint32_t)SWZ128(r * 128 + gb * 16);
        bo[i] = (unsigned)(n0 + r) * (unsigned)K + gb * 8;
    }
    const int nk = K / BK;

    auto load_tile = [&](int kt) {
        uint32_t st = sbase + (uint32_t)(kt & 1) * STAGE_B2;
        unsigned ko = (unsigned)kt * BK;
#pragma unroll
        for (int i = 0; i < 4; i++) {
            CP16(st + soA[i],           Ahi + ao[i] + ko, szA[i]);
            CP16(st + TILE_A2 + soA[i], Alo + ao[i] + ko, szA[i]);
        }
#pragma unroll
        for (int i = 0; i < 2; i++) {
            CP16(st + 2*TILE_A2 + soB[i],            Bhi + bo[i] + ko, 16u);
            CP16(st + 2*TILE_A2 + TILE_B2 + soB[i],  Blo + bo[i] + ko, 16u);
        }
    };

    int a_row_loc = ((lane >> 3) & 1) * 8 + (lane & 7);
    int a_kh = (lane >> 4) * 16;
    int b_row_loc = (lane >> 4) * 8 + (lane & 7);
    int b_kh = ((lane >> 3) & 1) * 16;

    float acc[4][2][4];
#pragma unroll
    for (int i = 0; i < 4; i++)
#pragma unroll
        for (int j = 0; j < 2; j++)
#pragma unroll
            for (int k = 0; k < 4; k++) acc[i][j][k] = 0.f;

    load_tile(0);
    CP_COMMIT();
    if (nk > 1) load_tile(1);
    CP_COMMIT();

    uint32_t a_base[4];
    int a_ph[4];
#pragma unroll
    for (int mt = 0; mt < 4; mt++) {
        int row = wm * 64 + mt * 16 + a_row_loc;
        a_base[mt] = (uint32_t)(row * 128);
        a_ph[mt] = (row & 7) << 4;
    }
    int brow = wn * 16 + b_row_loc;
    uint32_t b_base = (uint32_t)(brow * 128);
    int b_ph = (brow & 7) << 4;

    for (int kt = 0; kt < nk; kt++) {
        CP_WAIT(1);
        __syncthreads();
        uint32_t st = sbase + (uint32_t)(kt & 1) * STAGE_B2;
        uint32_t stA = st, stAl = st + TILE_A2;
        uint32_t stB = st + 2*TILE_A2, stBl = st + 2*TILE_A2 + TILE_B2;
#pragma unroll
        for (int ks = 0; ks < 4; ks++) {
            uint32_t ah[4][4], al[4][4], bh[4], bl[4];
            {
                uint32_t off = b_base + (uint32_t)((ks * 32 + b_kh) ^ b_ph);
                ldsm4(bh, stB + off);
                ldsm4(bl, stBl + off);
            }
#pragma unroll
            for (int mt = 0; mt < 4; mt++) {
                uint32_t off = a_base[mt] + (uint32_t)((ks * 32 + a_kh) ^ a_ph[mt]);
                ldsm4(ah[mt], stA + off);
                ldsm4(al[mt], stAl + off);
            }
#pragma unroll
            for (int mt = 0; mt < 4; mt++)
#pragma unroll
                for (int nt = 0; nt < 2; nt++) {
                    const uint32_t* bph = &bh[nt * 2];
                    const uint32_t* bpl = &bl[nt * 2];
                    mma16816(acc[mt][nt], ah[mt], bph);
                    mma16816(acc[mt][nt], ah[mt], bpl);
                    mma16816(acc[mt][nt], al[mt], bph);
                }
        }
        __syncthreads();
        if (kt + 2 < nk) load_tile(kt + 2);
        CP_COMMIT();
    }
    CP_WAIT(0);
    __syncthreads();

    float* stg = (float*)smem;
    int cr = lane >> 2, ccol = (lane & 3) * 2;
#pragma unroll
    for (int mt = 0; mt < 4; mt++)
#pragma unroll
        for (int nt = 0; nt < 2; nt++) {
            int r = wm * 64 + mt * 16 + cr;
            int cl = wn * 16 + nt * 8 + ccol;
            *(float2*)&stg[r * LDS2_ + cl]       = make_float2(acc[mt][nt][0], acc[mt][nt][1]);
            *(float2*)&stg[(r + 8) * LDS2_ + cl] = make_float2(acc[mt][nt][2], acc[mt][nt][3]);
        }
    __syncthreads();

#pragma unroll
    for (int i = 0; i < 8; i++) {
        int id = tid + 256 * i;
        int r = id >> 4, cc = (id & 15) * 4;
        int m = m0 + r;
        if (m < M) {
            int n = n0 + cc;
            float4 v = *(float4*)&stg[r * LDS2_ + cc];
            float4 bs = *(const float4*)&bias[n];
            v.x += bs.x; v.y += bs.y; v.z += bs.z; v.w += bs.w;
            size_t idx = (size_t)m * N + n;
            if (mode == 0) {
                *(float4*)&C[idx] = v;
            } else if (mode == 1) {
                float g0 = gelu_new(v.x), g1 = gelu_new(v.y);
                float g2 = gelu_new(v.z), g3 = gelu_new(v.w);
                uint32_t h01, l01, h23, l23;
                pack_hilo(g0, g1, h01, l01);
                pack_hilo(g2, g3, h23, l23);
                *(uint2*)&Chi[idx] = make_uint2(h01, h23);
                *(uint2*)&Clo[idx] = make_uint2(l01, l23);
            } else {
                float4 c0 = *(float4*)&C[idx];
                c0.x += v.x; c0.y += v.y; c0.z += v.z; c0.w += v.w;
                *(float4*)&C[idx] = c0;
            }
        }
    }
}

// ---------------- flash attention (split-bf16 mma) ----------------
#define AKHI 0
#define AKLO 38912
#define AVHI 77824
#define AVLO 116736
#define ATTN_SMEM 155648

__global__ void __launch_bounds__(256)
attn_flash(const float* __restrict__ qkv,
           __nv_bfloat16* __restrict__ ohi, __nv_bfloat16* __restrict__ olo)
{
    extern __shared__ __align__(128) char asmem[];
    uint32_t sb = smem_u32(asmem);
    int tid = threadIdx.x;
    int bh = blockIdx.x, b = bh >> 4, hd = bh & 15;
    const float* base = qkv + (size_t)b * LSEQ * 3072;
    int hoff = hd * 64;

    for (int idx = tid; idx < 304 * 64; idx += 256) {
        int j = idx >> 6, d = idx & 63;
        float kv = 0.f, vv = 0.f;
        if (j < LSEQ) {
            kv = base[(size_t)j * 3072 + 1024 + hoff + d];
            vv = base[(size_t)j * 3072 + 2048 + hoff + d];
        }
        uint32_t off = (uint32_t)SWZ128(j * 128 + d * 2);
        __nv_bfloat16 kh = __float2bfloat16(kv);
        *(__nv_bfloat16*)(asmem + AKHI + off) = kh;
        *(__nv_bfloat16*)(asmem + AKLO + off) = __float2bfloat16(kv - __bfloat162float(kh));
        __nv_bfloat16 vh = __float2bfloat16(vv);
        *(__nv_bfloat16*)(asmem + AVHI + off) = vh;
        *(__nv_bfloat16*)(asmem + AVLO + off) = __float2bfloat16(vv - __bfloat162float(vh));
    }
    __syncthreads();

    int w = tid >> 5, lane = tid & 31;
    int g = lane >> 2, t4 = lane & 3;
    int kb_row = (lane >> 4) * 8 + (lane & 7);
    int kb_kb  = ((lane >> 3) & 1) * 16;
    int vb_row = ((lane >> 3) & 1) * 8 + (lane & 7);
    int vb_nb  = (lane >> 4) * 16;

    for (int qi = 0; qi < 3; qi++) {
        int qt = (qi == 0) ? (18 - w) : ((qi == 1) ? (3 + w) : ((w < 3) ? (2 - w) : -1));
        if (qt < 0) continue;
        int q0 = qt * 16;

        uint32_t qh[4][4], ql[4][4];
        int r1 = q0 + g;       int r1c = r1 < LSEQ ? r1 : LSEQ - 1;
        int r2 = r1 + 8;       int r2c = r2 < LSEQ ? r2 : LSEQ - 1;
        const float* q1p = base + (size_t)r1c * 3072 + hoff;
        const float* q2p = base + (size_t)r2c * 3072 + hoff;
#pragma unroll
        for (int kt = 0; kt < 4; kt++) {
            int c0 = kt * 16 + 2 * t4;
            float2 x0 = *(const float2*)(q1p + c0);
            float2 x1 = *(const float2*)(q2p + c0);
            float2 x2 = *(const float2*)(q1p + c0 + 8);
            float2 x3 = *(const float2*)(q2p + c0 + 8);
            pack_hilo(x0.x, x0.y, qh[kt][0], ql[kt][0]);
            pack_hilo(x1.x, x1.y, qh[kt][1], ql[kt][1]);
            pack_hilo(x2.x, x2.y, qh[kt][2], ql[kt][2]);
            pack_hilo(x3.x, x3.y, qh[kt][3], ql[kt][3]);
        }

        float m0 = -1e30f, m1 = -1e30f, l0 = 0.f, l1 = 0.f;
        float o[8][4];
#pragma unroll
        for (int i = 0; i < 8; i++)
#pragma unroll
            for (int k = 0; k < 4; k++) o[i][k] = 0.f;

        for (int jt = 0; jt <= qt; jt++) {
            float s[2][4] = {{0,0,0,0},{0,0,0,0}};
#pragma unroll
            for (int kt = 0; kt < 4; kt++) {
                int row = jt * 16 + kb_row;
                uint32_t off = (uint32_t)(row * 128 + ((kt * 32 + kb_kb) ^ ((row & 7) << 4)));
                uint32_t kh4[4], kl4[4];
                ldsm4(kh4, sb + AKHI + off);
                ldsm4(kl4, sb + AKLO + off);
#pragma unroll
                for (int nt = 0; nt < 2; nt++) {
                    mma16816(s[nt], qh[kt], &kh4[nt*2]);
                    mma16816(s[nt], qh[kt], &kl4[nt*2]);
                    mma16816(s[nt], ql[kt], &kh4[nt*2]);
                }
            }
            int qr1 = q0 + g, qr2 = qr1 + 8;
#pragma unroll
            for (int nt = 0; nt < 2; nt++) {
                int jc = jt * 16 + nt * 8 + 2 * t4;
                s[nt][0] = (jc     <= qr1) ? s[nt][0] * 0.125f : -1e30f;
                s[nt][1] = (jc + 1 <= qr1) ? s[nt][1] * 0.125f : -1e30f;
                s[nt][2] = (jc     <= qr2) ? s[nt][2] * 0.125f : -1e30f;
                s[nt][3] = (jc + 1 <= qr2) ? s[nt][3] * 0.125f : -1e30f;
            }
            float tm0 = fmaxf(fmaxf(s[0][0], s[0][1]), fmaxf(s[1][0], s[1][1]));
            float tm1 = fmaxf(fmaxf(s[0][2], s[0][3]), fmaxf(s[1][2], s[1][3]));
            tm0 = fmaxf(tm0, __shfl_xor_sync(0xFFFFFFFFu, tm0, 1));
            tm0 = fmaxf(tm0, __shfl_xor_sync(0xFFFFFFFFu, tm0, 2));
            tm1 = fmaxf(tm1, __shfl_xor_sync(0xFFFFFFFFu, tm1, 1));
            tm1 = fmaxf(tm1, __shfl_xor_sync(0xFFFFFFFFu, tm1, 2));
            float mn0 = fmaxf(m0, tm0), mn1 = fmaxf(m1, tm1);
            float sc0 = expf(m0 - mn0), sc1 = expf(m1 - mn1);
            m0 = mn0; m1 = mn1;
            float p[2][4];
#pragma unroll
            for (int nt = 0; nt < 2; nt++) {
                p[nt][0] = expf(s[nt][0] - mn0);
                p[nt][1] = expf(s[nt][1] - mn0);
                p[nt][2] = expf(s[nt][2] - mn1);
                p[nt][3] = expf(s[nt][3] - mn1);
            }
            float ts0 = p[0][0] + p[0][1] + p[1][0] + p[1][1];
            float ts1 = p[0][2] + p[0][3] + p[1][2] + p[1][3];
            ts0 += __shfl_xor_sync(0xFFFFFFFFu, ts0, 1);
            ts0 += __shfl_xor_sync(0xFFFFFFFFu, ts0, 2);
            ts1 += __shfl_xor_sync(0xFFFFFFFFu, ts1, 1);
            ts1 += __shfl_xor_sync(0xFFFFFFFFu, ts1, 2);
            l0 = l0 * sc0 + ts0;
            l1 = l1 * sc1 + ts1;
#pragma unroll
            for (int nt = 0; nt < 8; nt++) {
                o[nt][0] *= sc0; o[nt][1] *= sc0; o[nt][2] *= sc1; o[nt][3] *= sc1;
            }
            uint32_t pah[4], pal[4];
            pack_hilo(p[0][0], p[0][1], pah[0], pal[0]);
            pack_hilo(p[0][2], p[0][3], pah[1], pal[1]);
            pack_hilo(p[1][0], p[1][1], pah[2], pal[2]);
            pack_hilo(p[1][2], p[1][3], pah[3], pal[3]);
#pragma unroll
            for (int dt = 0; dt < 4; dt++) {
                int row = jt * 16 + vb_row;
                uint32_t off = (uint32_t)(row * 128 + ((dt * 32 + vb_nb) ^ ((row & 7) << 4)));
                uint32_t vh4[4], vl4[4];
                ldsm4t(vh4, sb + AVHI + off);
                ldsm4t(vl4, sb + AVLO + off);
#pragma unroll
                for (int su = 0; su < 2; su++) {
                    int nt = dt * 2 + su;
                    mma16816(o[nt], pah, &vh4[su*2]);
                    mma16816(o[nt], pah, &vl4[su*2]);
                    mma16816(o[nt], pal, &vh4[su*2]);
                }
            }
        }
        float inv0 = 1.f / l0, inv1 = 1.f / l1;
        int row1 = q0 + g, row2 = row1 + 8;
#pragma unroll
        for (int nt = 0; nt < 8; nt++) {
            int col = nt * 8 + 2 * t4;
            if (row1 < LSEQ) {
                uint32_t hp, lp;
                pack_hilo(o[nt][0] * inv0, o[nt][1] * inv0, hp, lp);
                size_t idx = (size_t)(b * LSEQ + row1) * D_ + hoff + col;
                *(uint32_t*)&ohi[idx] = hp;
                *(uint32_t*)&olo[idx] = lp;
            }
            if (row2 < LSEQ) {
                uint32_t hp, lp;
                pack_hilo(o[nt][2] * inv1, o[nt][3] * inv1, hp, lp);
                size_t idx = (size_t)(b * LSEQ + row2) * D_ + hoff + col;
                *(uint32_t*)&ohi[idx] = hp;
                *(uint32_t*)&olo[idx] = lp;
            }
        }
    }
}

// ---------------- loss ----------------
__global__ void loss_kernel(const float* __restrict__ h,
                            const float* __restrict__ g,
                            const float* __restrict__ beta,
                            const float* __restrict__ pw,
                            const float* __restrict__ pb,
                            const int* __restrict__ actions,
                            const int* __restrict__ tact,
                            float* __restrict__ partial)
{
    __shared__ float red[4];
    __shared__ float lred[5][4];
    int idx = blockIdx.x;
    int b = idx / (CTX_ + 1), t = idx % (CTX_ + 1);
    const float* x = h + (size_t)(b * LSEQ + 3 * t) * D_;
    int tid = threadIdx.x, lane = tid & 31, w = tid >> 5;

    float v[8];
    float s = 0.f;
#pragma unroll
    for (int i = 0; i < 8; i++) { v[i] = x[tid + 128 * i]; s += v[i]; }
#pragma unroll
    for (int o = 16; o; o >>= 1) s += __shfl_xor_sync(0xFFFFFFFFu, s, o);
    if (lane == 0) red[w] = s;
    __syncthreads();
    float mean = (red[0] + red[1] + red[2] + red[3]) * (1.f / 1024.f);
    __syncthreads();
    float s2 = 0.f;
#pragma unroll
    for (int i = 0; i < 8; i++) { float d = v[i] - mean; s2 += d * d; }
#pragma unroll
    for (int o = 16; o; o >>= 1) s2 += __shfl_xor_sync(0xFFFFFFFFu, s2, o);
    if (lane == 0) red[w] = s2;
    __syncthreads();
    float var = (red[0] + red[1] + red[2] + red[3]) * (1.f / 1024.f);
    float inv = 1.f / sqrtf(var + 1e-5f);

    float acc[NA_] = {0.f, 0.f, 0.f, 0.f, 0.f};
#pragma unroll
    for (int i = 0; i < 8; i++) {
        int c = tid + 128 * i;
        float xn = (v[i] - mean) * inv * g[c] + beta[c];
#pragma unroll
        for (int a = 0; a < NA_; a++)
            acc[a] = fmaf(xn, pw[c * NA_ + a], acc[a]);
    }
#pragma unroll
    for (int a = 0; a < NA_; a++) {
        float tv = acc[a];
#pragma unroll
        for (int o = 16; o; o >>= 1) tv += __shfl_xor_sync(0xFFFFFFFFu, tv, o);
        if (lane == 0) lred[a][w] = tv;
    }
    __syncthreads();
    if (tid == 0) {
        float logit[NA_];
#pragma unroll
        for (int a = 0; a < NA_; a++)
            logit[a] = lred[a][0] + lred[a][1] + lred[a][2] + lred[a][3] + pb[a];
        int target = (t < CTX_) ? actions[b * CTX_ + t] : tact[b];
        float mx = logit[0]; int am = 0;
#pragma unroll
        for (int a = 1; a < NA_; a++) if (logit[a] > mx) { mx = logit[a]; am = a; }
        float se = 0.f;
#pragma unroll
        for (int a = 0; a < NA_; a++) se += expf(logit[a] - mx);
        float lse = mx + logf(se);
        float sl = 0.f;
#pragma unroll
        for (int a = 0; a < NA_; a++) sl += (logit[a] - lse);
        float nll = -(logit[target] - lse);
        float smooth = -sl * (1.f / NA_);
        partial[2 * idx]     = 0.9f * nll + 0.1f * smooth;
        partial[2 * idx + 1] = (am == target) ? 1.f : 0.f;
    }
}

__global__ void reduce_kernel(const float* __restrict__ partial, float* __restrict__ out)
{
    __shared__ float rl[8], ra[8];
    int tid = threadIdx.x, lane = tid & 31, w = tid >> 5;
    float l = 0.f, a = 0.f;
    for (int i = tid; i < NPOS; i += 256) {
        l += partial[2 * i];
        a += partial[2 * i + 1];
    }
#pragma unroll
    for (int o = 16; o; o >>= 1) {
        l += __shfl_xor_sync(0xFFFFFFFFu, l, o);
        a += __shfl_xor_sync(0xFFFFFFFFu, a, o);
    }
    if (lane == 0) { rl[w] = l; ra[w] = a; }
    __syncthreads();
    if (tid == 0) {
        float L = 0.f, A = 0.f;
#pragma unroll
        for (int i = 0; i < 8; i++) { L += rl[i]; A += ra[i]; }
        out[0] = L * (1.f / NPOS);
        out[1] = A * (1.f / NPOS);
    }
}

// ---------------- host ----------------
static inline void launch_gemm64(const __nv_bfloat16* Ahi, const __nv_bfloat16* Alo,
                                 const __nv_bfloat16* Bhi, const __nv_bfloat16* Blo,
                                 const float* bias, float* C,
                                 __nv_bfloat16* Chi, __nv_bfloat16* Clo,
                                 int M, int N, int K, int mode)
{
    dim3 grid(N / 64, (M + BM - 1) / BM);
    gemm_mma64<<<grid, 256, GEMM2_SMEM>>>(Ahi, Alo, Bhi, Blo, bias, C, Chi, Clo, M, N, K, mode);
}

extern "C" void kernel_launch(void* const* d_in, const int* in_sizes, int n_in,
                              void* d_out, int out_size)
{
    const int*   states  = (const int*)  d_in[0];
    const int*   actions = (const int*)  d_in[1];
    const float* rewards = (const float*)d_in[2];
    const int*   qstates = (const int*)  d_in[3];
    const int*   tact    = (const int*)  d_in[4];
    const float* wpe     = (const float*)d_in[5];
    const float* e_state = (const float*)d_in[6];
    const float* e_act   = (const float*)d_in[7];
    const float* erw     = (const float*)d_in[8];
    const float* erb     = (const float*)d_in[9];
    const float* ln1g    = (const float*)d_in[10];
    const float* ln1b    = (const float*)d_in[11];
    const float* attnw   = (const float*)d_in[12];
    const float* attnb   = (const float*)d_in[13];
    const float* apw     = (const float*)d_in[14];
    const float* apb     = (const float*)d_in[15];
    const float* ln2g    = (const float*)d_in[16];
    const float* ln2b    = (const float*)d_in[17];
    const float* fcw     = (const float*)d_in[18];
    const float* fcb     = (const float*)d_in[19];
    const float* mpw     = (const float*)d_in[20];
    const float* mpb     = (const float*)d_in[21];
    const float* lnfg    = (const float*)d_in[22];
    const float* lnfb    = (const float*)d_in[23];
    const float* predw   = (const float*)d_in[24];
    const float* predb   = (const float*)d_in[25];
    float* out = (float*)d_out;

    float *h, *qkv, *partial;
    __nv_bfloat16 *xhi, *xlo, *ahi, *alo, *fhi, *flo, *whi, *wlo;
    cudaGetSymbolAddress((void**)&h,    g_h);
    cudaGetSymbolAddress((void**)&qkv,  g_qkv);
    cudaGetSymbolAddress((void**)&partial, g_partial);
    cudaGetSymbolAddress((void**)&xhi,  g_xhi);
    cudaGetSymbolAddress((void**)&xlo,  g_xlo);
    cudaGetSymbolAddress((void**)&ahi,  g_ahi);
    cudaGetSymbolAddress((void**)&alo,  g_alo);
    cudaGetSymbolAddress((void**)&fhi,  g_fhi);
    cudaGetSymbolAddress((void**)&flo,  g_flo);
    cudaGetSymbolAddress((void**)&whi,  g_whi);
    cudaGetSymbolAddress((void**)&wlo,  g_wlo);

    cudaFuncSetAttribute(attn_flash, cudaFuncAttributeMaxDynamicSharedMemorySize, ATTN_SMEM);
    cudaFuncSetAttribute(gemm_mma64, cudaFuncAttributeMaxDynamicSharedMemorySize, GEMM2_SMEM);

    const size_t WPL = 12582912;
    const size_t OFF_QKV = 0, OFF_PROJ = 3145728, OFF_FC = 4194304, OFF_MP = 8388608;
    wprep_kernel<<<dim3(3 * D_ / 32, D_ / 32, NL_), dim3(32, 8)>>>(
        attnw, whi + OFF_QKV, wlo + OFF_QKV, D_, 3 * D_, (size_t)D_ * 3 * D_, WPL);
    wprep_kernel<<<dim3(D_ / 32, D_ / 32, NL_), dim3(32, 8)>>>(
        apw, whi + OFF_PROJ, wlo + OFF_PROJ, D_, D_, (size_t)D_ * D_, WPL);
    wprep_kernel<<<dim3(DFF_ / 32, D_ / 32, NL_), dim3(32, 8)>>>(
        fcw, whi + OFF_FC, wlo + OFF_FC, D_, DFF_, (size_t)D_ * DFF_, WPL);
    wprep_kernel<<<dim3(D_ / 32, DFF_ / 32, NL_), dim3(32, 8)>>>(
        mpw, whi + OFF_MP, wlo + OFF_MP, DFF_, D_, (size_t)DFF_ * D_, WPL);

    embed_kernel<<<NTOK, 256>>>(states, actions, rewards, qstates, wpe,
                                e_state, e_act, erw, erb, h);

    for (int i = 0; i < NL_; i++) {
        size_t off = (size_t)i * WPL;
        ln_kernel<<<NTOK, 256>>>(h, xhi, xlo, ln1g + i * D_, ln1b + i * D_);
        launch_gemm64(xhi, xlo, whi + off + OFF_QKV, wlo + off + OFF_QKV,
                      attnb + i * 3 * D_, qkv, nullptr, nullptr, NTOK, 3 * D_, D_, 0);
        attn_flash<<<B_ * H_, 256, ATTN_SMEM>>>(qkv, ahi, alo);
        launch_gemm64(ahi, alo, whi + off + OFF_PROJ, wlo + off + OFF_PROJ,
                      apb + i * D_, h, nullptr, nullptr, NTOK, D_, D_, 2);
        ln_kernel<<<NTOK, 256>>>(h, xhi, xlo, ln2g + i * D_, ln2b + i * D_);
        launch_gemm64(xhi, xlo, whi + off + OFF_FC, wlo + off + OFF_FC,
                      fcb + i * DFF_, nullptr, fhi, flo, NTOK, DFF_, D_, 1);
        launch_gemm64(fhi, flo, whi + off + OFF_MP, wlo + off + OFF_MP,
                      mpb + i * D_, h, nullptr, nullptr, NTOK, D_, DFF_, 2);
    }

    loss_kernel<<<NPOS, 128>>>(h, lnfg, lnfb, predw, predb, actions, tact, partial);
    reduce_kernel<<<1, 256>>>(partial, out);
}

// round 11
// speedup vs baseline: 3.8633x; 1.0005x over previous
#include <cuda_runtime.h>
#include <cuda_bf16.h>
#include <math.h>
#include <stdint.h>

#define B_    16
#define CTX_  100
#define LSEQ  301
#define D_    1024
#define H_    16
#define HD_   64
#define NL_   4
#define DFF_  4096
#define GRID_ 9
#define NA_   5
#define NTOK  (B_*LSEQ)
#define NPOS  (B_*(CTX_+1))
#define WPOOL 50331648

__device__ float g_h   [NTOK * D_];
__device__ float g_qkv [NTOK * 3 * D_];
__device__ __nv_bfloat16 g_xhi[NTOK * D_];
__device__ __nv_bfloat16 g_xlo[NTOK * D_];
__device__ __nv_bfloat16 g_ahi[NTOK * D_];
__device__ __nv_bfloat16 g_alo[NTOK * D_];
__device__ __nv_bfloat16 g_fhi[NTOK * DFF_];
__device__ __nv_bfloat16 g_flo[NTOK * DFF_];
__device__ __nv_bfloat16 g_whi[WPOOL];
__device__ __nv_bfloat16 g_wlo[WPOOL];
__device__ float g_partial[NPOS * 2];

#define CP16(d, s, z)  asm volatile("cp.async.cg.shared.global [%0], [%1], 16, %2;" :: "r"(d), "l"(s), "r"(z) : "memory")
#define CP_COMMIT()    asm volatile("cp.async.commit_group;" ::: "memory")
#define CP_WAIT(n)     asm volatile("cp.async.wait_group %0;" :: "n"(n) : "memory")
#define SWZ128(o) ((o) ^ (((o) >> 3) & 0x70))

__device__ __forceinline__ uint32_t smem_u32(const void* p) {
    uint32_t a;
    asm("{ .reg .u64 t; cvta.to.shared.u64 t, %1; cvt.u32.u64 %0, t; }" : "=r"(a) : "l"(p));
    return a;
}
__device__ __forceinline__ void ldsm4(uint32_t* r, uint32_t addr) {
    asm volatile("ldmatrix.sync.aligned.m8n8.x4.shared.b16 {%0,%1,%2,%3}, [%4];"
                 : "=r"(r[0]), "=r"(r[1]), "=r"(r[2]), "=r"(r[3]) : "r"(addr));
}
__device__ __forceinline__ void ldsm4t(uint32_t* r, uint32_t addr) {
    asm volatile("ldmatrix.sync.aligned.m8n8.x4.trans.shared.b16 {%0,%1,%2,%3}, [%4];"
                 : "=r"(r[0]), "=r"(r[1]), "=r"(r[2]), "=r"(r[3]) : "r"(addr));
}
__device__ __forceinline__ void mma16816(float* c, const uint32_t* a, const uint32_t* b) {
    asm volatile("mma.sync.aligned.m16n8k16.row.col.f32.bf16.bf16.f32 "
                 "{%0,%1,%2,%3}, {%4,%5,%6,%7}, {%8,%9}, {%0,%1,%2,%3};"
                 : "+f"(c[0]), "+f"(c[1]), "+f"(c[2]), "+f"(c[3])
                 : "r"(a[0]), "r"(a[1]), "r"(a[2]), "r"(a[3]), "r"(b[0]), "r"(b[1]));
}
__device__ __forceinline__ void pack_hilo(float x, float y, uint32_t& hi, uint32_t& lo) {
    __nv_bfloat16 xh = __float2bfloat16(x), yh = __float2bfloat16(y);
    __nv_bfloat162 hv; hv.x = xh; hv.y = yh;
    __nv_bfloat162 lv;
    lv.x = __float2bfloat16(x - __bfloat162float(xh));
    lv.y = __float2bfloat16(y - __bfloat162float(yh));
    hi = *(uint32_t*)&hv; lo = *(uint32_t*)&lv;
}

__device__ __forceinline__ float gelu_new(float xv) {
    float t = tanhf(0.7978845608028654f * (xv + 0.044715f * xv * xv * xv));
    return 0.5f * xv * (1.f + t);
}

// ---------------- embedding ----------------
__global__ void embed_kernel(const int* __restrict__ states,
                             const int* __restrict__ actions,
                             const float* __restrict__ rewards,
                             const int* __restrict__ qstates,
                             const float* __restrict__ wpe,
                             const float* __restrict__ e_state,
                             const float* __restrict__ e_act,
                             const float* __restrict__ erw,
                             const float* __restrict__ erb,
                             float* __restrict__ h)
{
    int tok = blockIdx.x;
    int b = tok / LSEQ, p = tok % LSEQ;
    const float* src = nullptr;
    float r = 0.f;
    int type = 0;
    if (p == 3 * CTX_) {
        int q = qstates[b * 2] * GRID_ + qstates[b * 2 + 1];
        src = e_state + (size_t)q * D_;
    } else {
        int t = p / 3, m = p % 3;
        if (m == 0) {
            int sid = states[(b * CTX_ + t) * 2] * GRID_ + states[(b * CTX_ + t) * 2 + 1];
            src = e_state + (size_t)sid * D_;
        } else if (m == 1) {
            src = e_act + (size_t)actions[b * CTX_ + t] * D_;
        } else {
            r = rewards[b * CTX_ + t];
            type = 1;
        }
    }
    for (int c = threadIdx.x; c < D_; c += blockDim.x) {
        float v = (type == 0) ? src[c] : fmaf(r, erw[c], erb[c]);
        h[(size_t)tok * D_ + c] = v + wpe[(size_t)p * D_ + c];
    }
}

// ---------------- weight transpose + split (batched over layers via z) ----------------
__global__ void wprep_kernel(const float* __restrict__ W,
                             __nv_bfloat16* __restrict__ Thi,
                             __nv_bfloat16* __restrict__ Tlo,
                             int K, int N, size_t sstride, size_t dstride)
{
    __shared__ float t[32][33];
    const float* Wz = W + (size_t)blockIdx.z * sstride;
    __nv_bfloat16* Th = Thi + (size_t)blockIdx.z * dstride;
    __nv_bfloat16* Tl = Tlo + (size_t)blockIdx.z * dstride;
    int n = blockIdx.x * 32 + threadIdx.x;
    int k0 = blockIdx.y * 32;
#pragma unroll
    for (int r = 0; r < 32; r += 8)
        t[threadIdx.y + r][threadIdx.x] = Wz[(size_t)(k0 + threadIdx.y + r) * N + n];
    __syncthreads();
    int k = k0 + threadIdx.x;
#pragma unroll
    for (int r = 0; r < 32; r += 8) {
        int nn = blockIdx.x * 32 + threadIdx.y + r;
        float v = t[threadIdx.x][threadIdx.y + r];
        __nv_bfloat16 hi = __float2bfloat16(v);
        Th[(size_t)nn * K + k] = hi;
        Tl[(size_t)nn * K + k] = __float2bfloat16(v - __bfloat162float(hi));
    }
}

// ---------------- LayerNorm -> hi/lo ----------------
__global__ void ln_kernel(const float* __restrict__ in,
                          __nv_bfloat16* __restrict__ ohi,
                          __nv_bfloat16* __restrict__ olo,
                          const float* __restrict__ g, const float* __restrict__ beta)
{
    __shared__ float red[8];
    int row = blockIdx.x;
    const float* x = in + (size_t)row * D_;
    int tid = threadIdx.x;
    float v[4];
    float s = 0.f;
#pragma unroll
    for (int i = 0; i < 4; i++) { v[i] = x[tid + 256 * i]; s += v[i]; }
#pragma unroll
    for (int o = 16; o; o >>= 1) s += __shfl_xor_sync(0xFFFFFFFFu, s, o);
    if ((tid & 31) == 0) red[tid >> 5] = s;
    __syncthreads();
    float mean = (red[0]+red[1]+red[2]+red[3]+red[4]+red[5]+red[6]+red[7]) * (1.f/1024.f);
    __syncthreads();
    float s2 = 0.f;
#pragma unroll
    for (int i = 0; i < 4; i++) { float d = v[i] - mean; s2 += d * d; }
#pragma unroll
    for (int o = 16; o; o >>= 1) s2 += __shfl_xor_sync(0xFFFFFFFFu, s2, o);
    if ((tid & 31) == 0) red[tid >> 5] = s2;
    __syncthreads();
    float var = (red[0]+red[1]+red[2]+red[3]+red[4]+red[5]+red[6]+red[7]) * (1.f/1024.f);
    float inv = 1.f / sqrtf(var + 1e-5f);
#pragma unroll
    for (int i = 0; i < 4; i++) {
        int c = tid + 256 * i;
        float y = (v[i] - mean) * inv * g[c] + beta[c];
        __nv_bfloat16 hi = __float2bfloat16(y);
        ohi[(size_t)row * D_ + c] = hi;
        olo[(size_t)row * D_ + c] = __float2bfloat16(y - __bfloat162float(hi));
    }
}

// ---------------- GEMM 128x64, 2-stage, 2 CTA/SM (all GEMMs) ----------------
#define BM 128
#define BK 64
#define TILE_A2 (128 * 128)
#define TILE_B2 (64 * 128)
#define STAGE_B2 (2 * TILE_A2 + 2 * TILE_B2)
#define GEMM2_SMEM (2 * STAGE_B2)
#define LDS2_ 68

__global__ void __launch_bounds__(256, 2)
gemm_mma64(const __nv_bfloat16* __restrict__ Ahi, const __nv_bfloat16* __restrict__ Alo,
           const __nv_bfloat16* __restrict__ Bhi, const __nv_bfloat16* __restrict__ Blo,
           const float* __restrict__ bias, float* __restrict__ C,
           __nv_bfloat16* __restrict__ Chi, __nv_bfloat16* __restrict__ Clo,
           int M, int N, int K, int mode)
{
    extern __shared__ __align__(128) char smem[];
    uint32_t sbase = smem_u32(smem);
    int tid = threadIdx.x, wid = tid >> 5, lane = tid & 31;
    int m0 = blockIdx.y * BM, n0 = blockIdx.x * 64;
    int wm = wid >> 2, wn = wid & 3;

    uint32_t soA[4], soB[2];
    unsigned ao[4], bo[2], szA[4];
#pragma unroll
    for (int i = 0; i < 4; i++) {
        int c = tid + 256 * i;
        int r = c >> 3, gb = c & 7;
        soA[i] = (uint32_t)SWZ128(r * 128 + gb * 16);
        bool ok = (m0 + r) < M;
        ao[i] = ok ? ((unsigned)(m0 + r) * (unsigned)K + gb * 8) : 0u;
        szA[i] = ok ? 16u : 0u;
    }
#pragma unroll
    for (int i = 0; i < 2; i++) {
        int c = tid + 256 * i;
        int r = c >> 3, gb = c & 7;
        soB[i] = (uint32_t)SWZ128(r * 128 + gb * 16);
        bo[i] = (unsigned)(n0 + r) * (unsigned)K + gb * 8;
    }
    const int nk = K / BK;

    auto load_tile = [&](int kt) {
        uint32_t st = sbase + (uint32_t)(kt & 1) * STAGE_B2;
        unsigned ko = (unsigned)kt * BK;
#pragma unroll
        for (int i = 0; i < 4; i++) {
            CP16(st + soA[i],           Ahi + ao[i] + ko, szA[i]);
            CP16(st + TILE_A2 + soA[i], Alo + ao[i] + ko, szA[i]);
        }
#pragma unroll
        for (int i = 0; i < 2; i++) {
            CP16(st + 2*TILE_A2 + soB[i],            Bhi + bo[i] + ko, 16u);
            CP16(st + 2*TILE_A2 + TILE_B2 + soB[i],  Blo + bo[i] + ko, 16u);
        }
    };

    int a_row_loc = ((lane >> 3) & 1) * 8 + (lane & 7);
    int a_kh = (lane >> 4) * 16;
    int b_row_loc = (lane >> 4) * 8 + (lane & 7);
    int b_kh = ((lane >> 3) & 1) * 16;

    float acc[4][2][4];
#pragma unroll
    for (int i = 0; i < 4; i++)
#pragma unroll
        for (int j = 0; j < 2; j++)
#pragma unroll
            for (int k = 0; k < 4; k++) acc[i][j][k] = 0.f;

    load_tile(0);
    CP_COMMIT();
    if (nk > 1) load_tile(1);
    CP_COMMIT();

    uint32_t a_base[4];
    int a_ph[4];
#pragma unroll
    for (int mt = 0; mt < 4; mt++) {
        int row = wm * 64 + mt * 16 + a_row_loc;
        a_base[mt] = (uint32_t)(row * 128);
        a_ph[mt] = (row & 7) << 4;
    }
    int brow = wn * 16 + b_row_loc;
    uint32_t b_base = (uint32_t)(brow * 128);
    int b_ph = (brow & 7) << 4;

    for (int kt = 0; kt < nk; kt++) {
        CP_WAIT(1);
        __syncthreads();
        uint32_t st = sbase + (uint32_t)(kt & 1) * STAGE_B2;
        uint32_t stA = st, stAl = st + TILE_A2;
        uint32_t stB = st + 2*TILE_A2, stBl = st + 2*TILE_A2 + TILE_B2;
#pragma unroll
        for (int ks = 0; ks < 4; ks++) {
            uint32_t ah[4][4], al[4][4], bh[4], bl[4];
            {
                uint32_t off = b_base + (uint32_t)((ks * 32 + b_kh) ^ b_ph);
                ldsm4(bh, stB + off);
                ldsm4(bl, stBl + off);
            }
#pragma unroll
            for (int mt = 0; mt < 4; mt++) {
                uint32_t off = a_base[mt] + (uint32_t)((ks * 32 + a_kh) ^ a_ph[mt]);
                ldsm4(ah[mt], stA + off);
                ldsm4(al[mt], stAl + off);
            }
#pragma unroll
            for (int mt = 0; mt < 4; mt++)
#pragma unroll
                for (int nt = 0; nt < 2; nt++) {
                    const uint32_t* bph = &bh[nt * 2];
                    const uint32_t* bpl = &bl[nt * 2];
                    mma16816(acc[mt][nt], ah[mt], bph);
                    mma16816(acc[mt][nt], ah[mt], bpl);
                    mma16816(acc[mt][nt], al[mt], bph);
                }
        }
        __syncthreads();
        if (kt + 2 < nk) load_tile(kt + 2);
        CP_COMMIT();
    }
    CP_WAIT(0);
    __syncthreads();

    float* stg = (float*)smem;
    int cr = lane >> 2, ccol = (lane & 3) * 2;
#pragma unroll
    for (int mt = 0; mt < 4; mt++)
#pragma unroll
        for (int nt = 0; nt < 2; nt++) {
            int r = wm * 64 + mt * 16 + cr;
            int cl = wn * 16 + nt * 8 + ccol;
            *(float2*)&stg[r * LDS2_ + cl]       = make_float2(acc[mt][nt][0], acc[mt][nt][1]);
            *(float2*)&stg[(r + 8) * LDS2_ + cl] = make_float2(acc[mt][nt][2], acc[mt][nt][3]);
        }
    __syncthreads();

#pragma unroll
    for (int i = 0; i < 8; i++) {
        int id = tid + 256 * i;
        int r = id >> 4, cc = (id & 15) * 4;
        int m = m0 + r;
        if (m < M) {
            int n = n0 + cc;
            float4 v = *(float4*)&stg[r * LDS2_ + cc];
            float4 bs = *(const float4*)&bias[n];
            v.x += bs.x; v.y += bs.y; v.z += bs.z; v.w += bs.w;
            size_t idx = (size_t)m * N + n;
            if (mode == 0) {
                *(float4*)&C[idx] = v;
            } else if (mode == 1) {
                float g0 = gelu_new(v.x), g1 = gelu_new(v.y);
                float g2 = gelu_new(v.z), g3 = gelu_new(v.w);
                uint32_t h01, l01, h23, l23;
                pack_hilo(g0, g1, h01, l01);
                pack_hilo(g2, g3, h23, l23);
                *(uint2*)&Chi[idx] = make_uint2(h01, h23);
                *(uint2*)&Clo[idx] = make_uint2(l01, l23);
            } else {
                float4 c0 = *(float4*)&C[idx];
                c0.x += v.x; c0.y += v.y; c0.z += v.z; c0.w += v.w;
                *(float4*)&C[idx] = c0;
            }
        }
    }
}

// ---------------- flash attention (split-bf16 mma, fast softmax) ----------------
#define AKHI 0
#define AKLO 38912
#define AVHI 77824
#define AVLO 116736
#define ATTN_SMEM 155648

__global__ void __launch_bounds__(256)
attn_flash(const float* __restrict__ qkv,
           __nv_bfloat16* __restrict__ ohi, __nv_bfloat16* __restrict__ olo)
{
    extern __shared__ __align__(128) char asmem[];
    uint32_t sb = smem_u32(asmem);
    int tid = threadIdx.x;
    int bh = blockIdx.x, b = bh >> 4, hd = bh & 15;
    const float* base = qkv + (size_t)b * LSEQ * 3072;
    int hoff = hd * 64;

    for (int idx = tid; idx < 304 * 64; idx += 256) {
        int j = idx >> 6, d = idx & 63;
        float kv = 0.f, vv = 0.f;
        if (j < LSEQ) {
            kv = base[(size_t)j * 3072 + 1024 + hoff + d];
            vv = base[(size_t)j * 3072 + 2048 + hoff + d];
        }
        uint32_t off = (uint32_t)SWZ128(j * 128 + d * 2);
        __nv_bfloat16 kh = __float2bfloat16(kv);
        *(__nv_bfloat16*)(asmem + AKHI + off) = kh;
        *(__nv_bfloat16*)(asmem + AKLO + off) = __float2bfloat16(kv - __bfloat162float(kh));
        __nv_bfloat16 vh = __float2bfloat16(vv);
        *(__nv_bfloat16*)(asmem + AVHI + off) = vh;
        *(__nv_bfloat16*)(asmem + AVLO + off) = __float2bfloat16(vv - __bfloat162float(vh));
    }
    __syncthreads();

    int w = tid >> 5, lane = tid & 31;
    int g = lane >> 2, t4 = lane & 3;
    int kb_row = (lane >> 4) * 8 + (lane & 7);
    int kb_kb  = ((lane >> 3) & 1) * 16;
    int vb_row = ((lane >> 3) & 1) * 8 + (lane & 7);
    int vb_nb  = (lane >> 4) * 16;

    for (int qi = 0; qi < 3; qi++) {
        int qt = (qi == 0) ? (18 - w) : ((qi == 1) ? (3 + w) : ((w < 3) ? (2 - w) : -1));
        if (qt < 0) continue;
        int q0 = qt * 16;

        uint32_t qh[4][4], ql[4][4];
        int r1 = q0 + g;       int r1c = r1 < LSEQ ? r1 : LSEQ - 1;
        int r2 = r1 + 8;       int r2c = r2 < LSEQ ? r2 : LSEQ - 1;
        const float* q1p = base + (size_t)r1c * 3072 + hoff;
        const float* q2p = base + (size_t)r2c * 3072 + hoff;
#pragma unroll
        for (int kt = 0; kt < 4; kt++) {
            int c0 = kt * 16 + 2 * t4;
            float2 x0 = *(const float2*)(q1p + c0);
            float2 x1 = *(const float2*)(q2p + c0);
            float2 x2 = *(const float2*)(q1p + c0 + 8);
            float2 x3 = *(const float2*)(q2p + c0 + 8);
            pack_hilo(x0.x, x0.y, qh[kt][0], ql[kt][0]);
            pack_hilo(x1.x, x1.y, qh[kt][1], ql[kt][1]);
            pack_hilo(x2.x, x2.y, qh[kt][2], ql[kt][2]);
            pack_hilo(x3.x, x3.y, qh[kt][3], ql[kt][3]);
        }

        float m0 = -1e30f, m1 = -1e30f, l0 = 0.f, l1 = 0.f;
        float o[8][4];
#pragma unroll
        for (int i = 0; i < 8; i++)
#pragma unroll
            for (int k = 0; k < 4; k++) o[i][k] = 0.f;

        for (int jt = 0; jt <= qt; jt++) {
            float s[2][4] = {{0,0,0,0},{0,0,0,0}};
#pragma unroll
            for (int kt = 0; kt < 4; kt++) {
                int row = jt * 16 + kb_row;
                uint32_t off = (uint32_t)(row * 128 + ((kt * 32 + kb_kb) ^ ((row & 7) << 4)));
                uint32_t kh4[4], kl4[4];
                ldsm4(kh4, sb + AKHI + off);
                ldsm4(kl4, sb + AKLO + off);
#pragma unroll
                for (int nt = 0; nt < 2; nt++) {
                    mma16816(s[nt], qh[kt], &kh4[nt*2]);
                    mma16816(s[nt], qh[kt], &kl4[nt*2]);
                    mma16816(s[nt], ql[kt], &kh4[nt*2]);
                }
            }
            int qr1 = q0 + g, qr2 = qr1 + 8;
#pragma unroll
            for (int nt = 0; nt < 2; nt++) {
                int jc = jt * 16 + nt * 8 + 2 * t4;
                s[nt][0] = (jc     <= qr1) ? s[nt][0] * 0.125f : -1e30f;
                s[nt][1] = (jc + 1 <= qr1) ? s[nt][1] * 0.125f : -1e30f;
                s[nt][2] = (jc     <= qr2) ? s[nt][2] * 0.125f : -1e30f;
                s[nt][3] = (jc + 1 <= qr2) ? s[nt][3] * 0.125f : -1e30f;
            }
            float tm0 = fmaxf(fmaxf(s[0][0], s[0][1]), fmaxf(s[1][0], s[1][1]));
            float tm1 = fmaxf(fmaxf(s[0][2], s[0][3]), fmaxf(s[1][2], s[1][3]));
            tm0 = fmaxf(tm0, __shfl_xor_sync(0xFFFFFFFFu, tm0, 1));
            tm0 = fmaxf(tm0, __shfl_xor_sync(0xFFFFFFFFu, tm0, 2));
            tm1 = fmaxf(tm1, __shfl_xor_sync(0xFFFFFFFFu, tm1, 1));
            tm1 = fmaxf(tm1, __shfl_xor_sync(0xFFFFFFFFu, tm1, 2));
            float mn0 = fmaxf(m0, tm0), mn1 = fmaxf(m1, tm1);
            float sc0 = __expf(m0 - mn0), sc1 = __expf(m1 - mn1);
            m0 = mn0; m1 = mn1;
            float p[2][4];
#pragma unroll
            for (int nt = 0; nt < 2; nt++) {
                p[nt][0] = __expf(s[nt][0] - mn0);
                p[nt][1] = __expf(s[nt][1] - mn0);
                p[nt][2] = __expf(s[nt][2] - mn1);
                p[nt][3] = __expf(s[nt][3] - mn1);
            }
            float ts0 = p[0][0] + p[0][1] + p[1][0] + p[1][1];
            float ts1 = p[0][2] + p[0][3] + p[1][2] + p[1][3];
            ts0 += __shfl_xor_sync(0xFFFFFFFFu, ts0, 1);
            ts0 += __shfl_xor_sync(0xFFFFFFFFu, ts0, 2);
            ts1 += __shfl_xor_sync(0xFFFFFFFFu, ts1, 1);
            ts1 += __shfl_xor_sync(0xFFFFFFFFu, ts1, 2);
            l0 = l0 * sc0 + ts0;
            l1 = l1 * sc1 + ts1;
            // warp-uniform skip of O-rescale when max unchanged everywhere
            bool need = __any_sync(0xFFFFFFFFu, (sc0 != 1.f) || (sc1 != 1.f));
            if (need) {
#pragma unroll
                for (int nt = 0; nt < 8; nt++) {
                    o[nt][0] *= sc0; o[nt][1] *= sc0; o[nt][2] *= sc1; o[nt][3] *= sc1;
                }
            }
            uint32_t pah[4], pal[4];
            pack_hilo(p[0][0], p[0][1], pah[0], pal[0]);
            pack_hilo(p[0][2], p[0][3], pah[1], pal[1]);
            pack_hilo(p[1][0], p[1][1], pah[2], pal[2]);
            pack_hilo(p[1][2], p[1][3], pah[3], pal[3]);
#pragma unroll
            for (int dt = 0; dt < 4; dt++) {
                int row = jt * 16 + vb_row;
                uint32_t off = (uint32_t)(row * 128 + ((dt * 32 + vb_nb) ^ ((row & 7) << 4)));
                uint32_t vh4[4], vl4[4];
                ldsm4t(vh4, sb + AVHI + off);
                ldsm4t(vl4, sb + AVLO + off);
#pragma unroll
                for (int su = 0; su < 2; su++) {
                    int nt = dt * 2 + su;
                    mma16816(o[nt], pah, &vh4[su*2]);
                    mma16816(o[nt], pah, &vl4[su*2]);
                    mma16816(o[nt], pal, &vh4[su*2]);
                }
            }
        }
        float inv0 = 1.f / l0, inv1 = 1.f / l1;
        int row1 = q0 + g, row2 = row1 + 8;
#pragma unroll
        for (int nt = 0; nt < 8; nt++) {
            int col = nt * 8 + 2 * t4;
            if (row1 < LSEQ) {
                uint32_t hp, lp;
                pack_hilo(o[nt][0] * inv0, o[nt][1] * inv0, hp, lp);
                size_t idx = (size_t)(b * LSEQ + row1) * D_ + hoff + col;
                *(uint32_t*)&ohi[idx] = hp;
                *(uint32_t*)&olo[idx] = lp;
            }
            if (row2 < LSEQ) {
                uint32_t hp, lp;
                pack_hilo(o[nt][2] * inv1, o[nt][3] * inv1, hp, lp);
                size_t idx = (size_t)(b * LSEQ + row2) * D_ + hoff + col;
                *(uint32_t*)&ohi[idx] = hp;
                *(uint32_t*)&olo[idx] = lp;
            }
        }
    }
}

// ---------------- loss ----------------
__global__ void loss_kernel(const float* __restrict__ h,
                            const float* __restrict__ g,
                            const float* __restrict__ beta,
                            const float* __restrict__ pw,
                            const float* __restrict__ pb,
                            const int* __restrict__ actions,
                            const int* __restrict__ tact,
                            float* __restrict__ partial)
{
    __shared__ float red[4];
    __shared__ float lred[5][4];
    int idx = blockIdx.x;
    int b = idx / (CTX_ + 1), t = idx % (CTX_ + 1);
    const float* x = h + (size_t)(b * LSEQ + 3 * t) * D_;
    int tid = threadIdx.x, lane = tid & 31, w = tid >> 5;

    float v[8];
    float s = 0.f;
#pragma unroll
    for (int i = 0; i < 8; i++) { v[i] = x[tid + 128 * i]; s += v[i]; }
#pragma unroll
    for (int o = 16; o; o >>= 1) s += __shfl_xor_sync(0xFFFFFFFFu, s, o);
    if (lane == 0) red[w] = s;
    __syncthreads();
    float mean = (red[0] + red[1] + red[2] + red[3]) * (1.f / 1024.f);
    __syncthreads();
    float s2 = 0.f;
#pragma unroll
    for (int i = 0; i < 8; i++) { float d = v[i] - mean; s2 += d * d; }
#pragma unroll
    for (int o = 16; o; o >>= 1) s2 += __shfl_xor_sync(0xFFFFFFFFu, s2, o);
    if (lane == 0) red[w] = s2;
    __syncthreads();
    float var = (red[0] + red[1] + red[2] + red[3]) * (1.f / 1024.f);
    float inv = 1.f / sqrtf(var + 1e-5f);

    float acc[NA_] = {0.f, 0.f, 0.f, 0.f, 0.f};
#pragma unroll
    for (int i = 0; i < 8; i++) {
        int c = tid + 128 * i;
        float xn = (v[i] - mean) * inv * g[c] + beta[c];
#pragma unroll
        for (int a = 0; a < NA_; a++)
            acc[a] = fmaf(xn, pw[c * NA_ + a], acc[a]);
    }
#pragma unroll
    for (int a = 0; a < NA_; a++) {
        float tv = acc[a];
#pragma unroll
        for (int o = 16; o; o >>= 1) tv += __shfl_xor_sync(0xFFFFFFFFu, tv, o);
        if (lane == 0) lred[a][w] = tv;
    }
    __syncthreads();
    if (tid == 0) {
        float logit[NA_];
#pragma unroll
        for (int a = 0; a < NA_; a++)
            logit[a] = lred[a][0] + lred[a][1] + lred[a][2] + lred[a][3] + pb[a];
        int target = (t < CTX_) ? actions[b * CTX_ + t] : tact[b];
        float mx = logit[0]; int am = 0;
#pragma unroll
        for (int a = 1; a < NA_; a++) if (logit[a] > mx) { mx = logit[a]; am = a; }
        float se = 0.f;
#pragma unroll
        for (int a = 0; a < NA_; a++) se += expf(logit[a] - mx);
        float lse = mx + logf(se);
        float sl = 0.f;
#pragma unroll
        for (int a = 0; a < NA_; a++) sl += (logit[a] - lse);
        float nll = -(logit[target] - lse);
        float smooth = -sl * (1.f / NA_);
        partial[2 * idx]     = 0.9f * nll + 0.1f * smooth;
        partial[2 * idx + 1] = (am == target) ? 1.f : 0.f;
    }
}

__global__ void reduce_kernel(const float* __restrict__ partial, float* __restrict__ out)
{
    __shared__ float rl[8], ra[8];
    int tid = threadIdx.x, lane = tid & 31, w = tid >> 5;
    float l = 0.f, a = 0.f;
    for (int i = tid; i < NPOS; i += 256) {
        l += partial[2 * i];
        a += partial[2 * i + 1];
    }
#pragma unroll
    for (int o = 16; o; o >>= 1) {
        l += __shfl_xor_sync(0xFFFFFFFFu, l, o);
        a += __shfl_xor_sync(0xFFFFFFFFu, a, o);
    }
    if (lane == 0) { rl[w] = l; ra[w] = a; }
    __syncthreads();
    if (tid == 0) {
        float L = 0.f, A = 0.f;
#pragma unroll
        for (int i = 0; i < 8; i++) { L += rl[i]; A += ra[i]; }
        out[0] = L * (1.f / NPOS);
        out[1] = A * (1.f / NPOS);
    }
}

// ---------------- host ----------------
static inline void launch_gemm64(const __nv_bfloat16* Ahi, const __nv_bfloat16* Alo,
                                 const __nv_bfloat16* Bhi, const __nv_bfloat16* Blo,
                                 const float* bias, float* C,
                                 __nv_bfloat16* Chi, __nv_bfloat16* Clo,
                                 int M, int N, int K, int mode)
{
    dim3 grid(N / 64, (M + BM - 1) / BM);
    gemm_mma64<<<grid, 256, GEMM2_SMEM>>>(Ahi, Alo, Bhi, Blo, bias, C, Chi, Clo, M, N, K, mode);
}

extern "C" void kernel_launch(void* const* d_in, const int* in_sizes, int n_in,
                              void* d_out, int out_size)
{
    const int*   states  = (const int*)  d_in[0];
    const int*   actions = (const int*)  d_in[1];
    const float* rewards = (const float*)d_in[2];
    const int*   qstates = (const int*)  d_in[3];
    const int*   tact    = (const int*)  d_in[4];
    const float* wpe     = (const float*)d_in[5];
    const float* e_state = (const float*)d_in[6];
    const float* e_act   = (const float*)d_in[7];
    const float* erw     = (const float*)d_in[8];
    const float* erb     = (const float*)d_in[9];
    const float* ln1g    = (const float*)d_in[10];
    const float* ln1b    = (const float*)d_in[11];
    const float* attnw   = (const float*)d_in[12];
    const float* attnb   = (const float*)d_in[13];
    const float* apw     = (const float*)d_in[14];
    const float* apb     = (const float*)d_in[15];
    const float* ln2g    = (const float*)d_in[16];
    const float* ln2b    = (const float*)d_in[17];
    const float* fcw     = (const float*)d_in[18];
    const float* fcb     = (const float*)d_in[19];
    const float* mpw     = (const float*)d_in[20];
    const float* mpb     = (const float*)d_in[21];
    const float* lnfg    = (const float*)d_in[22];
    const float* lnfb    = (const float*)d_in[23];
    const float* predw   = (const float*)d_in[24];
    const float* predb   = (const float*)d_in[25];
    float* out = (float*)d_out;

    float *h, *qkv, *partial;
    __nv_bfloat16 *xhi, *xlo, *ahi, *alo, *fhi, *flo, *whi, *wlo;
    cudaGetSymbolAddress((void**)&h,    g_h);
    cudaGetSymbolAddress((void**)&qkv,  g_qkv);
    cudaGetSymbolAddress((void**)&partial, g_partial);
    cudaGetSymbolAddress((void**)&xhi,  g_xhi);
    cudaGetSymbolAddress((void**)&xlo,  g_xlo);
    cudaGetSymbolAddress((void**)&ahi,  g_ahi);
    cudaGetSymbolAddress((void**)&alo,  g_alo);
    cudaGetSymbolAddress((void**)&fhi,  g_fhi);
    cudaGetSymbolAddress((void**)&flo,  g_flo);
    cudaGetSymbolAddress((void**)&whi,  g_whi);
    cudaGetSymbolAddress((void**)&wlo,  g_wlo);

    cudaFuncSetAttribute(attn_flash, cudaFuncAttributeMaxDynamicSharedMemorySize, ATTN_SMEM);
    cudaFuncSetAttribute(gemm_mma64, cudaFuncAttributeMaxDynamicSharedMemorySize, GEMM2_SMEM);

    const size_t WPL = 12582912;
    const size_t OFF_QKV = 0, OFF_PROJ = 3145728, OFF_FC = 4194304, OFF_MP = 8388608;
    wprep_kernel<<<dim3(3 * D_ / 32, D_ / 32, NL_), dim3(32, 8)>>>(
        attnw, whi + OFF_QKV, wlo + OFF_QKV, D_, 3 * D_, (size_t)D_ * 3 * D_, WPL);
    wprep_kernel<<<dim3(D_ / 32, D_ / 32, NL_), dim3(32, 8)>>>(
        apw, whi + OFF_PROJ, wlo + OFF_PROJ, D_, D_, (size_t)D_ * D_, WPL);
    wprep_kernel<<<dim3(DFF_ / 32, D_ / 32, NL_), dim3(32, 8)>>>(
        fcw, whi + OFF_FC, wlo + OFF_FC, D_, DFF_, (size_t)D_ * DFF_, WPL);
    wprep_kernel<<<dim3(D_ / 32, DFF_ / 32, NL_), dim3(32, 8)>>>(
        mpw, whi + OFF_MP, wlo + OFF_MP, DFF_, D_, (size_t)DFF_ * D_, WPL);

    embed_kernel<<<NTOK, 256>>>(states, actions, rewards, qstates, wpe,
                                e_state, e_act, erw, erb, h);

    for (int i = 0; i < NL_; i++) {
        size_t off = (size_t)i * WPL;
        ln_kernel<<<NTOK, 256>>>(h, xhi, xlo, ln1g + i * D_, ln1b + i * D_);
        launch_gemm64(xhi, xlo, whi + off + OFF_QKV, wlo + off + OFF_QKV,
                      attnb + i * 3 * D_, qkv, nullptr, nullptr, NTOK, 3 * D_, D_, 0);
        attn_flash<<<B_ * H_, 256, ATTN_SMEM>>>(qkv, ahi, alo);
        launch_gemm64(ahi, alo, whi + off + OFF_PROJ, wlo + off + OFF_PROJ,
                      apb + i * D_, h, nullptr, nullptr, NTOK, D_, D_, 2);
        ln_kernel<<<NTOK, 256>>>(h, xhi, xlo, ln2g + i * D_, ln2b + i * D_);
        launch_gemm64(xhi, xlo, whi + off + OFF_FC, wlo + off + OFF_FC,
                      fcb + i * DFF_, nullptr, fhi, flo, NTOK, DFF_, D_, 1);
        launch_gemm64(fhi, flo, whi + off + OFF_MP, wlo + off + OFF_MP,
                      mpb + i * D_, h, nullptr, nullptr, NTOK, D_, DFF_, 2);
    }

    loss_kernel<<<NPOS, 128>>>(h, lnfg, lnfb, predw, predb, actions, tact, partial);
    reduce_kernel<<<1, 256>>>(partial, out);
}

// round 12
// speedup vs baseline: 3.9300x; 1.0173x over previous
#include <cuda_runtime.h>
#include <cuda_bf16.h>
#include <math.h>
#include <stdint.h>

#define B_    16
#define CTX_  100
#define LSEQ  301
#define D_    1024
#define H_    16
#define HD_   64
#define NL_   4
#define DFF_  4096
#define GRID_ 9
#define NA_   5
#define NTOK  (B_*LSEQ)
#define NPOS  (B_*(CTX_+1))
#define WPOOL 50331648

__device__ float g_h   [NTOK * D_];
__device__ float g_qkv [NTOK * 3 * D_];
__device__ __nv_bfloat16 g_xhi[NTOK * D_];
__device__ __nv_bfloat16 g_xlo[NTOK * D_];
__device__ __nv_bfloat16 g_ahi[NTOK * D_];
__device__ __nv_bfloat16 g_alo[NTOK * D_];
__device__ __nv_bfloat16 g_fhi[NTOK * DFF_];
__device__ __nv_bfloat16 g_flo[NTOK * DFF_];
__device__ __nv_bfloat16 g_whi[WPOOL];
__device__ __nv_bfloat16 g_wlo[WPOOL];
__device__ float g_partial[NPOS * 2];

#define CP16(d, s, z)  asm volatile("cp.async.cg.shared.global [%0], [%1], 16, %2;" :: "r"(d), "l"(s), "r"(z) : "memory")
#define CP_COMMIT()    asm volatile("cp.async.commit_group;" ::: "memory")
#define CP_WAIT(n)     asm volatile("cp.async.wait_group %0;" :: "n"(n) : "memory")
#define SWZ128(o) ((o) ^ (((o) >> 3) & 0x70))

__device__ __forceinline__ uint32_t smem_u32(const void* p) {
    uint32_t a;
    asm("{ .reg .u64 t; cvta.to.shared.u64 t, %1; cvt.u32.u64 %0, t; }" : "=r"(a) : "l"(p));
    return a;
}
__device__ __forceinline__ void ldsm4(uint32_t* r, uint32_t addr) {
    asm volatile("ldmatrix.sync.aligned.m8n8.x4.shared.b16 {%0,%1,%2,%3}, [%4];"
                 : "=r"(r[0]), "=r"(r[1]), "=r"(r[2]), "=r"(r[3]) : "r"(addr));
}
__device__ __forceinline__ void ldsm4t(uint32_t* r, uint32_t addr) {
    asm volatile("ldmatrix.sync.aligned.m8n8.x4.trans.shared.b16 {%0,%1,%2,%3}, [%4];"
                 : "=r"(r[0]), "=r"(r[1]), "=r"(r[2]), "=r"(r[3]) : "r"(addr));
}
__device__ __forceinline__ void mma16816(float* c, const uint32_t* a, const uint32_t* b) {
    asm volatile("mma.sync.aligned.m16n8k16.row.col.f32.bf16.bf16.f32 "
                 "{%0,%1,%2,%3}, {%4,%5,%6,%7}, {%8,%9}, {%0,%1,%2,%3};"
                 : "+f"(c[0]), "+f"(c[1]), "+f"(c[2]), "+f"(c[3])
                 : "r"(a[0]), "r"(a[1]), "r"(a[2]), "r"(a[3]), "r"(b[0]), "r"(b[1]));
}
__device__ __forceinline__ void pack_hilo(float x, float y, uint32_t& hi, uint32_t& lo) {
    __nv_bfloat16 xh = __float2bfloat16(x), yh = __float2bfloat16(y);
    __nv_bfloat162 hv; hv.x = xh; hv.y = yh;
    __nv_bfloat162 lv;
    lv.x = __float2bfloat16(x - __bfloat162float(xh));
    lv.y = __float2bfloat16(y - __bfloat162float(yh));
    hi = *(uint32_t*)&hv; lo = *(uint32_t*)&lv;
}

__device__ __forceinline__ float gelu_new(float xv) {
    float t = tanhf(0.7978845608028654f * (xv + 0.044715f * xv * xv * xv));
    return 0.5f * xv * (1.f + t);
}

// ---------------- embedding ----------------
__global__ void embed_kernel(const int* __restrict__ states,
                             const int* __restrict__ actions,
                             const float* __restrict__ rewards,
                             const int* __restrict__ qstates,
                             const float* __restrict__ wpe,
                             const float* __restrict__ e_state,
                             const float* __restrict__ e_act,
                             const float* __restrict__ erw,
                             const float* __restrict__ erb,
                             float* __restrict__ h)
{
    int tok = blockIdx.x;
    int b = tok / LSEQ, p = tok % LSEQ;
    const float* src = nullptr;
    float r = 0.f;
    int type = 0;
    if (p == 3 * CTX_) {
        int q = qstates[b * 2] * GRID_ + qstates[b * 2 + 1];
        src = e_state + (size_t)q * D_;
    } else {
        int t = p / 3, m = p % 3;
        if (m == 0) {
            int sid = states[(b * CTX_ + t) * 2] * GRID_ + states[(b * CTX_ + t) * 2 + 1];
            src = e_state + (size_t)sid * D_;
        } else if (m == 1) {
            src = e_act + (size_t)actions[b * CTX_ + t] * D_;
        } else {
            r = rewards[b * CTX_ + t];
            type = 1;
        }
    }
    for (int c = threadIdx.x; c < D_; c += blockDim.x) {
        float v = (type == 0) ? src[c] : fmaf(r, erw[c], erb[c]);
        h[(size_t)tok * D_ + c] = v + wpe[(size_t)p * D_ + c];
    }
}

// ---------------- weight transpose + split, vectorized writes ----------------
// block: 32 n x 64 k; each thread writes bf16x2 pairs (32-bit stores)
__global__ void wprep_kernel(const float* __restrict__ W,
                             __nv_bfloat16* __restrict__ Thi,
                             __nv_bfloat16* __restrict__ Tlo,
                             int K, int N, size_t sstride, size_t dstride)
{
    __shared__ float t[64][33];
    const float* Wz = W + (size_t)blockIdx.z * sstride;
    __nv_bfloat16* Th = Thi + (size_t)blockIdx.z * dstride;
    __nv_bfloat16* Tl = Tlo + (size_t)blockIdx.z * dstride;
    int n = blockIdx.x * 32 + threadIdx.x;
    int k0 = blockIdx.y * 64;
#pragma unroll
    for (int r = 0; r < 64; r += 8)
        t[threadIdx.y + r][threadIdx.x] = Wz[(size_t)(k0 + threadIdx.y + r) * N + n];
    __syncthreads();
    int kp = k0 + 2 * threadIdx.x;
#pragma unroll
    for (int r = 0; r < 32; r += 8) {
        int nn = blockIdx.x * 32 + threadIdx.y + r;
        float v0 = t[2 * threadIdx.x][threadIdx.y + r];
        float v1 = t[2 * threadIdx.x + 1][threadIdx.y + r];
        uint32_t hi, lo;
        pack_hilo(v0, v1, hi, lo);
        *(uint32_t*)&Th[(size_t)nn * K + kp] = hi;
        *(uint32_t*)&Tl[(size_t)nn * K + kp] = lo;
    }
}

// ---------------- LayerNorm -> hi/lo ----------------
__global__ void ln_kernel(const float* __restrict__ in,
                          __nv_bfloat16* __restrict__ ohi,
                          __nv_bfloat16* __restrict__ olo,
                          const float* __restrict__ g, const float* __restrict__ beta)
{
    __shared__ float red[8];
    int row = blockIdx.x;
    const float* x = in + (size_t)row * D_;
    int tid = threadIdx.x;
    float v[4];
    float s = 0.f;
#pragma unroll
    for (int i = 0; i < 4; i++) { v[i] = x[tid + 256 * i]; s += v[i]; }
#pragma unroll
    for (int o = 16; o; o >>= 1) s += __shfl_xor_sync(0xFFFFFFFFu, s, o);
    if ((tid & 31) == 0) red[tid >> 5] = s;
    __syncthreads();
    float mean = (red[0]+red[1]+red[2]+red[3]+red[4]+red[5]+red[6]+red[7]) * (1.f/1024.f);
    __syncthreads();
    float s2 = 0.f;
#pragma unroll
    for (int i = 0; i < 4; i++) { float d = v[i] - mean; s2 += d * d; }
#pragma unroll
    for (int o = 16; o; o >>= 1) s2 += __shfl_xor_sync(0xFFFFFFFFu, s2, o);
    if ((tid & 31) == 0) red[tid >> 5] = s2;
    __syncthreads();
    float var = (red[0]+red[1]+red[2]+red[3]+red[4]+red[5]+red[6]+red[7]) * (1.f/1024.f);
    float inv = 1.f / sqrtf(var + 1e-5f);
#pragma unroll
    for (int i = 0; i < 4; i++) {
        int c = tid + 256 * i;
        float y = (v[i] - mean) * inv * g[c] + beta[c];
        __nv_bfloat16 hi = __float2bfloat16(y);
        ohi[(size_t)row * D_ + c] = hi;
        olo[(size_t)row * D_ + c] = __float2bfloat16(y - __bfloat162float(hi));
    }
}

// ---------------- GEMM 128x64, 2-stage, 2 CTA/SM (all GEMMs) ----------------
#define BM 128
#define BK 64
#define TILE_A2 (128 * 128)
#define TILE_B2 (64 * 128)
#define STAGE_B2 (2 * TILE_A2 + 2 * TILE_B2)
#define GEMM2_SMEM (2 * STAGE_B2)
#define LDS2_ 68

__global__ void __launch_bounds__(256, 2)
gemm_mma64(const __nv_bfloat16* __restrict__ Ahi, const __nv_bfloat16* __restrict__ Alo,
           const __nv_bfloat16* __restrict__ Bhi, const __nv_bfloat16* __restrict__ Blo,
           const float* __restrict__ bias, float* __restrict__ C,
           __nv_bfloat16* __restrict__ Chi, __nv_bfloat16* __restrict__ Clo,
           int M, int N, int K, int mode)
{
    extern __shared__ __align__(128) char smem[];
    uint32_t sbase = smem_u32(smem);
    int tid = threadIdx.x, wid = tid >> 5, lane = tid & 31;
    int m0 = blockIdx.y * BM, n0 = blockIdx.x * 64;
    int wm = wid >> 2, wn = wid & 3;

    uint32_t soA[4], soB[2];
    unsigned ao[4], bo[2], szA[4];
#pragma unroll
    for (int i = 0; i < 4; i++) {
        int c = tid + 256 * i;
        int r = c >> 3, gb = c & 7;
        soA[i] = (uint32_t)SWZ128(r * 128 + gb * 16);
        bool ok = (m0 + r) < M;
        ao[i] = ok ? ((unsigned)(m0 + r) * (unsigned)K + gb * 8) : 0u;
        szA[i] = ok ? 16u : 0u;
    }
#pragma unroll
    for (int i = 0; i < 2; i++) {
        int c = tid + 256 * i;
        int r = c >> 3, gb = c & 7;
        soB[i] = (uint32_t)SWZ128(r * 128 + gb * 16);
        bo[i] = (unsigned)(n0 + r) * (unsigned)K + gb * 8;
    }
    const int nk = K / BK;

    auto load_tile = [&](int kt) {
        uint32_t st = sbase + (uint32_t)(kt & 1) * STAGE_B2;
        unsigned ko = (unsigned)kt * BK;
#pragma unroll
        for (int i = 0; i < 4; i++) {
            CP16(st + soA[i],           Ahi + ao[i] + ko, szA[i]);
            CP16(st + TILE_A2 + soA[i], Alo + ao[i] + ko, szA[i]);
        }
#pragma unroll
        for (int i = 0; i < 2; i++) {
            CP16(st + 2*TILE_A2 + soB[i],            Bhi + bo[i] + ko, 16u);
            CP16(st + 2*TILE_A2 + TILE_B2 + soB[i],  Blo + bo[i] + ko, 16u);
        }
    };

    int a_row_loc = ((lane >> 3) & 1) * 8 + (lane & 7);
    int a_kh = (lane >> 4) * 16;
    int b_row_loc = (lane >> 4) * 8 + (lane & 7);
    int b_kh = ((lane >> 3) & 1) * 16;

    float acc[4][2][4];
#pragma unroll
    for (int i = 0; i < 4; i++)
#pragma unroll
        for (int j = 0; j < 2; j++)
#pragma unroll
            for (int k = 0; k < 4; k++) acc[i][j][k] = 0.f;

    load_tile(0);
    CP_COMMIT();
    if (nk > 1) load_tile(1);
    CP_COMMIT();

    uint32_t a_base[4];
    int a_ph[4];
#pragma unroll
    for (int mt = 0; mt < 4; mt++) {
        int row = wm * 64 + mt * 16 + a_row_loc;
        a_base[mt] = (uint32_t)(row * 128);
        a_ph[mt] = (row & 7) << 4;
    }
    int brow = wn * 16 + b_row_loc;
    uint32_t b_base = (uint32_t)(brow * 128);
    int b_ph = (brow & 7) << 4;

    for (int kt = 0; kt < nk; kt++) {
        CP_WAIT(1);
        __syncthreads();
        uint32_t st = sbase + (uint32_t)(kt & 1) * STAGE_B2;
        uint32_t stA = st, stAl = st + TILE_A2;
        uint32_t stB = st + 2*TILE_A2, stBl = st + 2*TILE_A2 + TILE_B2;
#pragma unroll
        for (int ks = 0; ks < 4; ks++) {
            uint32_t ah[4][4], al[4][4], bh[4], bl[4];
            {
                uint32_t off = b_base + (uint32_t)((ks * 32 + b_kh) ^ b_ph);
                ldsm4(bh, stB + off);
                ldsm4(bl, stBl + off);
            }
#pragma unroll
            for (int mt = 0; mt < 4; mt++) {
                uint32_t off = a_base[mt] + (uint32_t)((ks * 32 + a_kh) ^ a_ph[mt]);
                ldsm4(ah[mt], stA + off);
                ldsm4(al[mt], stAl + off);
            }
#pragma unroll
            for (int mt = 0; mt < 4; mt++)
#pragma unroll
                for (int nt = 0; nt < 2; nt++) {
                    const uint32_t* bph = &bh[nt * 2];
                    const uint32_t* bpl = &bl[nt * 2];
                    mma16816(acc[mt][nt], ah[mt], bph);
                    mma16816(acc[mt][nt], ah[mt], bpl);
                    mma16816(acc[mt][nt], al[mt], bph);
                }
        }
        __syncthreads();
        if (kt + 2 < nk) load_tile(kt + 2);
        CP_COMMIT();
    }
    CP_WAIT(0);
    __syncthreads();

    float* stg = (float*)smem;
    int cr = lane >> 2, ccol = (lane & 3) * 2;
#pragma unroll
    for (int mt = 0; mt < 4; mt++)
#pragma unroll
        for (int nt = 0; nt < 2; nt++) {
            int r = wm * 64 + mt * 16 + cr;
            int cl = wn * 16 + nt * 8 + ccol;
            *(float2*)&stg[r * LDS2_ + cl]       = make_float2(acc[mt][nt][0], acc[mt][nt][1]);
            *(float2*)&stg[(r + 8) * LDS2_ + cl] = make_float2(acc[mt][nt][2], acc[mt][nt][3]);
        }
    __syncthreads();

#pragma unroll
    for (int i = 0; i < 8; i++) {
        int id = tid + 256 * i;
        int r = id >> 4, cc = (id & 15) * 4;
        int m = m0 + r;
        if (m < M) {
            int n = n0 + cc;
            float4 v = *(float4*)&stg[r * LDS2_ + cc];
            float4 bs = *(const float4*)&bias[n];
            v.x += bs.x; v.y += bs.y; v.z += bs.z; v.w += bs.w;
            size_t idx = (size_t)m * N + n;
            if (mode == 0) {
                *(float4*)&C[idx] = v;
            } else if (mode == 1) {
                float g0 = gelu_new(v.x), g1 = gelu_new(v.y);
                float g2 = gelu_new(v.z), g3 = gelu_new(v.w);
                uint32_t h01, l01, h23, l23;
                pack_hilo(g0, g1, h01, l01);
                pack_hilo(g2, g3, h23, l23);
                *(uint2*)&Chi[idx] = make_uint2(h01, h23);
                *(uint2*)&Clo[idx] = make_uint2(l01, l23);
            } else {
                float4 c0 = *(float4*)&C[idx];
                c0.x += v.x; c0.y += v.y; c0.z += v.z; c0.w += v.w;
                *(float4*)&C[idx] = c0;
            }
        }
    }
}

// ---------------- flash attention (split-bf16 mma, 16 warps) ----------------
#define AKHI 0
#define AKLO 38912
#define AVHI 77824
#define AVLO 116736
#define ATTN_SMEM 155648

__global__ void __launch_bounds__(512)
attn_flash(const float* __restrict__ qkv,
           __nv_bfloat16* __restrict__ ohi, __nv_bfloat16* __restrict__ olo)
{
    extern __shared__ __align__(128) char asmem[];
    uint32_t sb = smem_u32(asmem);
    int tid = threadIdx.x;
    int bh = blockIdx.x, b = bh >> 4, hd = bh & 15;
    const float* base = qkv + (size_t)b * LSEQ * 3072;
    int hoff = hd * 64;

    for (int idx = tid; idx < 304 * 64; idx += 512) {
        int j = idx >> 6, d = idx & 63;
        float kv = 0.f, vv = 0.f;
        if (j < LSEQ) {
            kv = base[(size_t)j * 3072 + 1024 + hoff + d];
            vv = base[(size_t)j * 3072 + 2048 + hoff + d];
        }
        uint32_t off = (uint32_t)SWZ128(j * 128 + d * 2);
        __nv_bfloat16 kh = __float2bfloat16(kv);
        *(__nv_bfloat16*)(asmem + AKHI + off) = kh;
        *(__nv_bfloat16*)(asmem + AKLO + off) = __float2bfloat16(kv - __bfloat162float(kh));
        __nv_bfloat16 vh = __float2bfloat16(vv);
        *(__nv_bfloat16*)(asmem + AVHI + off) = vh;
        *(__nv_bfloat16*)(asmem + AVLO + off) = __float2bfloat16(vv - __bfloat162float(vh));
    }
    __syncthreads();

    int w = tid >> 5, lane = tid & 31;
    int g = lane >> 2, t4 = lane & 3;
    int kb_row = (lane >> 4) * 8 + (lane & 7);
    int kb_kb  = ((lane >> 3) & 1) * 16;
    int vb_row = ((lane >> 3) & 1) * 8 + (lane & 7);
    int vb_nb  = (lane >> 4) * 16;

    // LPT over 16 warps: pass 0 -> qt = 18 - w (w=0..15 -> 18..3);
    // pass 1 -> warps 15,14,13 take qt 2,1,0.
    for (int qi = 0; qi < 2; qi++) {
        int qt;
        if (qi == 0) qt = 18 - w;
        else qt = (w == 15) ? 2 : (w == 14) ? 1 : (w == 13) ? 0 : -1;
        if (qt < 0) continue;
        int q0 = qt * 16;

        uint32_t qh[4][4], ql[4][4];
        int r1 = q0 + g;       int r1c = r1 < LSEQ ? r1 : LSEQ - 1;
        int r2 = r1 + 8;       int r2c = r2 < LSEQ ? r2 : LSEQ - 1;
        const float* q1p = base + (size_t)r1c * 3072 + hoff;
        const float* q2p = base + (size_t)r2c * 3072 + hoff;
#pragma unroll
        for (int kt = 0; kt < 4; kt++) {
            int c0 = kt * 16 + 2 * t4;
            float2 x0 = *(const float2*)(q1p + c0);
            float2 x1 = *(const float2*)(q2p + c0);
            float2 x2 = *(const float2*)(q1p + c0 + 8);
            float2 x3 = *(const float2*)(q2p + c0 + 8);
            pack_hilo(x0.x, x0.y, qh[kt][0], ql[kt][0]);
            pack_hilo(x1.x, x1.y, qh[kt][1], ql[kt][1]);
            pack_hilo(x2.x, x2.y, qh[kt][2], ql[kt][2]);
            pack_hilo(x3.x, x3.y, qh[kt][3], ql[kt][3]);
        }

        float m0 = -1e30f, m1 = -1e30f, l0 = 0.f, l1 = 0.f;
        float o[8][4];
#pragma unroll
        for (int i = 0; i < 8; i++)
#pragma unroll
            for (int k = 0; k < 4; k++) o[i][k] = 0.f;

        for (int jt = 0; jt <= qt; jt++) {
            float s[2][4] = {{0,0,0,0},{0,0,0,0}};
#pragma unroll
            for (int kt = 0; kt < 4; kt++) {
                int row = jt * 16 + kb_row;
                uint32_t off = (uint32_t)(row * 128 + ((kt * 32 + kb_kb) ^ ((row & 7) << 4)));
                uint32_t kh4[4], kl4[4];
                ldsm4(kh4, sb + AKHI + off);
                ldsm4(kl4, sb + AKLO + off);
#pragma unroll
                for (int nt = 0; nt < 2; nt++) {
                    mma16816(s[nt], qh[kt], &kh4[nt*2]);
                    mma16816(s[nt], qh[kt], &kl4[nt*2]);
                    mma16816(s[nt], ql[kt], &kh4[nt*2]);
                }
            }
            int qr1 = q0 + g, qr2 = qr1 + 8;
#pragma unroll
            for (int nt = 0; nt < 2; nt++) {
                int jc = jt * 16 + nt * 8 + 2 * t4;
                s[nt][0] = (jc     <= qr1) ? s[nt][0] * 0.125f : -1e30f;
                s[nt][1] = (jc + 1 <= qr1) ? s[nt][1] * 0.125f : -1e30f;
                s[nt][2] = (jc     <= qr2) ? s[nt][2] * 0.125f : -1e30f;
                s[nt][3] = (jc + 1 <= qr2) ? s[nt][3] * 0.125f : -1e30f;
            }
            float tm0 = fmaxf(fmaxf(s[0][0], s[0][1]), fmaxf(s[1][0], s[1][1]));
            float tm1 = fmaxf(fmaxf(s[0][2], s[0][3]), fmaxf(s[1][2], s[1][3]));
            tm0 = fmaxf(tm0, __shfl_xor_sync(0xFFFFFFFFu, tm0, 1));
            tm0 = fmaxf(tm0, __shfl_xor_sync(0xFFFFFFFFu, tm0, 2));
            tm1 = fmaxf(tm1, __shfl_xor_sync(0xFFFFFFFFu, tm1, 1));
            tm1 = fmaxf(tm1, __shfl_xor_sync(0xFFFFFFFFu, tm1, 2));
            float mn0 = fmaxf(m0, tm0), mn1 = fmaxf(m1, tm1);
            float sc0 = __expf(m0 - mn0), sc1 = __expf(m1 - mn1);
            m0 = mn0; m1 = mn1;
            float p[2][4];
#pragma unroll
            for (int nt = 0; nt < 2; nt++) {
                p[nt][0] = __expf(s[nt][0] - mn0);
                p[nt][1] = __expf(s[nt][1] - mn0);
                p[nt][2] = __expf(s[nt][2] - mn1);
                p[nt][3] = __expf(s[nt][3] - mn1);
            }
            float ts0 = p[0][0] + p[0][1] + p[1][0] + p[1][1];
            float ts1 = p[0][2] + p[0][3] + p[1][2] + p[1][3];
            ts0 += __shfl_xor_sync(0xFFFFFFFFu, ts0, 1);
            ts0 += __shfl_xor_sync(0xFFFFFFFFu, ts0, 2);
            ts1 += __shfl_xor_sync(0xFFFFFFFFu, ts1, 1);
            ts1 += __shfl_xor_sync(0xFFFFFFFFu, ts1, 2);
            l0 = l0 * sc0 + ts0;
            l1 = l1 * sc1 + ts1;
            bool need = __any_sync(0xFFFFFFFFu, (sc0 != 1.f) || (sc1 != 1.f));
            if (need) {
#pragma unroll
                for (int nt = 0; nt < 8; nt++) {
                    o[nt][0] *= sc0; o[nt][1] *= sc0; o[nt][2] *= sc1; o[nt][3] *= sc1;
                }
            }
            uint32_t pah[4], pal[4];
            pack_hilo(p[0][0], p[0][1], pah[0], pal[0]);
            pack_hilo(p[0][2], p[0][3], pah[1], pal[1]);
            pack_hilo(p[1][0], p[1][1], pah[2], pal[2]);
            pack_hilo(p[1][2], p[1][3], pah[3], pal[3]);
#pragma unroll
            for (int dt = 0; dt < 4; dt++) {
                int row = jt * 16 + vb_row;
                uint32_t off = (uint32_t)(row * 128 + ((dt * 32 + vb_nb) ^ ((row & 7) << 4)));
                uint32_t vh4[4], vl4[4];
                ldsm4t(vh4, sb + AVHI + off);
                ldsm4t(vl4, sb + AVLO + off);
#pragma unroll
                for (int su = 0; su < 2; su++) {
                    int nt = dt * 2 + su;
                    mma16816(o[nt], pah, &vh4[su*2]);
                    mma16816(o[nt], pah, &vl4[su*2]);
                    mma16816(o[nt], pal, &vh4[su*2]);
                }
            }
        }
        float inv0 = 1.f / l0, inv1 = 1.f / l1;
        int row1 = q0 + g, row2 = row1 + 8;
#pragma unroll
        for (int nt = 0; nt < 8; nt++) {
            int col = nt * 8 + 2 * t4;
            if (row1 < LSEQ) {
                uint32_t hp, lp;
                pack_hilo(o[nt][0] * inv0, o[nt][1] * inv0, hp, lp);
                size_t idx = (size_t)(b * LSEQ + row1) * D_ + hoff + col;
                *(uint32_t*)&ohi[idx] = hp;
                *(uint32_t*)&olo[idx] = lp;
            }
            if (row2 < LSEQ) {
                uint32_t hp, lp;
                pack_hilo(o[nt][2] * inv1, o[nt][3] * inv1, hp, lp);
                size_t idx = (size_t)(b * LSEQ + row2) * D_ + hoff + col;
                *(uint32_t*)&ohi[idx] = hp;
                *(uint32_t*)&olo[idx] = lp;
            }
        }
    }
}

// ---------------- loss ----------------
__global__ void loss_kernel(const float* __restrict__ h,
                            const float* __restrict__ g,
                            const float* __restrict__ beta,
                            const float* __restrict__ pw,
                            const float* __restrict__ pb,
                            const int* __restrict__ actions,
                            const int* __restrict__ tact,
                            float* __restrict__ partial)
{
    __shared__ float red[4];
    __shared__ float lred[5][4];
    int idx = blockIdx.x;
    int b = idx / (CTX_ + 1), t = idx % (CTX_ + 1);
    const float* x = h + (size_t)(b * LSEQ + 3 * t) * D_;
    int tid = threadIdx.x, lane = tid & 31, w = tid >> 5;

    float v[8];
    float s = 0.f;
#pragma unroll
    for (int i = 0; i < 8; i++) { v[i] = x[tid + 128 * i]; s += v[i]; }
#pragma unroll
    for (int o = 16; o; o >>= 1) s += __shfl_xor_sync(0xFFFFFFFFu, s, o);
    if (lane == 0) red[w] = s;
    __syncthreads();
    float mean = (red[0] + red[1] + red[2] + red[3]) * (1.f / 1024.f);
    __syncthreads();
    float s2 = 0.f;
#pragma unroll
    for (int i = 0; i < 8; i++) { float d = v[i] - mean; s2 += d * d; }
#pragma unroll
    for (int o = 16; o; o >>= 1) s2 += __shfl_xor_sync(0xFFFFFFFFu, s2, o);
    if (lane == 0) red[w] = s2;
    __syncthreads();
    float var = (red[0] + red[1] + red[2] + red[3]) * (1.f / 1024.f);
    float inv = 1.f / sqrtf(var + 1e-5f);

    float acc[NA_] = {0.f, 0.f, 0.f, 0.f, 0.f};
#pragma unroll
    for (int i = 0; i < 8; i++) {
        int c = tid + 128 * i;
        float xn = (v[i] - mean) * inv * g[c] + beta[c];
#pragma unroll
        for (int a = 0; a < NA_; a++)
            acc[a] = fmaf(xn, pw[c * NA_ + a], acc[a]);
    }
#pragma unroll
    for (int a = 0; a < NA_; a++) {
        float tv = acc[a];
#pragma unroll
        for (int o = 16; o; o >>= 1) tv += __shfl_xor_sync(0xFFFFFFFFu, tv, o);
        if (lane == 0) lred[a][w] = tv;
    }
    __syncthreads();
    if (tid == 0) {
        float logit[NA_];
#pragma unroll
        for (int a = 0; a < NA_; a++)
            logit[a] = lred[a][0] + lred[a][1] + lred[a][2] + lred[a][3] + pb[a];
        int target = (t < CTX_) ? actions[b * CTX_ + t] : tact[b];
        float mx = logit[0]; int am = 0;
#pragma unroll
        for (int a = 1; a < NA_; a++) if (logit[a] > mx) { mx = logit[a]; am = a; }
        float se = 0.f;
#pragma unroll
        for (int a = 0; a < NA_; a++) se += expf(logit[a] - mx);
        float lse = mx + logf(se);
        float sl = 0.f;
#pragma unroll
        for (int a = 0; a < NA_; a++) sl += (logit[a] - lse);
        float nll = -(logit[target] - lse);
        float smooth = -sl * (1.f / NA_);
        partial[2 * idx]     = 0.9f * nll + 0.1f * smooth;
        partial[2 * idx + 1] = (am == target) ? 1.f : 0.f;
    }
}

__global__ void reduce_kernel(const float* __restrict__ partial, float* __restrict__ out)
{
    __shared__ float rl[8], ra[8];
    int tid = threadIdx.x, lane = tid & 31, w = tid >> 5;
    float l = 0.f, a = 0.f;
    for (int i = tid; i < NPOS; i += 256) {
        l += partial[2 * i];
        a += partial[2 * i + 1];
    }
#pragma unroll
    for (int o = 16; o; o >>= 1) {
        l += __shfl_xor_sync(0xFFFFFFFFu, l, o);
        a += __shfl_xor_sync(0xFFFFFFFFu, a, o);
    }
    if (lane == 0) { rl[w] = l; ra[w] = a; }
    __syncthreads();
    if (tid == 0) {
        float L = 0.f, A = 0.f;
#pragma unroll
        for (int i = 0; i < 8; i++) { L += rl[i]; A += ra[i]; }
        out[0] = L * (1.f / NPOS);
        out[1] = A * (1.f / NPOS);
    }
}

// ---------------- host ----------------
static inline void launch_gemm64(const __nv_bfloat16* Ahi, const __nv_bfloat16* Alo,
                                 const __nv_bfloat16* Bhi, const __nv_bfloat16* Blo,
                                 const float* bias, float* C,
                                 __nv_bfloat16* Chi, __nv_bfloat16* Clo,
                                 int M, int N, int K, int mode)
{
    dim3 grid(N / 64, (M + BM - 1) / BM);
    gemm_mma64<<<grid, 256, GEMM2_SMEM>>>(Ahi, Alo, Bhi, Blo, bias, C, Chi, Clo, M, N, K, mode);
}

extern "C" void kernel_launch(void* const* d_in, const int* in_sizes, int n_in,
                              void* d_out, int out_size)
{
    const int*   states  = (const int*)  d_in[0];
    const int*   actions = (const int*)  d_in[1];
    const float* rewards = (const float*)d_in[2];
    const int*   qstates = (const int*)  d_in[3];
    const int*   tact    = (const int*)  d_in[4];
    const float* wpe     = (const float*)d_in[5];
    const float* e_state = (const float*)d_in[6];
    const float* e_act   = (const float*)d_in[7];
    const float* erw     = (const float*)d_in[8];
    const float* erb     = (const float*)d_in[9];
    const float* ln1g    = (const float*)d_in[10];
    const float* ln1b    = (const float*)d_in[11];
    const float* attnw   = (const float*)d_in[12];
    const float* attnb   = (const float*)d_in[13];
    const float* apw     = (const float*)d_in[14];
    const float* apb     = (const float*)d_in[15];
    const float* ln2g    = (const float*)d_in[16];
    const float* ln2b    = (const float*)d_in[17];
    const float* fcw     = (const float*)d_in[18];
    const float* fcb     = (const float*)d_in[19];
    const float* mpw     = (const float*)d_in[20];
    const float* mpb     = (const float*)d_in[21];
    const float* lnfg    = (const float*)d_in[22];
    const float* lnfb    = (const float*)d_in[23];
    const float* predw   = (const float*)d_in[24];
    const float* predb   = (const float*)d_in[25];
    float* out = (float*)d_out;

    float *h, *qkv, *partial;
    __nv_bfloat16 *xhi, *xlo, *ahi, *alo, *fhi, *flo, *whi, *wlo;
    cudaGetSymbolAddress((void**)&h,    g_h);
    cudaGetSymbolAddress((void**)&qkv,  g_qkv);
    cudaGetSymbolAddress((void**)&partial, g_partial);
    cudaGetSymbolAddress((void**)&xhi,  g_xhi);
    cudaGetSymbolAddress((void**)&xlo,  g_xlo);
    cudaGetSymbolAddress((void**)&ahi,  g_ahi);
    cudaGetSymbolAddress((void**)&alo,  g_alo);
    cudaGetSymbolAddress((void**)&fhi,  g_fhi);
    cudaGetSymbolAddress((void**)&flo,  g_flo);
    cudaGetSymbolAddress((void**)&whi,  g_whi);
    cudaGetSymbolAddress((void**)&wlo,  g_wlo);

    cudaFuncSetAttribute(attn_flash, cudaFuncAttributeMaxDynamicSharedMemorySize, ATTN_SMEM);
    cudaFuncSetAttribute(gemm_mma64, cudaFuncAttributeMaxDynamicSharedMemorySize, GEMM2_SMEM);

    const size_t WPL = 12582912;
    const size_t OFF_QKV = 0, OFF_PROJ = 3145728, OFF_FC = 4194304, OFF_MP = 8388608;
    wprep_kernel<<<dim3(3 * D_ / 32, D_ / 64, NL_), dim3(32, 8)>>>(
        attnw, whi + OFF_QKV, wlo + OFF_QKV, D_, 3 * D_, (size_t)D_ * 3 * D_, WPL);
    wprep_kernel<<<dim3(D_ / 32, D_ / 64, NL_), dim3(32, 8)>>>(
        apw, whi + OFF_PROJ, wlo + OFF_PROJ, D_, D_, (size_t)D_ * D_, WPL);
    wprep_kernel<<<dim3(DFF_ / 32, D_ / 64, NL_), dim3(32, 8)>>>(
        fcw, whi + OFF_FC, wlo + OFF_FC, D_, DFF_, (size_t)D_ * DFF_, WPL);
    wprep_kernel<<<dim3(D_ / 32, DFF_ / 64, NL_), dim3(32, 8)>>>(
        mpw, whi + OFF_MP, wlo + OFF_MP, DFF_, D_, (size_t)DFF_ * D_, WPL);

    embed_kernel<<<NTOK, 256>>>(states, actions, rewards, qstates, wpe,
                                e_state, e_act, erw, erb, h);

    for (int i = 0; i < NL_; i++) {
        size_t off = (size_t)i * WPL;
        ln_kernel<<<NTOK, 256>>>(h, xhi, xlo, ln1g + i * D_, ln1b + i * D_);
        launch_gemm64(xhi, xlo, whi + off + OFF_QKV, wlo + off + OFF_QKV,
                      attnb + i * 3 * D_, qkv, nullptr, nullptr, NTOK, 3 * D_, D_, 0);
        attn_flash<<<B_ * H_, 512, ATTN_SMEM>>>(qkv, ahi, alo);
        launch_gemm64(ahi, alo, whi + off + OFF_PROJ, wlo + off + OFF_PROJ,
                      apb + i * D_, h, nullptr, nullptr, NTOK, D_, D_, 2);
        ln_kernel<<<NTOK, 256>>>(h, xhi, xlo, ln2g + i * D_, ln2b + i * D_);
        launch_gemm64(xhi, xlo, whi + off + OFF_FC, wlo + off + OFF_FC,
                      fcb + i * DFF_, nullptr, fhi, flo, NTOK, DFF_, D_, 1);
        launch_gemm64(fhi, flo, whi + off + OFF_MP, wlo + off + OFF_MP,
                      mpb + i * D_, h, nullptr, nullptr, NTOK, D_, DFF_, 2);
    }

    loss_kernel<<<NPOS, 128>>>(h, lnfg, lnfb, predw, predb, actions, tact, partial);
    reduce_kernel<<<1, 256>>>(partial, out);
}

// round 13
// speedup vs baseline: 3.9467x; 1.0042x over previous
#include <cuda_runtime.h>
#include <cuda_bf16.h>
#include <math.h>
#include <stdint.h>

#define B_    16
#define CTX_  100
#define LSEQ  301
#define D_    1024
#define H_    16
#define HD_   64
#define NL_   4
#define DFF_  4096
#define GRID_ 9
#define NA_   5
#define NTOK  (B_*LSEQ)
#define NPOS  (B_*(CTX_+1))
#define WPOOL 50331648

__device__ float g_h   [NTOK * D_];
__device__ float g_qkv [NTOK * 3 * D_];
__device__ __nv_bfloat16 g_xhi[NTOK * D_];
__device__ __nv_bfloat16 g_xlo[NTOK * D_];
__device__ __nv_bfloat16 g_ahi[NTOK * D_];
__device__ __nv_bfloat16 g_alo[NTOK * D_];
__device__ __nv_bfloat16 g_fhi[NTOK * DFF_];
__device__ __nv_bfloat16 g_flo[NTOK * DFF_];
__device__ __nv_bfloat16 g_whi[WPOOL];
__device__ __nv_bfloat16 g_wlo[WPOOL];
__device__ float g_partial[NPOS * 2];

#define CP16(d, s, z)  asm volatile("cp.async.cg.shared.global [%0], [%1], 16, %2;" :: "r"(d), "l"(s), "r"(z) : "memory")
#define CP_COMMIT()    asm volatile("cp.async.commit_group;" ::: "memory")
#define CP_WAIT(n)     asm volatile("cp.async.wait_group %0;" :: "n"(n) : "memory")
#define SWZ128(o) ((o) ^ (((o) >> 3) & 0x70))

__device__ __forceinline__ uint32_t smem_u32(const void* p) {
    uint32_t a;
    asm("{ .reg .u64 t; cvta.to.shared.u64 t, %1; cvt.u32.u64 %0, t; }" : "=r"(a) : "l"(p));
    return a;
}
__device__ __forceinline__ void ldsm4(uint32_t* r, uint32_t addr) {
    asm volatile("ldmatrix.sync.aligned.m8n8.x4.shared.b16 {%0,%1,%2,%3}, [%4];"
                 : "=r"(r[0]), "=r"(r[1]), "=r"(r[2]), "=r"(r[3]) : "r"(addr));
}
__device__ __forceinline__ void ldsm4t(uint32_t* r, uint32_t addr) {
    asm volatile("ldmatrix.sync.aligned.m8n8.x4.trans.shared.b16 {%0,%1,%2,%3}, [%4];"
                 : "=r"(r[0]), "=r"(r[1]), "=r"(r[2]), "=r"(r[3]) : "r"(addr));
}
__device__ __forceinline__ void mma16816(float* c, const uint32_t* a, const uint32_t* b) {
    asm volatile("mma.sync.aligned.m16n8k16.row.col.f32.bf16.bf16.f32 "
                 "{%0,%1,%2,%3}, {%4,%5,%6,%7}, {%8,%9}, {%0,%1,%2,%3};"
                 : "+f"(c[0]), "+f"(c[1]), "+f"(c[2]), "+f"(c[3])
                 : "r"(a[0]), "r"(a[1]), "r"(a[2]), "r"(a[3]), "r"(b[0]), "r"(b[1]));
}
__device__ __forceinline__ void pack_hilo(float x, float y, uint32_t& hi, uint32_t& lo) {
    __nv_bfloat16 xh = __float2bfloat16(x), yh = __float2bfloat16(y);
    __nv_bfloat162 hv; hv.x = xh; hv.y = yh;
    __nv_bfloat162 lv;
    lv.x = __float2bfloat16(x - __bfloat162float(xh));
    lv.y = __float2bfloat16(y - __bfloat162float(yh));
    hi = *(uint32_t*)&hv; lo = *(uint32_t*)&lv;
}

__device__ __forceinline__ float gelu_new(float xv) {
    float t = tanhf(0.7978845608028654f * (xv + 0.044715f * xv * xv * xv));
    return 0.5f * xv * (1.f + t);
}

// ---------------- embedding (vectorized) ----------------
__global__ void embed_kernel(const int* __restrict__ states,
                             const int* __restrict__ actions,
                             const float* __restrict__ rewards,
                             const int* __restrict__ qstates,
                             const float* __restrict__ wpe,
                             const float* __restrict__ e_state,
                             const float* __restrict__ e_act,
                             const float* __restrict__ erw,
                             const float* __restrict__ erb,
                             float* __restrict__ h)
{
    int tok = blockIdx.x;
    int b = tok / LSEQ, p = tok % LSEQ;
    const float* src = nullptr;
    float r = 0.f;
    int type = 0;
    if (p == 3 * CTX_) {
        int q = qstates[b * 2] * GRID_ + qstates[b * 2 + 1];
        src = e_state + (size_t)q * D_;
    } else {
        int t = p / 3, m = p % 3;
        if (m == 0) {
            int sid = states[(b * CTX_ + t) * 2] * GRID_ + states[(b * CTX_ + t) * 2 + 1];
            src = e_state + (size_t)sid * D_;
        } else if (m == 1) {
            src = e_act + (size_t)actions[b * CTX_ + t] * D_;
        } else {
            r = rewards[b * CTX_ + t];
            type = 1;
        }
    }
    int c = threadIdx.x * 4;
    float4 wp = *(const float4*)&wpe[(size_t)p * D_ + c];
    float4 v;
    if (type == 0) {
        v = *(const float4*)&src[c];
    } else {
        float4 ew = *(const float4*)&erw[c];
        float4 eb = *(const float4*)&erb[c];
        v.x = fmaf(r, ew.x, eb.x); v.y = fmaf(r, ew.y, eb.y);
        v.z = fmaf(r, ew.z, eb.z); v.w = fmaf(r, ew.w, eb.w);
    }
    v.x += wp.x; v.y += wp.y; v.z += wp.z; v.w += wp.w;
    *(float4*)&h[(size_t)tok * D_ + c] = v;
}

// ---------------- weight transpose + split, vectorized ----------------
__global__ void wprep_kernel(const float* __restrict__ W,
                             __nv_bfloat16* __restrict__ Thi,
                             __nv_bfloat16* __restrict__ Tlo,
                             int K, int N, size_t sstride, size_t dstride)
{
    __shared__ float t[64][33];
    const float* Wz = W + (size_t)blockIdx.z * sstride;
    __nv_bfloat16* Th = Thi + (size_t)blockIdx.z * dstride;
    __nv_bfloat16* Tl = Tlo + (size_t)blockIdx.z * dstride;
    int n = blockIdx.x * 32 + threadIdx.x;
    int k0 = blockIdx.y * 64;
#pragma unroll
    for (int r = 0; r < 64; r += 8)
        t[threadIdx.y + r][threadIdx.x] = Wz[(size_t)(k0 + threadIdx.y + r) * N + n];
    __syncthreads();
    int kp = k0 + 2 * threadIdx.x;
#pragma unroll
    for (int r = 0; r < 32; r += 8) {
        int nn = blockIdx.x * 32 + threadIdx.y + r;
        float v0 = t[2 * threadIdx.x][threadIdx.y + r];
        float v1 = t[2 * threadIdx.x + 1][threadIdx.y + r];
        uint32_t hi, lo;
        pack_hilo(v0, v1, hi, lo);
        *(uint32_t*)&Th[(size_t)nn * K + kp] = hi;
        *(uint32_t*)&Tl[(size_t)nn * K + kp] = lo;
    }
}

// ---------------- LayerNorm -> hi/lo (vectorized) ----------------
__global__ void ln_kernel(const float* __restrict__ in,
                          __nv_bfloat16* __restrict__ ohi,
                          __nv_bfloat16* __restrict__ olo,
                          const float* __restrict__ g, const float* __restrict__ beta)
{
    __shared__ float red[8];
    int row = blockIdx.x;
    int tid = threadIdx.x;
    float4 v = *(const float4*)&in[(size_t)row * D_ + tid * 4];
    float s = (v.x + v.y) + (v.z + v.w);
#pragma unroll
    for (int o = 16; o; o >>= 1) s += __shfl_xor_sync(0xFFFFFFFFu, s, o);
    if ((tid & 31) == 0) red[tid >> 5] = s;
    __syncthreads();
    float mean = (red[0]+red[1]+red[2]+red[3]+red[4]+red[5]+red[6]+red[7]) * (1.f/1024.f);
    __syncthreads();
    float dx = v.x - mean, dy = v.y - mean, dz = v.z - mean, dw = v.w - mean;
    float s2 = (dx * dx + dy * dy) + (dz * dz + dw * dw);
#pragma unroll
    for (int o = 16; o; o >>= 1) s2 += __shfl_xor_sync(0xFFFFFFFFu, s2, o);
    if ((tid & 31) == 0) red[tid >> 5] = s2;
    __syncthreads();
    float var = (red[0]+red[1]+red[2]+red[3]+red[4]+red[5]+red[6]+red[7]) * (1.f/1024.f);
    float inv = 1.f / sqrtf(var + 1e-5f);
    int c = tid * 4;
    float4 gg = *(const float4*)&g[c];
    float4 bb = *(const float4*)&beta[c];
    float y0 = dx * inv * gg.x + bb.x;
    float y1 = dy * inv * gg.y + bb.y;
    float y2 = dz * inv * gg.z + bb.z;
    float y3 = dw * inv * gg.w + bb.w;
    uint32_t h01, l01, h23, l23;
    pack_hilo(y0, y1, h01, l01);
    pack_hilo(y2, y3, h23, l23);
    size_t idx = (size_t)row * D_ + c;
    *(uint2*)&ohi[idx] = make_uint2(h01, h23);
    *(uint2*)&olo[idx] = make_uint2(l01, l23);
}

// ---------------- GEMM 128x64, 2-stage, 2 CTA/SM (all GEMMs) ----------------
#define BM 128
#define BK 64
#define TILE_A2 (128 * 128)
#define TILE_B2 (64 * 128)
#define STAGE_B2 (2 * TILE_A2 + 2 * TILE_B2)
#define GEMM2_SMEM (2 * STAGE_B2)
#define LDS2_ 68

__global__ void __launch_bounds__(256, 2)
gemm_mma64(const __nv_bfloat16* __restrict__ Ahi, const __nv_bfloat16* __restrict__ Alo,
           const __nv_bfloat16* __restrict__ Bhi, const __nv_bfloat16* __restrict__ Blo,
           const float* __restrict__ bias, float* __restrict__ C,
           __nv_bfloat16* __restrict__ Chi, __nv_bfloat16* __restrict__ Clo,
           int M, int N, int K, int mode)
{
    extern __shared__ __align__(128) char smem[];
    uint32_t sbase = smem_u32(smem);
    int tid = threadIdx.x, wid = tid >> 5, lane = tid & 31;
    int m0 = blockIdx.y * BM, n0 = blockIdx.x * 64;
    int wm = wid >> 2, wn = wid & 3;

    uint32_t soA[4], soB[2];
    unsigned ao[4], bo[2], szA[4];
#pragma unroll
    for (int i = 0; i < 4; i++) {
        int c = tid + 256 * i;
        int r = c >> 3, gb = c & 7;
        soA[i] = (uint32_t)SWZ128(r * 128 + gb * 16);
        bool ok = (m0 + r) < M;
        ao[i] = ok ? ((unsigned)(m0 + r) * (unsigned)K + gb * 8) : 0u;
        szA[i] = ok ? 16u : 0u;
    }
#pragma unroll
    for (int i = 0; i < 2; i++) {
        int c = tid + 256 * i;
        int r = c >> 3, gb = c & 7;
        soB[i] = (uint32_t)SWZ128(r * 128 + gb * 16);
        bo[i] = (unsigned)(n0 + r) * (unsigned)K + gb * 8;
    }
    const int nk = K / BK;

    auto load_tile = [&](int kt) {
        uint32_t st = sbase + (uint32_t)(kt & 1) * STAGE_B2;
        unsigned ko = (unsigned)kt * BK;
#pragma unroll
        for (int i = 0; i < 4; i++) {
            CP16(st + soA[i],           Ahi + ao[i] + ko, szA[i]);
            CP16(st + TILE_A2 + soA[i], Alo + ao[i] + ko, szA[i]);
        }
#pragma unroll
        for (int i = 0; i < 2; i++) {
            CP16(st + 2*TILE_A2 + soB[i],            Bhi + bo[i] + ko, 16u);
            CP16(st + 2*TILE_A2 + TILE_B2 + soB[i],  Blo + bo[i] + ko, 16u);
        }
    };

    int a_row_loc = ((lane >> 3) & 1) * 8 + (lane & 7);
    int a_kh = (lane >> 4) * 16;
    int b_row_loc = (lane >> 4) * 8 + (lane & 7);
    int b_kh = ((lane >> 3) & 1) * 16;

    float acc[4][2][4];
#pragma unroll
    for (int i = 0; i < 4; i++)
#pragma unroll
        for (int j = 0; j < 2; j++)
#pragma unroll
            for (int k = 0; k < 4; k++) acc[i][j][k] = 0.f;

    load_tile(0);
    CP_COMMIT();
    if (nk > 1) load_tile(1);
    CP_COMMIT();

    uint32_t a_base[4];
    int a_ph[4];
#pragma unroll
    for (int mt = 0; mt < 4; mt++) {
        int row = wm * 64 + mt * 16 + a_row_loc;
        a_base[mt] = (uint32_t)(row * 128);
        a_ph[mt] = (row & 7) << 4;
    }
    int brow = wn * 16 + b_row_loc;
    uint32_t b_base = (uint32_t)(brow * 128);
    int b_ph = (brow & 7) << 4;

    for (int kt = 0; kt < nk; kt++) {
        CP_WAIT(1);
        __syncthreads();
        uint32_t st = sbase + (uint32_t)(kt & 1) * STAGE_B2;
        uint32_t stA = st, stAl = st + TILE_A2;
        uint32_t stB = st + 2*TILE_A2, stBl = st + 2*TILE_A2 + TILE_B2;
#pragma unroll
        for (int ks = 0; ks < 4; ks++) {
            uint32_t ah[4][4], al[4][4], bh[4], bl[4];
            {
                uint32_t off = b_base + (uint32_t)((ks * 32 + b_kh) ^ b_ph);
                ldsm4(bh, stB + off);
                ldsm4(bl, stBl + off);
            }
#pragma unroll
            for (int mt = 0; mt < 4; mt++) {
                uint32_t off = a_base[mt] + (uint32_t)((ks * 32 + a_kh) ^ a_ph[mt]);
                ldsm4(ah[mt], stA + off);
                ldsm4(al[mt], stAl + off);
            }
#pragma unroll
            for (int mt = 0; mt < 4; mt++)
#pragma unroll
                for (int nt = 0; nt < 2; nt++) {
                    const uint32_t* bph = &bh[nt * 2];
                    const uint32_t* bpl = &bl[nt * 2];
                    mma16816(acc[mt][nt], ah[mt], bph);
                    mma16816(acc[mt][nt], ah[mt], bpl);
                    mma16816(acc[mt][nt], al[mt], bph);
                }
        }
        __syncthreads();
        if (kt + 2 < nk) load_tile(kt + 2);
        CP_COMMIT();
    }
    CP_WAIT(0);
    __syncthreads();

    float* stg = (float*)smem;
    int cr = lane >> 2, ccol = (lane & 3) * 2;
#pragma unroll
    for (int mt = 0; mt < 4; mt++)
#pragma unroll
        for (int nt = 0; nt < 2; nt++) {
            int r = wm * 64 + mt * 16 + cr;
            int cl = wn * 16 + nt * 8 + ccol;
            *(float2*)&stg[r * LDS2_ + cl]       = make_float2(acc[mt][nt][0], acc[mt][nt][1]);
            *(float2*)&stg[(r + 8) * LDS2_ + cl] = make_float2(acc[mt][nt][2], acc[mt][nt][3]);
        }
    __syncthreads();

#pragma unroll
    for (int i = 0; i < 8; i++) {
        int id = tid + 256 * i;
        int r = id >> 4, cc = (id & 15) * 4;
        int m = m0 + r;
        if (m < M) {
            int n = n0 + cc;
            float4 v = *(float4*)&stg[r * LDS2_ + cc];
            float4 bs = *(const float4*)&bias[n];
            v.x += bs.x; v.y += bs.y; v.z += bs.z; v.w += bs.w;
            size_t idx = (size_t)m * N + n;
            if (mode == 0) {
                *(float4*)&C[idx] = v;
            } else if (mode == 1) {
                float g0 = gelu_new(v.x), g1 = gelu_new(v.y);
                float g2 = gelu_new(v.z), g3 = gelu_new(v.w);
                uint32_t h01, l01, h23, l23;
                pack_hilo(g0, g1, h01, l01);
                pack_hilo(g2, g3, h23, l23);
                *(uint2*)&Chi[idx] = make_uint2(h01, h23);
                *(uint2*)&Clo[idx] = make_uint2(l01, l23);
            } else {
                float4 c0 = *(float4*)&C[idx];
                c0.x += v.x; c0.y += v.y; c0.z += v.z; c0.w += v.w;
                *(float4*)&C[idx] = c0;
            }
        }
    }
}

// ---------------- flash attention (split-bf16 mma, 16 warps) ----------------
#define AKHI 0
#define AKLO 38912
#define AVHI 77824
#define AVLO 116736
#define ATTN_SMEM 155648

__global__ void __launch_bounds__(512)
attn_flash(const float* __restrict__ qkv,
           __nv_bfloat16* __restrict__ ohi, __nv_bfloat16* __restrict__ olo)
{
    extern __shared__ __align__(128) char asmem[];
    uint32_t sb = smem_u32(asmem);
    int tid = threadIdx.x;
    int bh = blockIdx.x, b = bh >> 4, hd = bh & 15;
    const float* base = qkv + (size_t)b * LSEQ * 3072;
    int hoff = hd * 64;

    for (int idx = tid; idx < 304 * 64; idx += 512) {
        int j = idx >> 6, d = idx & 63;
        float kv = 0.f, vv = 0.f;
        if (j < LSEQ) {
            kv = base[(size_t)j * 3072 + 1024 + hoff + d];
            vv = base[(size_t)j * 3072 + 2048 + hoff + d];
        }
        uint32_t off = (uint32_t)SWZ128(j * 128 + d * 2);
        __nv_bfloat16 kh = __float2bfloat16(kv);
        *(__nv_bfloat16*)(asmem + AKHI + off) = kh;
        *(__nv_bfloat16*)(asmem + AKLO + off) = __float2bfloat16(kv - __bfloat162float(kh));
        __nv_bfloat16 vh = __float2bfloat16(vv);
        *(__nv_bfloat16*)(asmem + AVHI + off) = vh;
        *(__nv_bfloat16*)(asmem + AVLO + off) = __float2bfloat16(vv - __bfloat162float(vh));
    }
    __syncthreads();

    int w = tid >> 5, lane = tid & 31;
    int g = lane >> 2, t4 = lane & 3;
    int kb_row = (lane >> 4) * 8 + (lane & 7);
    int kb_kb  = ((lane >> 3) & 1) * 16;
    int vb_row = ((lane >> 3) & 1) * 8 + (lane & 7);
    int vb_nb  = (lane >> 4) * 16;

    for (int qi = 0; qi < 2; qi++) {
        int qt;
        if (qi == 0) qt = 18 - w;
        else qt = (w == 15) ? 2 : (w == 14) ? 1 : (w == 13) ? 0 : -1;
        if (qt < 0) continue;
        int q0 = qt * 16;

        uint32_t qh[4][4], ql[4][4];
        int r1 = q0 + g;       int r1c = r1 < LSEQ ? r1 : LSEQ - 1;
        int r2 = r1 + 8;       int r2c = r2 < LSEQ ? r2 : LSEQ - 1;
        const float* q1p = base + (size_t)r1c * 3072 + hoff;
        const float* q2p = base + (size_t)r2c * 3072 + hoff;
#pragma unroll
        for (int kt = 0; kt < 4; kt++) {
            int c0 = kt * 16 + 2 * t4;
            float2 x0 = *(const float2*)(q1p + c0);
            float2 x1 = *(const float2*)(q2p + c0);
            float2 x2 = *(const float2*)(q1p + c0 + 8);
            float2 x3 = *(const float2*)(q2p + c0 + 8);
            pack_hilo(x0.x, x0.y, qh[kt][0], ql[kt][0]);
            pack_hilo(x1.x, x1.y, qh[kt][1], ql[kt][1]);
            pack_hilo(x2.x, x2.y, qh[kt][2], ql[kt][2]);
            pack_hilo(x3.x, x3.y, qh[kt][3], ql[kt][3]);
        }

        float m0 = -1e30f, m1 = -1e30f, l0 = 0.f, l1 = 0.f;
        float o[8][4];
#pragma unroll
        for (int i = 0; i < 8; i++)
#pragma unroll
            for (int k = 0; k < 4; k++) o[i][k] = 0.f;

        for (int jt = 0; jt <= qt; jt++) {
            float s[2][4] = {{0,0,0,0},{0,0,0,0}};
#pragma unroll
            for (int kt = 0; kt < 4; kt++) {
                int row = jt * 16 + kb_row;
                uint32_t off = (uint32_t)(row * 128 + ((kt * 32 + kb_kb) ^ ((row & 7) << 4)));
                uint32_t kh4[4], kl4[4];
                ldsm4(kh4, sb + AKHI + off);
                ldsm4(kl4, sb + AKLO + off);
#pragma unroll
                for (int nt = 0; nt < 2; nt++) {
                    mma16816(s[nt], qh[kt], &kh4[nt*2]);
                    mma16816(s[nt], qh[kt], &kl4[nt*2]);
                    mma16816(s[nt], ql[kt], &kh4[nt*2]);
                }
            }
            int qr1 = q0 + g, qr2 = qr1 + 8;
#pragma unroll
            for (int nt = 0; nt < 2; nt++) {
                int jc = jt * 16 + nt * 8 + 2 * t4;
                s[nt][0] = (jc     <= qr1) ? s[nt][0] * 0.125f : -1e30f;
                s[nt][1] = (jc + 1 <= qr1) ? s[nt][1] * 0.125f : -1e30f;
                s[nt][2] = (jc     <= qr2) ? s[nt][2] * 0.125f : -1e30f;
                s[nt][3] = (jc + 1 <= qr2) ? s[nt][3] * 0.125f : -1e30f;
            }
            float tm0 = fmaxf(fmaxf(s[0][0], s[0][1]), fmaxf(s[1][0], s[1][1]));
            float tm1 = fmaxf(fmaxf(s[0][2], s[0][3]), fmaxf(s[1][2], s[1][3]));
            tm0 = fmaxf(tm0, __shfl_xor_sync(0xFFFFFFFFu, tm0, 1));
            tm0 = fmaxf(tm0, __shfl_xor_sync(0xFFFFFFFFu, tm0, 2));
            tm1 = fmaxf(tm1, __shfl_xor_sync(0xFFFFFFFFu, tm1, 1));
            tm1 = fmaxf(tm1, __shfl_xor_sync(0xFFFFFFFFu, tm1, 2));
            float mn0 = fmaxf(m0, tm0), mn1 = fmaxf(m1, tm1);
            float sc0 = __expf(m0 - mn0), sc1 = __expf(m1 - mn1);
            m0 = mn0; m1 = mn1;
            float p[2][4];
#pragma unroll
            for (int nt = 0; nt < 2; nt++) {
                p[nt][0] = __expf(s[nt][0] - mn0);
                p[nt][1] = __expf(s[nt][1] - mn0);
                p[nt][2] = __expf(s[nt][2] - mn1);
                p[nt][3] = __expf(s[nt][3] - mn1);
            }
            float ts0 = p[0][0] + p[0][1] + p[1][0] + p[1][1];
            float ts1 = p[0][2] + p[0][3] + p[1][2] + p[1][3];
            ts0 += __shfl_xor_sync(0xFFFFFFFFu, ts0, 1);
            ts0 += __shfl_xor_sync(0xFFFFFFFFu, ts0, 2);
            ts1 += __shfl_xor_sync(0xFFFFFFFFu, ts1, 1);
            ts1 += __shfl_xor_sync(0xFFFFFFFFu, ts1, 2);
            l0 = l0 * sc0 + ts0;
            l1 = l1 * sc1 + ts1;
            bool need = __any_sync(0xFFFFFFFFu, (sc0 != 1.f) || (sc1 != 1.f));
            if (need) {
#pragma unroll
                for (int nt = 0; nt < 8; nt++) {
                    o[nt][0] *= sc0; o[nt][1] *= sc0; o[nt][2] *= sc1; o[nt][3] *= sc1;
                }
            }
            uint32_t pah[4], pal[4];
            pack_hilo(p[0][0], p[0][1], pah[0], pal[0]);
            pack_hilo(p[0][2], p[0][3], pah[1], pal[1]);
            pack_hilo(p[1][0], p[1][1], pah[2], pal[2]);
            pack_hilo(p[1][2], p[1][3], pah[3], pal[3]);
#pragma unroll
            for (int dt = 0; dt < 4; dt++) {
                int row = jt * 16 + vb_row;
                uint32_t off = (uint32_t)(row * 128 + ((dt * 32 + vb_nb) ^ ((row & 7) << 4)));
                uint32_t vh4[4], vl4[4];
                ldsm4t(vh4, sb + AVHI + off);
                ldsm4t(vl4, sb + AVLO + off);
#pragma unroll
                for (int su = 0; su < 2; su++) {
                    int nt = dt * 2 + su;
                    mma16816(o[nt], pah, &vh4[su*2]);
                    mma16816(o[nt], pah, &vl4[su*2]);
                    mma16816(o[nt], pal, &vh4[su*2]);
                }
            }
        }
        float inv0 = 1.f / l0, inv1 = 1.f / l1;
        int row1 = q0 + g, row2 = row1 + 8;
#pragma unroll
        for (int nt = 0; nt < 8; nt++) {
            int col = nt * 8 + 2 * t4;
            if (row1 < LSEQ) {
                uint32_t hp, lp;
                pack_hilo(o[nt][0] * inv0, o[nt][1] * inv0, hp, lp);
                size_t idx = (size_t)(b * LSEQ + row1) * D_ + hoff + col;
                *(uint32_t*)&ohi[idx] = hp;
                *(uint32_t*)&olo[idx] = lp;
            }
            if (row2 < LSEQ) {
                uint32_t hp, lp;
                pack_hilo(o[nt][2] * inv1, o[nt][3] * inv1, hp, lp);
                size_t idx = (size_t)(b * LSEQ + row2) * D_ + hoff + col;
                *(uint32_t*)&ohi[idx] = hp;
                *(uint32_t*)&olo[idx] = lp;
            }
        }
    }
}

// ---------------- loss ----------------
__global__ void loss_kernel(const float* __restrict__ h,
                            const float* __restrict__ g,
                            const float* __restrict__ beta,
                            const float* __restrict__ pw,
                            const float* __restrict__ pb,
                            const int* __restrict__ actions,
                            const int* __restrict__ tact,
                            float* __restrict__ partial)
{
    __shared__ float red[4];
    __shared__ float lred[5][4];
    int idx = blockIdx.x;
    int b = idx / (CTX_ + 1), t = idx % (CTX_ + 1);
    const float* x = h + (size_t)(b * LSEQ + 3 * t) * D_;
    int tid = threadIdx.x, lane = tid & 31, w = tid >> 5;

    float v[8];
    float s = 0.f;
#pragma unroll
    for (int i = 0; i < 8; i++) { v[i] = x[tid + 128 * i]; s += v[i]; }
#pragma unroll
    for (int o = 16; o; o >>= 1) s += __shfl_xor_sync(0xFFFFFFFFu, s, o);
    if (lane == 0) red[w] = s;
    __syncthreads();
    float mean = (red[0] + red[1] + red[2] + red[3]) * (1.f / 1024.f);
    __syncthreads();
    float s2 = 0.f;
#pragma unroll
    for (int i = 0; i < 8; i++) { float d = v[i] - mean; s2 += d * d; }
#pragma unroll
    for (int o = 16; o; o >>= 1) s2 += __shfl_xor_sync(0xFFFFFFFFu, s2, o);
    if (lane == 0) red[w] = s2;
    __syncthreads();
    float var = (red[0] + red[1] + red[2] + red[3]) * (1.f / 1024.f);
    float inv = 1.f / sqrtf(var + 1e-5f);

    float acc[NA_] = {0.f, 0.f, 0.f, 0.f, 0.f};
#pragma unroll
    for (int i = 0; i < 8; i++) {
        int c = tid + 128 * i;
        float xn = (v[i] - mean) * inv * g[c] + beta[c];
#pragma unroll
        for (int a = 0; a < NA_; a++)
            acc[a] = fmaf(xn, pw[c * NA_ + a], acc[a]);
    }
#pragma unroll
    for (int a = 0; a < NA_; a++) {
        float tv = acc[a];
#pragma unroll
        for (int o = 16; o; o >>= 1) tv += __shfl_xor_sync(0xFFFFFFFFu, tv, o);
        if (lane == 0) lred[a][w] = tv;
    }
    __syncthreads();
    if (tid == 0) {
        float logit[NA_];
#pragma unroll
        for (int a = 0; a < NA_; a++)
            logit[a] = lred[a][0] + lred[a][1] + lred[a][2] + lred[a][3] + pb[a];
        int target = (t < CTX_) ? actions[b * CTX_ + t] : tact[b];
        float mx = logit[0]; int am = 0;
#pragma unroll
        for (int a = 1; a < NA_; a++) if (logit[a] > mx) { mx = logit[a]; am = a; }
        float se = 0.f;
#pragma unroll
        for (int a = 0; a < NA_; a++) se += expf(logit[a] - mx);
        float lse = mx + logf(se);
        float sl = 0.f;
#pragma unroll
        for (int a = 0; a < NA_; a++) sl += (logit[a] - lse);
        float nll = -(logit[target] - lse);
        float smooth = -sl * (1.f / NA_);
        partial[2 * idx]     = 0.9f * nll + 0.1f * smooth;
        partial[2 * idx + 1] = (am == target) ? 1.f : 0.f;
    }
}

__global__ void reduce_kernel(const float* __restrict__ partial, float* __restrict__ out)
{
    __shared__ float rl[8], ra[8];
    int tid = threadIdx.x, lane = tid & 31, w = tid >> 5;
    float l = 0.f, a = 0.f;
    for (int i = tid; i < NPOS; i += 256) {
        l += partial[2 * i];
        a += partial[2 * i + 1];
    }
#pragma unroll
    for (int o = 16; o; o >>= 1) {
        l += __shfl_xor_sync(0xFFFFFFFFu, l, o);
        a += __shfl_xor_sync(0xFFFFFFFFu, a, o);
    }
    if (lane == 0) { rl[w] = l; ra[w] = a; }
    __syncthreads();
    if (tid == 0) {
        float L = 0.f, A = 0.f;
#pragma unroll
        for (int i = 0; i < 8; i++) { L += rl[i]; A += ra[i]; }
        out[0] = L * (1.f / NPOS);
        out[1] = A * (1.f / NPOS);
    }
}

// ---------------- host ----------------
static inline void launch_gemm64(const __nv_bfloat16* Ahi, const __nv_bfloat16* Alo,
                                 const __nv_bfloat16* Bhi, const __nv_bfloat16* Blo,
                                 const float* bias, float* C,
                                 __nv_bfloat16* Chi, __nv_bfloat16* Clo,
                                 int M, int N, int K, int mode)
{
    dim3 grid(N / 64, (M + BM - 1) / BM);
    gemm_mma64<<<grid, 256, GEMM2_SMEM>>>(Ahi, Alo, Bhi, Blo, bias, C, Chi, Clo, M, N, K, mode);
}

extern "C" void kernel_launch(void* const* d_in, const int* in_sizes, int n_in,
                              void* d_out, int out_size)
{
    const int*   states  = (const int*)  d_in[0];
    const int*   actions = (const int*)  d_in[1];
    const float* rewards = (const float*)d_in[2];
    const int*   qstates = (const int*)  d_in[3];
    const int*   tact    = (const int*)  d_in[4];
    const float* wpe     = (const float*)d_in[5];
    const float* e_state = (const float*)d_in[6];
    const float* e_act   = (const float*)d_in[7];
    const float* erw     = (const float*)d_in[8];
    const float* erb     = (const float*)d_in[9];
    const float* ln1g    = (const float*)d_in[10];
    const float* ln1b    = (const float*)d_in[11];
    const float* attnw   = (const float*)d_in[12];
    const float* attnb   = (const float*)d_in[13];
    const float* apw     = (const float*)d_in[14];
    const float* apb     = (const float*)d_in[15];
    const float* ln2g    = (const float*)d_in[16];
    const float* ln2b    = (const float*)d_in[17];
    const float* fcw     = (const float*)d_in[18];
    const float* fcb     = (const float*)d_in[19];
    const float* mpw     = (const float*)d_in[20];
    const float* mpb     = (const float*)d_in[21];
    const float* lnfg    = (const float*)d_in[22];
    const float* lnfb    = (const float*)d_in[23];
    const float* predw   = (const float*)d_in[24];
    const float* predb   = (const float*)d_in[25];
    float* out = (float*)d_out;

    float *h, *qkv, *partial;
    __nv_bfloat16 *xhi, *xlo, *ahi, *alo, *fhi, *flo, *whi, *wlo;
    cudaGetSymbolAddress((void**)&h,    g_h);
    cudaGetSymbolAddress((void**)&qkv,  g_qkv);
    cudaGetSymbolAddress((void**)&partial, g_partial);
    cudaGetSymbolAddress((void**)&xhi,  g_xhi);
    cudaGetSymbolAddress((void**)&xlo,  g_xlo);
    cudaGetSymbolAddress((void**)&ahi,  g_ahi);
    cudaGetSymbolAddress((void**)&alo,  g_alo);
    cudaGetSymbolAddress((void**)&fhi,  g_fhi);
    cudaGetSymbolAddress((void**)&flo,  g_flo);
    cudaGetSymbolAddress((void**)&whi,  g_whi);
    cudaGetSymbolAddress((void**)&wlo,  g_wlo);

    cudaFuncSetAttribute(attn_flash, cudaFuncAttributeMaxDynamicSharedMemorySize, ATTN_SMEM);
    cudaFuncSetAttribute(gemm_mma64, cudaFuncAttributeMaxDynamicSharedMemorySize, GEMM2_SMEM);

    const size_t WPL = 12582912;
    const size_t OFF_QKV = 0, OFF_PROJ = 3145728, OFF_FC = 4194304, OFF_MP = 8388608;
    wprep_kernel<<<dim3(3 * D_ / 32, D_ / 64, NL_), dim3(32, 8)>>>(
        attnw, whi + OFF_QKV, wlo + OFF_QKV, D_, 3 * D_, (size_t)D_ * 3 * D_, WPL);
    wprep_kernel<<<dim3(D_ / 32, D_ / 64, NL_), dim3(32, 8)>>>(
        apw, whi + OFF_PROJ, wlo + OFF_PROJ, D_, D_, (size_t)D_ * D_, WPL);
    wprep_kernel<<<dim3(DFF_ / 32, D_ / 64, NL_), dim3(32, 8)>>>(
        fcw, whi + OFF_FC, wlo + OFF_FC, D_, DFF_, (size_t)D_ * DFF_, WPL);
    wprep_kernel<<<dim3(D_ / 32, DFF_ / 64, NL_), dim3(32, 8)>>>(
        mpw, whi + OFF_MP, wlo + OFF_MP, DFF_, D_, (size_t)DFF_ * D_, WPL);

    embed_kernel<<<NTOK, 256>>>(states, actions, rewards, qstates, wpe,
                                e_state, e_act, erw, erb, h);

    for (int i = 0; i < NL_; i++) {
        size_t off = (size_t)i * WPL;
        ln_kernel<<<NTOK, 256>>>(h, xhi, xlo, ln1g + i * D_, ln1b + i * D_);
        launch_gemm64(xhi, xlo, whi + off + OFF_QKV, wlo + off + OFF_QKV,
                      attnb + i * 3 * D_, qkv, nullptr, nullptr, NTOK, 3 * D_, D_, 0);
        attn_flash<<<B_ * H_, 512, ATTN_SMEM>>>(qkv, ahi, alo);
        launch_gemm64(ahi, alo, whi + off + OFF_PROJ, wlo + off + OFF_PROJ,
                      apb + i * D_, h, nullptr, nullptr, NTOK, D_, D_, 2);
        ln_kernel<<<NTOK, 256>>>(h, xhi, xlo, ln2g + i * D_, ln2b + i * D_);
        launch_gemm64(xhi, xlo, whi + off + OFF_FC, wlo + off + OFF_FC,
                      fcb + i * DFF_, nullptr, fhi, flo, NTOK, DFF_, D_, 1);
        launch_gemm64(fhi, flo, whi + off + OFF_MP, wlo + off + OFF_MP,
                      mpb + i * D_, h, nullptr, nullptr, NTOK, D_, DFF_, 2);
    }

    loss_kernel<<<NPOS, 128>>>(h, lnfg, lnfb, predw, predb, actions, tact, partial);
    reduce_kernel<<<1, 256>>>(partial, out);
}